// round 1
// baseline (speedup 1.0000x reference)
#include <cuda_runtime.h>
#include <cstddef>

// Problem constants
#define S_LEN   2048
#define D_MODEL 1024
#define H_NUM   16
#define DH      64
#define M_TOK   4096          // B * S = 2 * 2048
#define QKV_LD  3072          // 3 * D

// Intermediate buffers (no cudaMalloc allowed -> device globals)
__device__ float g_qkv[(size_t)M_TOK * QKV_LD];   // [token][h*192 + {q:0..63,k:64..127,v:128..191}]
__device__ float g_ao [(size_t)M_TOK * D_MODEL];  // attention output [token][h*64+d]

// ---------------------------------------------------------------------------
// SGEMM: C[M,N] = A[M,K] @ B[N,K]^T (+ bias), both inputs K-major (NT form).
// 128x128x16 tiles, 256 threads, 8x8 per thread, transposed smem staging.
// ---------------------------------------------------------------------------
template <bool HAS_BIAS>
__global__ __launch_bounds__(256) void sgemm_nt(
    const float* __restrict__ A, const float* __restrict__ B,
    const float* __restrict__ bias, float* __restrict__ C,
    int M, int N, int K)
{
    __shared__ __align__(16) float As[16 * 132];  // [kk][m], stride 132
    __shared__ __align__(16) float Bs[16 * 132];  // [kk][n]

    const int tid = threadIdx.x;
    const int ttx = tid & 15;
    const int tty = tid >> 4;
    const int bm  = blockIdx.y * 128;
    const int bn  = blockIdx.x * 128;
    const int lr  = tid >> 2;   // 0..63 (load row)
    const int lk  = tid & 3;    // which float4 along K

    float acc[8][8];
#pragma unroll
    for (int i = 0; i < 8; ++i)
#pragma unroll
        for (int j = 0; j < 8; ++j) acc[i][j] = 0.f;

    const float* Aptr = A + (size_t)bm * K;
    const float* Bptr = B + (size_t)bn * K;

    for (int kt = 0; kt < K; kt += 16) {
#pragma unroll
        for (int it = 0; it < 2; ++it) {
            int row = lr + it * 64;
            float4 av = *reinterpret_cast<const float4*>(&Aptr[(size_t)row * K + kt + lk * 4]);
            As[(lk * 4 + 0) * 132 + row] = av.x;
            As[(lk * 4 + 1) * 132 + row] = av.y;
            As[(lk * 4 + 2) * 132 + row] = av.z;
            As[(lk * 4 + 3) * 132 + row] = av.w;
            float4 bv = *reinterpret_cast<const float4*>(&Bptr[(size_t)row * K + kt + lk * 4]);
            Bs[(lk * 4 + 0) * 132 + row] = bv.x;
            Bs[(lk * 4 + 1) * 132 + row] = bv.y;
            Bs[(lk * 4 + 2) * 132 + row] = bv.z;
            Bs[(lk * 4 + 3) * 132 + row] = bv.w;
        }
        __syncthreads();

#pragma unroll
        for (int kk = 0; kk < 16; ++kk) {
            float a[8], bb[8];
            float4 t;
            t = *reinterpret_cast<const float4*>(&As[kk * 132 + tty * 4]);
            a[0] = t.x; a[1] = t.y; a[2] = t.z; a[3] = t.w;
            t = *reinterpret_cast<const float4*>(&As[kk * 132 + 64 + tty * 4]);
            a[4] = t.x; a[5] = t.y; a[6] = t.z; a[7] = t.w;
            t = *reinterpret_cast<const float4*>(&Bs[kk * 132 + ttx * 4]);
            bb[0] = t.x; bb[1] = t.y; bb[2] = t.z; bb[3] = t.w;
            t = *reinterpret_cast<const float4*>(&Bs[kk * 132 + 64 + ttx * 4]);
            bb[4] = t.x; bb[5] = t.y; bb[6] = t.z; bb[7] = t.w;
#pragma unroll
            for (int i = 0; i < 8; ++i)
#pragma unroll
                for (int j = 0; j < 8; ++j)
                    acc[i][j] = fmaf(a[i], bb[j], acc[i][j]);
        }
        __syncthreads();
    }

#pragma unroll
    for (int i = 0; i < 8; ++i) {
        int r = bm + ((i < 4) ? (tty * 4 + i) : (64 + tty * 4 + i - 4));
#pragma unroll
        for (int half = 0; half < 2; ++half) {
            int c = bn + half * 64 + ttx * 4;
            const float* ap = &acc[i][half * 4];
            float4 ov;
            if (HAS_BIAS)
                ov = make_float4(ap[0] + bias[c + 0], ap[1] + bias[c + 1],
                                 ap[2] + bias[c + 2], ap[3] + bias[c + 3]);
            else
                ov = make_float4(ap[0], ap[1], ap[2], ap[3]);
            *reinterpret_cast<float4*>(&C[(size_t)r * N + c]) = ov;
        }
    }
}

// ---------------------------------------------------------------------------
// Flash attention, causal, fp32. One CTA = one (batch, head, 64-row q block).
// Br = Bc = 64, dh = 64. 256 threads (16x16), 4x4 per-thread tiles.
// smem: Qs[64][68] as [kk][r], KP[64][68] (K as [kk][c], reused as P[r][c]),
//       Vs[64][64] as [c][d].  Total 51200 B dynamic.
// ---------------------------------------------------------------------------
#define FLASH_SMEM_BYTES ((64 * 68 * 2 + 64 * 64) * 4)

__global__ __launch_bounds__(256) void flash_attn_kernel(
    const float* __restrict__ qkv, float* __restrict__ ao)
{
    extern __shared__ __align__(16) float sm[];
    float* Qs = sm;               // [kk*68 + r]
    float* KP = sm + 64 * 68;     // K: [kk*68 + c] ; later P: [r*68 + c]
    float* Vs = sm + 2 * 64 * 68; // [c*64 + d]

    const int tid = threadIdx.x;
    const int ttx = tid & 15;
    const int tty = tid >> 4;
    const int qb  = blockIdx.x;        // q block 0..31
    const int bh  = blockIdx.y;        // 0..31
    const int b   = bh >> 4;
    const int h   = bh & 15;

    const size_t base = (size_t)b * S_LEN * QKV_LD + (size_t)h * 192;
    const int q0 = qb * 64;

    // Load Q tile transposed: Qs[kk][r]
#pragma unroll
    for (int it = 0; it < 4; ++it) {
        int lin = tid + it * 256;
        int r = lin >> 4;           // 0..63
        int g = lin & 15;           // float4 group along dh
        float4 v = *reinterpret_cast<const float4*>(
            &qkv[base + (size_t)(q0 + r) * QKV_LD + g * 4]);
        Qs[(g * 4 + 0) * 68 + r] = v.x;
        Qs[(g * 4 + 1) * 68 + r] = v.y;
        Qs[(g * 4 + 2) * 68 + r] = v.z;
        Qs[(g * 4 + 3) * 68 + r] = v.w;
    }

    float o[16];
    float m[4], l[4];
#pragma unroll
    for (int i = 0; i < 16; ++i) o[i] = 0.f;
#pragma unroll
    for (int i = 0; i < 4; ++i) { m[i] = -1e30f; l[i] = 0.f; }

    for (int kb = 0; kb <= qb; ++kb) {
        __syncthreads();  // protect KP/Vs from previous iteration's readers
        // Load K transposed (KP[kk][c]) and V natural (Vs[c][d])
#pragma unroll
        for (int it = 0; it < 4; ++it) {
            int lin = tid + it * 256;
            int r = lin >> 4;
            int g = lin & 15;
            size_t tk = base + (size_t)(kb * 64 + r) * QKV_LD + 64 + g * 4;
            float4 kv = *reinterpret_cast<const float4*>(&qkv[tk]);
            KP[(g * 4 + 0) * 68 + r] = kv.x;
            KP[(g * 4 + 1) * 68 + r] = kv.y;
            KP[(g * 4 + 2) * 68 + r] = kv.z;
            KP[(g * 4 + 3) * 68 + r] = kv.w;
            float4 vv = *reinterpret_cast<const float4*>(&qkv[tk + 64]);
            *reinterpret_cast<float4*>(&Vs[r * 64 + g * 4]) = vv;
        }
        __syncthreads();

        // S = Q @ K^T  (thread owns rows 4*tty+i, cols 4*ttx+j)
        float s[16];
#pragma unroll
        for (int i = 0; i < 16; ++i) s[i] = 0.f;
#pragma unroll 8
        for (int kk = 0; kk < 64; ++kk) {
            float4 q4 = *reinterpret_cast<const float4*>(&Qs[kk * 68 + tty * 4]);
            float4 k4 = *reinterpret_cast<const float4*>(&KP[kk * 68 + ttx * 4]);
            float qa[4] = {q4.x, q4.y, q4.z, q4.w};
            float ka[4] = {k4.x, k4.y, k4.z, k4.w};
#pragma unroll
            for (int i = 0; i < 4; ++i)
#pragma unroll
                for (int j = 0; j < 4; ++j)
                    s[i * 4 + j] = fmaf(qa[i], ka[j], s[i * 4 + j]);
        }

        const float scale = 0.125f;  // 1/sqrt(64)
        if (kb == qb) {
#pragma unroll
            for (int i = 0; i < 4; ++i)
#pragma unroll
                for (int j = 0; j < 4; ++j) {
                    int rg = tty * 4 + i, cg = ttx * 4 + j;
                    s[i * 4 + j] = (cg <= rg) ? s[i * 4 + j] * scale : -1e30f;
                }
        } else {
#pragma unroll
            for (int i = 0; i < 16; ++i) s[i] *= scale;
        }

        // Online softmax: reduce across the 16-lane tx group (within-warp).
        float corr[4];
#pragma unroll
        for (int i = 0; i < 4; ++i) {
            float mx = fmaxf(fmaxf(s[i * 4 + 0], s[i * 4 + 1]),
                             fmaxf(s[i * 4 + 2], s[i * 4 + 3]));
#pragma unroll
            for (int w = 1; w < 16; w <<= 1)
                mx = fmaxf(mx, __shfl_xor_sync(0xffffffffu, mx, w));
            float mn = fmaxf(m[i], mx);
            corr[i] = __expf(m[i] - mn);
            m[i] = mn;
            float rs = 0.f;
#pragma unroll
            for (int j = 0; j < 4; ++j) {
                float p = __expf(s[i * 4 + j] - mn);
                s[i * 4 + j] = p;
                rs += p;
            }
#pragma unroll
            for (int w = 1; w < 16; w <<= 1)
                rs += __shfl_xor_sync(0xffffffffu, rs, w);
            l[i] = l[i] * corr[i] + rs;
        }
#pragma unroll
        for (int i = 0; i < 4; ++i)
#pragma unroll
            for (int j = 0; j < 4; ++j)
                o[i * 4 + j] *= corr[i];

        __syncthreads();  // all threads done reading KP as K
        // Store P natural: KP[r][c], float4 per thread row
#pragma unroll
        for (int i = 0; i < 4; ++i) {
            float4 p4 = make_float4(s[i * 4 + 0], s[i * 4 + 1],
                                    s[i * 4 + 2], s[i * 4 + 3]);
            *reinterpret_cast<float4*>(&KP[(tty * 4 + i) * 68 + ttx * 4]) = p4;
        }
        __syncthreads();

        // O += P @ V
#pragma unroll 8
        for (int c = 0; c < 64; ++c) {
            float4 v4 = *reinterpret_cast<const float4*>(&Vs[c * 64 + ttx * 4]);
            float va[4] = {v4.x, v4.y, v4.z, v4.w};
            float pa[4];
#pragma unroll
            for (int i = 0; i < 4; ++i) pa[i] = KP[(tty * 4 + i) * 68 + c];
#pragma unroll
            for (int i = 0; i < 4; ++i)
#pragma unroll
                for (int j = 0; j < 4; ++j)
                    o[i * 4 + j] = fmaf(pa[i], va[j], o[i * 4 + j]);
        }
    }

    // Normalize + write: ao[token][h*64 + d]
#pragma unroll
    for (int i = 0; i < 4; ++i) {
        float inv = 1.f / l[i];
        int r = q0 + tty * 4 + i;
        size_t addr = ((size_t)(b * S_LEN + r)) * D_MODEL + h * DH + ttx * 4;
        float4 ov = make_float4(o[i * 4 + 0] * inv, o[i * 4 + 1] * inv,
                                o[i * 4 + 2] * inv, o[i * 4 + 3] * inv);
        *reinterpret_cast<float4*>(&ao[addr]) = ov;
    }
}

// ---------------------------------------------------------------------------
extern "C" void kernel_launch(void* const* d_in, const int* in_sizes, int n_in,
                              void* d_out, int out_size)
{
    (void)in_sizes; (void)n_in; (void)out_size;
    const float* x     = (const float*)d_in[0];  // [2,2048,1024]
    const float* w_qkv = (const float*)d_in[1];  // [3072,1024]
    const float* w_out = (const float*)d_in[2];  // [1024,1024]
    const float* b_out = (const float*)d_in[3];  // [1024]
    float* out = (float*)d_out;                  // [2,2048,1024]

    float *qkv, *ao;
    cudaGetSymbolAddress((void**)&qkv, g_qkv);
    cudaGetSymbolAddress((void**)&ao, g_ao);

    cudaFuncSetAttribute(flash_attn_kernel,
                         cudaFuncAttributeMaxDynamicSharedMemorySize,
                         FLASH_SMEM_BYTES);

    // 1) QKV projection: [4096,3072] = x @ w_qkv^T
    sgemm_nt<false><<<dim3(QKV_LD / 128, M_TOK / 128), 256>>>(
        x, w_qkv, nullptr, qkv, M_TOK, QKV_LD, D_MODEL);

    // 2) Causal flash attention per head
    flash_attn_kernel<<<dim3(S_LEN / 64, 2 * H_NUM), 256, FLASH_SMEM_BYTES>>>(qkv, ao);

    // 3) Output projection + bias: [4096,1024] = ao @ w_out^T + b
    sgemm_nt<true><<<dim3(D_MODEL / 128, M_TOK / 128), 256>>>(
        ao, w_out, b_out, out, M_TOK, D_MODEL, D_MODEL);
}

// round 3
// speedup vs baseline: 1.4272x; 1.4272x over previous
#include <cuda_runtime.h>
#include <cuda_bf16.h>
#include <cstdint>
#include <cstddef>

// Problem constants
#define S_LEN   2048
#define D_MODEL 1024
#define H_NUM   16
#define DH      64
#define M_TOK   4096          // B * S
#define QKV_LD  3072          // 3 * D

typedef __nv_bfloat16 bf16;

// ---------------------------------------------------------------------------
// Device scratch (no cudaMalloc allowed)
// ---------------------------------------------------------------------------
__device__ float g_qkv[(size_t)M_TOK * QKV_LD];
__device__ float g_ao [(size_t)M_TOK * D_MODEL];

__device__ bf16 g_x_hi   [(size_t)M_TOK * D_MODEL];
__device__ bf16 g_x_lo   [(size_t)M_TOK * D_MODEL];
__device__ bf16 g_wqkv_hi[(size_t)QKV_LD * D_MODEL];
__device__ bf16 g_wqkv_lo[(size_t)QKV_LD * D_MODEL];
__device__ bf16 g_ao_hi  [(size_t)M_TOK * D_MODEL];
__device__ bf16 g_ao_lo  [(size_t)M_TOK * D_MODEL];
__device__ bf16 g_wout_hi[(size_t)D_MODEL * D_MODEL];
__device__ bf16 g_wout_lo[(size_t)D_MODEL * D_MODEL];

// ---------------------------------------------------------------------------
// PTX helpers (base sm_100-legal only: mma.sync / ldmatrix / cp.async)
// ---------------------------------------------------------------------------
__device__ __forceinline__ uint32_t smem_u32(const void* p) {
    uint32_t a;
    asm("{ .reg .u64 t; cvta.to.shared.u64 t, %1; cvt.u32.u64 %0, t; }" : "=r"(a) : "l"(p));
    return a;
}
__device__ __forceinline__ void cp_async16(uint32_t dst, const void* src) {
    asm volatile("cp.async.cg.shared.global [%0], [%1], 16;" :: "r"(dst), "l"(src));
}
__device__ __forceinline__ void cp_commit() {
    asm volatile("cp.async.commit_group;" ::: "memory");
}
template <int N>
__device__ __forceinline__ void cp_wait() {
    asm volatile("cp.async.wait_group %0;" :: "n"(N) : "memory");
}
__device__ __forceinline__ void ldsm_x4(uint32_t& r0, uint32_t& r1, uint32_t& r2,
                                        uint32_t& r3, uint32_t a) {
    asm volatile("ldmatrix.sync.aligned.m8n8.x4.shared.b16 {%0,%1,%2,%3}, [%4];"
                 : "=r"(r0), "=r"(r1), "=r"(r2), "=r"(r3) : "r"(a));
}
__device__ __forceinline__ void mma_bf16(float* d, const uint32_t* a, const uint32_t* b) {
    asm volatile("mma.sync.aligned.m16n8k16.row.col.f32.bf16.bf16.f32 "
                 "{%0,%1,%2,%3}, {%4,%5,%6,%7}, {%8,%9}, {%0,%1,%2,%3};"
                 : "+f"(d[0]), "+f"(d[1]), "+f"(d[2]), "+f"(d[3])
                 : "r"(a[0]), "r"(a[1]), "r"(a[2]), "r"(a[3]), "r"(b[0]), "r"(b[1]));
}

// ---------------------------------------------------------------------------
// Split pack: fp32 -> bf16 hi + bf16 lo  (x ~= hi + lo, residual ~2^-17)
// ---------------------------------------------------------------------------
__global__ __launch_bounds__(256) void pack_split(
    const float* __restrict__ in, bf16* __restrict__ hi,
    bf16* __restrict__ lo, int n4)
{
    int i = blockIdx.x * 256 + threadIdx.x;
    if (i >= n4) return;
    float4 v = reinterpret_cast<const float4*>(in)[i];
    bf16 h0 = __float2bfloat16(v.x), h1 = __float2bfloat16(v.y);
    bf16 h2 = __float2bfloat16(v.z), h3 = __float2bfloat16(v.w);
    bf16 l0 = __float2bfloat16(v.x - __bfloat162float(h0));
    bf16 l1 = __float2bfloat16(v.y - __bfloat162float(h1));
    bf16 l2 = __float2bfloat16(v.z - __bfloat162float(h2));
    bf16 l3 = __float2bfloat16(v.w - __bfloat162float(h3));
    reinterpret_cast<__nv_bfloat162*>(hi)[2 * i + 0] = __nv_bfloat162(h0, h1);
    reinterpret_cast<__nv_bfloat162*>(hi)[2 * i + 1] = __nv_bfloat162(h2, h3);
    reinterpret_cast<__nv_bfloat162*>(lo)[2 * i + 0] = __nv_bfloat162(l0, l1);
    reinterpret_cast<__nv_bfloat162*>(lo)[2 * i + 1] = __nv_bfloat162(l2, l3);
}

// ---------------------------------------------------------------------------
// HMMA split-bf16 GEMM: C[M,N] = A[M,K] @ B[N,K]^T (+bias), fp32 out.
// CTA 128x128, K-slab 32, 8 warps (2x4), warp tile 64x32.
// smem per stage: Ahi|Alo|Bhi|Blo, each 128 rows x 32 elems padded to 40
// (80B row stride -> conflict-free ldmatrix). 2 stages, cp.async pipeline.
// ---------------------------------------------------------------------------
#define BK        32
#define PAD_K     40
#define TILE_SMB  (128 * PAD_K * 2)      // 10240 B
#define STAGE_B   (4 * TILE_SMB)         // 40960 B
#define GEMM_SMEM (2 * STAGE_B)          // 81920 B

template <bool HAS_BIAS>
__global__ __launch_bounds__(256) void gemm_mma(
    const bf16* __restrict__ Ahi, const bf16* __restrict__ Alo,
    const bf16* __restrict__ Bhi, const bf16* __restrict__ Blo,
    const float* __restrict__ bias, float* __restrict__ C,
    int M, int N, int K)
{
    extern __shared__ char smem[];
    const uint32_t sb = smem_u32(smem);
    const int tid = threadIdx.x;
    const int wid = tid >> 5;
    const int lane = tid & 31;
    const int bm = blockIdx.y * 128;
    const int bn = blockIdx.x * 128;
    const int wm = wid >> 2;      // 0..1 -> rows wm*64
    const int wn = wid & 3;       // 0..3 -> cols wn*32
    const int nk = K / BK;

    // cp.async chunk coords (2 chunks of 16B per thread per tile)
    const int r0 = tid >> 2, q0 = tid & 3;          // chunk tid
    const int r1 = r0 + 64, q1 = q0;                // chunk tid+256

    const bf16* gsrc[4] = { Ahi + (size_t)bm * K, Alo + (size_t)bm * K,
                            Bhi + (size_t)bn * K, Blo + (size_t)bn * K };

    auto load_stage = [&](int s, int k0) {
        uint32_t base = sb + s * STAGE_B;
#pragma unroll
        for (int t = 0; t < 4; ++t) {
            const bf16* g = gsrc[t];
            uint32_t db = base + t * TILE_SMB;
            cp_async16(db + (r0 * PAD_K + q0 * 8) * 2, g + (size_t)r0 * K + k0 + q0 * 8);
            cp_async16(db + (r1 * PAD_K + q1 * 8) * 2, g + (size_t)r1 * K + k0 + q1 * 8);
        }
        cp_commit();
    };

    float acc[4][4][4];
#pragma unroll
    for (int mt = 0; mt < 4; ++mt)
#pragma unroll
        for (int nt = 0; nt < 4; ++nt)
#pragma unroll
            for (int e = 0; e < 4; ++e) acc[mt][nt][e] = 0.f;

    // ldmatrix lane address components
    const int lrow8 = lane & 7;
    const int lq    = lane >> 3;      // 0..3
    // A x4: row = mbase + lrow8 + (lq&1)*8 ; col = kk + (lq>>1)*8
    const int a_roff = lrow8 + (lq & 1) * 8;
    const int a_coff = (lq >> 1) * 8;
    // B x4 (two n-tiles): n = nbase + lrow8 + (lq>>1)*8 ; col = kk + (lq&1)*8
    const int b_noff = lrow8 + (lq >> 1) * 8;
    const int b_coff = (lq & 1) * 8;

    load_stage(0, 0);

    for (int i = 0; i < nk; ++i) {
        const int s = i & 1;
        if (i + 1 < nk) { load_stage(s ^ 1, (i + 1) * BK); cp_wait<1>(); }
        else            { cp_wait<0>(); }
        __syncthreads();

        const uint32_t stg = sb + s * STAGE_B;
#pragma unroll
        for (int kk = 0; kk < BK; kk += 16) {
            // B fragments: [hi/lo][nt][2]
            uint32_t bh[4][2], bl[4][2];
#pragma unroll
            for (int ntp = 0; ntp < 2; ++ntp) {
                int nidx = wn * 32 + ntp * 16 + b_noff;
                int cidx = kk + b_coff;
                uint32_t addr_h = stg + 2 * TILE_SMB + (nidx * PAD_K + cidx) * 2;
                uint32_t addr_l = stg + 3 * TILE_SMB + (nidx * PAD_K + cidx) * 2;
                ldsm_x4(bh[2 * ntp][0], bh[2 * ntp][1], bh[2 * ntp + 1][0], bh[2 * ntp + 1][1], addr_h);
                ldsm_x4(bl[2 * ntp][0], bl[2 * ntp][1], bl[2 * ntp + 1][0], bl[2 * ntp + 1][1], addr_l);
            }
#pragma unroll
            for (int mt = 0; mt < 4; ++mt) {
                int midx = wm * 64 + mt * 16 + a_roff;
                int cidx = kk + a_coff;
                uint32_t ah[4], al[4];
                ldsm_x4(ah[0], ah[1], ah[2], ah[3], stg + 0 * TILE_SMB + (midx * PAD_K + cidx) * 2);
                ldsm_x4(al[0], al[1], al[2], al[3], stg + 1 * TILE_SMB + (midx * PAD_K + cidx) * 2);
#pragma unroll
                for (int nt = 0; nt < 4; ++nt) {
                    mma_bf16(acc[mt][nt], ah, bh[nt]);
                    mma_bf16(acc[mt][nt], ah, bl[nt]);
                    mma_bf16(acc[mt][nt], al, bh[nt]);
                }
            }
        }
        __syncthreads();
    }

    // Epilogue: write fp32 (+bias)
#pragma unroll
    for (int mt = 0; mt < 4; ++mt) {
#pragma unroll
        for (int nt = 0; nt < 4; ++nt) {
            int r = bm + wm * 64 + mt * 16 + (lane >> 2);
            int c = bn + wn * 32 + nt * 8 + (lane & 3) * 2;
            float b0 = 0.f, b1 = 0.f;
            if (HAS_BIAS) { b0 = bias[c]; b1 = bias[c + 1]; }
            float2 v0 = make_float2(acc[mt][nt][0] + b0, acc[mt][nt][1] + b1);
            float2 v1 = make_float2(acc[mt][nt][2] + b0, acc[mt][nt][3] + b1);
            *reinterpret_cast<float2*>(&C[(size_t)r * N + c]) = v0;
            *reinterpret_cast<float2*>(&C[(size_t)(r + 8) * N + c]) = v1;
        }
    }
}

// ---------------------------------------------------------------------------
// Flash attention, causal, fp32 (proven at rel_err 5.8e-7)
// ---------------------------------------------------------------------------
#define FLASH_SMEM_BYTES ((64 * 68 * 2 + 64 * 64) * 4)

__global__ __launch_bounds__(256) void flash_attn_kernel(
    const float* __restrict__ qkv, float* __restrict__ ao)
{
    extern __shared__ __align__(16) float sm[];
    float* Qs = sm;
    float* KP = sm + 64 * 68;
    float* Vs = sm + 2 * 64 * 68;

    const int tid = threadIdx.x;
    const int ttx = tid & 15;
    const int tty = tid >> 4;
    const int qb  = blockIdx.x;
    const int bh  = blockIdx.y;
    const int b   = bh >> 4;
    const int h   = bh & 15;

    const size_t base = (size_t)b * S_LEN * QKV_LD + (size_t)h * 192;
    const int q0 = qb * 64;

#pragma unroll
    for (int it = 0; it < 4; ++it) {
        int lin = tid + it * 256;
        int r = lin >> 4;
        int g = lin & 15;
        float4 v = *reinterpret_cast<const float4*>(
            &qkv[base + (size_t)(q0 + r) * QKV_LD + g * 4]);
        Qs[(g * 4 + 0) * 68 + r] = v.x;
        Qs[(g * 4 + 1) * 68 + r] = v.y;
        Qs[(g * 4 + 2) * 68 + r] = v.z;
        Qs[(g * 4 + 3) * 68 + r] = v.w;
    }

    float o[16];
    float m[4], l[4];
#pragma unroll
    for (int i = 0; i < 16; ++i) o[i] = 0.f;
#pragma unroll
    for (int i = 0; i < 4; ++i) { m[i] = -1e30f; l[i] = 0.f; }

    for (int kb = 0; kb <= qb; ++kb) {
        __syncthreads();
#pragma unroll
        for (int it = 0; it < 4; ++it) {
            int lin = tid + it * 256;
            int r = lin >> 4;
            int g = lin & 15;
            size_t tk = base + (size_t)(kb * 64 + r) * QKV_LD + 64 + g * 4;
            float4 kv = *reinterpret_cast<const float4*>(&qkv[tk]);
            KP[(g * 4 + 0) * 68 + r] = kv.x;
            KP[(g * 4 + 1) * 68 + r] = kv.y;
            KP[(g * 4 + 2) * 68 + r] = kv.z;
            KP[(g * 4 + 3) * 68 + r] = kv.w;
            float4 vv = *reinterpret_cast<const float4*>(&qkv[tk + 64]);
            *reinterpret_cast<float4*>(&Vs[r * 64 + g * 4]) = vv;
        }
        __syncthreads();

        float s[16];
#pragma unroll
        for (int i = 0; i < 16; ++i) s[i] = 0.f;
#pragma unroll 8
        for (int kk = 0; kk < 64; ++kk) {
            float4 q4 = *reinterpret_cast<const float4*>(&Qs[kk * 68 + tty * 4]);
            float4 k4 = *reinterpret_cast<const float4*>(&KP[kk * 68 + ttx * 4]);
            float qa[4] = {q4.x, q4.y, q4.z, q4.w};
            float ka[4] = {k4.x, k4.y, k4.z, k4.w};
#pragma unroll
            for (int i = 0; i < 4; ++i)
#pragma unroll
                for (int j = 0; j < 4; ++j)
                    s[i * 4 + j] = fmaf(qa[i], ka[j], s[i * 4 + j]);
        }

        const float scale = 0.125f;
        if (kb == qb) {
#pragma unroll
            for (int i = 0; i < 4; ++i)
#pragma unroll
                for (int j = 0; j < 4; ++j) {
                    int rg = tty * 4 + i, cg = ttx * 4 + j;
                    s[i * 4 + j] = (cg <= rg) ? s[i * 4 + j] * scale : -1e30f;
                }
        } else {
#pragma unroll
            for (int i = 0; i < 16; ++i) s[i] *= scale;
        }

        float corr[4];
#pragma unroll
        for (int i = 0; i < 4; ++i) {
            float mx = fmaxf(fmaxf(s[i * 4 + 0], s[i * 4 + 1]),
                             fmaxf(s[i * 4 + 2], s[i * 4 + 3]));
#pragma unroll
            for (int w = 1; w < 16; w <<= 1)
                mx = fmaxf(mx, __shfl_xor_sync(0xffffffffu, mx, w));
            float mn = fmaxf(m[i], mx);
            corr[i] = __expf(m[i] - mn);
            m[i] = mn;
            float rs = 0.f;
#pragma unroll
            for (int j = 0; j < 4; ++j) {
                float p = __expf(s[i * 4 + j] - mn);
                s[i * 4 + j] = p;
                rs += p;
            }
#pragma unroll
            for (int w = 1; w < 16; w <<= 1)
                rs += __shfl_xor_sync(0xffffffffu, rs, w);
            l[i] = l[i] * corr[i] + rs;
        }
#pragma unroll
        for (int i = 0; i < 4; ++i)
#pragma unroll
            for (int j = 0; j < 4; ++j)
                o[i * 4 + j] *= corr[i];

        __syncthreads();
#pragma unroll
        for (int i = 0; i < 4; ++i) {
            float4 p4 = make_float4(s[i * 4 + 0], s[i * 4 + 1],
                                    s[i * 4 + 2], s[i * 4 + 3]);
            *reinterpret_cast<float4*>(&KP[(tty * 4 + i) * 68 + ttx * 4]) = p4;
        }
        __syncthreads();

#pragma unroll 8
        for (int c = 0; c < 64; ++c) {
            float4 v4 = *reinterpret_cast<const float4*>(&Vs[c * 64 + ttx * 4]);
            float va[4] = {v4.x, v4.y, v4.z, v4.w};
            float pa[4];
#pragma unroll
            for (int i = 0; i < 4; ++i) pa[i] = KP[(tty * 4 + i) * 68 + c];
#pragma unroll
            for (int i = 0; i < 4; ++i)
#pragma unroll
                for (int j = 0; j < 4; ++j)
                    o[i * 4 + j] = fmaf(pa[i], va[j], o[i * 4 + j]);
        }
    }

#pragma unroll
    for (int i = 0; i < 4; ++i) {
        float inv = 1.f / l[i];
        int r = q0 + tty * 4 + i;
        size_t addr = ((size_t)(b * S_LEN + r)) * D_MODEL + h * DH + ttx * 4;
        float4 ov = make_float4(o[i * 4 + 0] * inv, o[i * 4 + 1] * inv,
                                o[i * 4 + 2] * inv, o[i * 4 + 3] * inv);
        *reinterpret_cast<float4*>(&ao[addr]) = ov;
    }
}

// ---------------------------------------------------------------------------
extern "C" void kernel_launch(void* const* d_in, const int* in_sizes, int n_in,
                              void* d_out, int out_size)
{
    (void)in_sizes; (void)n_in; (void)out_size;
    const float* x     = (const float*)d_in[0];
    const float* w_qkv = (const float*)d_in[1];
    const float* w_out = (const float*)d_in[2];
    const float* b_out = (const float*)d_in[3];
    float* out = (float*)d_out;

    float *qkv, *ao;
    cudaGetSymbolAddress((void**)&qkv, g_qkv);
    cudaGetSymbolAddress((void**)&ao, g_ao);
    bf16 *xhi, *xlo, *whi, *wlo, *aohi, *aolo, *wohi, *wolo;
    cudaGetSymbolAddress((void**)&xhi, g_x_hi);
    cudaGetSymbolAddress((void**)&xlo, g_x_lo);
    cudaGetSymbolAddress((void**)&whi, g_wqkv_hi);
    cudaGetSymbolAddress((void**)&wlo, g_wqkv_lo);
    cudaGetSymbolAddress((void**)&aohi, g_ao_hi);
    cudaGetSymbolAddress((void**)&aolo, g_ao_lo);
    cudaGetSymbolAddress((void**)&wohi, g_wout_hi);
    cudaGetSymbolAddress((void**)&wolo, g_wout_lo);

    cudaFuncSetAttribute(gemm_mma<false>,
                         cudaFuncAttributeMaxDynamicSharedMemorySize, GEMM_SMEM);
    cudaFuncSetAttribute(gemm_mma<true>,
                         cudaFuncAttributeMaxDynamicSharedMemorySize, GEMM_SMEM);
    cudaFuncSetAttribute(flash_attn_kernel,
                         cudaFuncAttributeMaxDynamicSharedMemorySize, FLASH_SMEM_BYTES);

    // 1) split-pack inputs
    {
        int n4 = M_TOK * D_MODEL / 4;
        pack_split<<<(n4 + 255) / 256, 256>>>(x, xhi, xlo, n4);
        n4 = QKV_LD * D_MODEL / 4;
        pack_split<<<(n4 + 255) / 256, 256>>>(w_qkv, whi, wlo, n4);
        n4 = D_MODEL * D_MODEL / 4;
        pack_split<<<(n4 + 255) / 256, 256>>>(w_out, wohi, wolo, n4);
    }

    // 2) QKV projection on tensor cores (HMMA)
    gemm_mma<false><<<dim3(QKV_LD / 128, M_TOK / 128), 256, GEMM_SMEM>>>(
        xhi, xlo, whi, wlo, nullptr, qkv, M_TOK, QKV_LD, D_MODEL);

    // 3) causal flash attention (fp32)
    flash_attn_kernel<<<dim3(S_LEN / 64, 2 * H_NUM), 256, FLASH_SMEM_BYTES>>>(qkv, ao);

    // 4) pack attention output, then output projection (HMMA)
    {
        int n4 = M_TOK * D_MODEL / 4;
        pack_split<<<(n4 + 255) / 256, 256>>>(ao, aohi, aolo, n4);
    }
    gemm_mma<true><<<dim3(D_MODEL / 128, M_TOK / 128), 256, GEMM_SMEM>>>(
        aohi, aolo, wohi, wolo, b_out, out, M_TOK, D_MODEL, D_MODEL);
}

// round 4
// speedup vs baseline: 2.4592x; 1.7230x over previous
#include <cuda_runtime.h>
#include <cuda_bf16.h>
#include <cstdint>
#include <cstddef>

#define S_LEN   2048
#define D_MODEL 1024
#define H_NUM   16
#define DH      64
#define M_TOK   4096
#define QKV_LD  3072

typedef __nv_bfloat16 bf16;

// ---------------------------------------------------------------------------
// Device scratch
// ---------------------------------------------------------------------------
__device__ bf16 g_x_hi   [(size_t)M_TOK * D_MODEL];
__device__ bf16 g_x_lo   [(size_t)M_TOK * D_MODEL];
__device__ bf16 g_wqkv_hi[(size_t)QKV_LD * D_MODEL];
__device__ bf16 g_wqkv_lo[(size_t)QKV_LD * D_MODEL];
__device__ bf16 g_qkv_hi [(size_t)M_TOK * QKV_LD];
__device__ bf16 g_qkv_lo [(size_t)M_TOK * QKV_LD];
__device__ bf16 g_ao_hi  [(size_t)M_TOK * D_MODEL];
__device__ bf16 g_ao_lo  [(size_t)M_TOK * D_MODEL];
__device__ bf16 g_wout_hi[(size_t)D_MODEL * D_MODEL];
__device__ bf16 g_wout_lo[(size_t)D_MODEL * D_MODEL];

// ---------------------------------------------------------------------------
// PTX helpers (base sm_100-legal)
// ---------------------------------------------------------------------------
__device__ __forceinline__ uint32_t smem_u32(const void* p) {
    uint32_t a;
    asm("{ .reg .u64 t; cvta.to.shared.u64 t, %1; cvt.u32.u64 %0, t; }" : "=r"(a) : "l"(p));
    return a;
}
__device__ __forceinline__ void cp_async16(uint32_t dst, const void* src) {
    asm volatile("cp.async.cg.shared.global [%0], [%1], 16;" :: "r"(dst), "l"(src));
}
__device__ __forceinline__ void cp_commit() {
    asm volatile("cp.async.commit_group;" ::: "memory");
}
template <int N>
__device__ __forceinline__ void cp_wait() {
    asm volatile("cp.async.wait_group %0;" :: "n"(N) : "memory");
}
__device__ __forceinline__ void ldsm_x4(uint32_t& r0, uint32_t& r1, uint32_t& r2,
                                        uint32_t& r3, uint32_t a) {
    asm volatile("ldmatrix.sync.aligned.m8n8.x4.shared.b16 {%0,%1,%2,%3}, [%4];"
                 : "=r"(r0), "=r"(r1), "=r"(r2), "=r"(r3) : "r"(a));
}
__device__ __forceinline__ void ldsm_x4_t(uint32_t& r0, uint32_t& r1, uint32_t& r2,
                                          uint32_t& r3, uint32_t a) {
    asm volatile("ldmatrix.sync.aligned.m8n8.x4.trans.shared.b16 {%0,%1,%2,%3}, [%4];"
                 : "=r"(r0), "=r"(r1), "=r"(r2), "=r"(r3) : "r"(a));
}
__device__ __forceinline__ void mma_bf16(float* d, const uint32_t* a, const uint32_t* b) {
    asm volatile("mma.sync.aligned.m16n8k16.row.col.f32.bf16.bf16.f32 "
                 "{%0,%1,%2,%3}, {%4,%5,%6,%7}, {%8,%9}, {%0,%1,%2,%3};"
                 : "+f"(d[0]), "+f"(d[1]), "+f"(d[2]), "+f"(d[3])
                 : "r"(a[0]), "r"(a[1]), "r"(a[2]), "r"(a[3]), "r"(b[0]), "r"(b[1]));
}
// pack two fp32 -> bf16x2 (first arg -> low half)
__device__ __forceinline__ uint32_t pack_bf2(float e0, float e1) {
    uint16_t a = __bfloat16_as_ushort(__float2bfloat16(e0));
    uint16_t b = __bfloat16_as_ushort(__float2bfloat16(e1));
    return (uint32_t)a | ((uint32_t)b << 16);
}
// split pair into hi/lo bf16x2 words
__device__ __forceinline__ void split_pair(float a, float b, uint32_t& hi, uint32_t& lo) {
    bf16 ha = __float2bfloat16(a), hb = __float2bfloat16(b);
    hi = (uint32_t)__bfloat16_as_ushort(ha) | ((uint32_t)__bfloat16_as_ushort(hb) << 16);
    float la = a - __bfloat162float(ha), lb = b - __bfloat162float(hb);
    lo = (uint32_t)__bfloat16_as_ushort(__float2bfloat16(la)) |
         ((uint32_t)__bfloat16_as_ushort(__float2bfloat16(lb)) << 16);
}

// ---------------------------------------------------------------------------
// Split pack: fp32 -> bf16 hi + lo
// ---------------------------------------------------------------------------
__global__ __launch_bounds__(256) void pack_split(
    const float* __restrict__ in, bf16* __restrict__ hi,
    bf16* __restrict__ lo, int n4)
{
    int i = blockIdx.x * 256 + threadIdx.x;
    if (i >= n4) return;
    float4 v = reinterpret_cast<const float4*>(in)[i];
    uint32_t h0, l0, h1, l1;
    split_pair(v.x, v.y, h0, l0);
    split_pair(v.z, v.w, h1, l1);
    reinterpret_cast<uint2*>(hi)[i] = make_uint2(h0, h1);
    reinterpret_cast<uint2*>(lo)[i] = make_uint2(l0, l1);
}

// ---------------------------------------------------------------------------
// HMMA split-bf16 GEMM. SPLIT_OUT: write bf16 hi/lo instead of fp32.
// ---------------------------------------------------------------------------
#define BK        32
#define PAD_K     40
#define TILE_SMB  (128 * PAD_K * 2)
#define STAGE_B   (4 * TILE_SMB)
#define GEMM_SMEM (2 * STAGE_B)

template <bool HAS_BIAS, bool SPLIT_OUT>
__global__ __launch_bounds__(256) void gemm_mma(
    const bf16* __restrict__ Ahi, const bf16* __restrict__ Alo,
    const bf16* __restrict__ Bhi, const bf16* __restrict__ Blo,
    const float* __restrict__ bias, float* __restrict__ C,
    bf16* __restrict__ Chi, bf16* __restrict__ Clo,
    int M, int N, int K)
{
    extern __shared__ char smem[];
    const uint32_t sb = smem_u32(smem);
    const int tid = threadIdx.x;
    const int wid = tid >> 5;
    const int lane = tid & 31;
    const int bm = blockIdx.y * 128;
    const int bn = blockIdx.x * 128;
    const int wm = wid >> 2;
    const int wn = wid & 3;
    const int nk = K / BK;

    const int r0 = tid >> 2, q0 = tid & 3;
    const int r1 = r0 + 64;

    const bf16* gsrc[4] = { Ahi + (size_t)bm * K, Alo + (size_t)bm * K,
                            Bhi + (size_t)bn * K, Blo + (size_t)bn * K };

    auto load_stage = [&](int s, int k0) {
        uint32_t base = sb + s * STAGE_B;
#pragma unroll
        for (int t = 0; t < 4; ++t) {
            const bf16* g = gsrc[t];
            uint32_t db = base + t * TILE_SMB;
            cp_async16(db + (r0 * PAD_K + q0 * 8) * 2, g + (size_t)r0 * K + k0 + q0 * 8);
            cp_async16(db + (r1 * PAD_K + q0 * 8) * 2, g + (size_t)r1 * K + k0 + q0 * 8);
        }
        cp_commit();
    };

    float acc[4][4][4];
#pragma unroll
    for (int mt = 0; mt < 4; ++mt)
#pragma unroll
        for (int nt = 0; nt < 4; ++nt)
#pragma unroll
            for (int e = 0; e < 4; ++e) acc[mt][nt][e] = 0.f;

    const int lrow8 = lane & 7;
    const int lq    = lane >> 3;
    const int a_roff = lrow8 + (lq & 1) * 8;
    const int a_coff = (lq >> 1) * 8;
    const int b_noff = lrow8 + (lq >> 1) * 8;
    const int b_coff = (lq & 1) * 8;

    load_stage(0, 0);

    for (int i = 0; i < nk; ++i) {
        const int s = i & 1;
        if (i + 1 < nk) { load_stage(s ^ 1, (i + 1) * BK); cp_wait<1>(); }
        else            { cp_wait<0>(); }
        __syncthreads();

        const uint32_t stg = sb + s * STAGE_B;
#pragma unroll
        for (int kk = 0; kk < BK; kk += 16) {
            uint32_t bh[4][2], bl[4][2];
#pragma unroll
            for (int ntp = 0; ntp < 2; ++ntp) {
                int nidx = wn * 32 + ntp * 16 + b_noff;
                int cidx = kk + b_coff;
                ldsm_x4(bh[2 * ntp][0], bh[2 * ntp][1], bh[2 * ntp + 1][0], bh[2 * ntp + 1][1],
                        stg + 2 * TILE_SMB + (nidx * PAD_K + cidx) * 2);
                ldsm_x4(bl[2 * ntp][0], bl[2 * ntp][1], bl[2 * ntp + 1][0], bl[2 * ntp + 1][1],
                        stg + 3 * TILE_SMB + (nidx * PAD_K + cidx) * 2);
            }
#pragma unroll
            for (int mt = 0; mt < 4; ++mt) {
                int midx = wm * 64 + mt * 16 + a_roff;
                int cidx = kk + a_coff;
                uint32_t ah[4], al[4];
                ldsm_x4(ah[0], ah[1], ah[2], ah[3], stg + 0 * TILE_SMB + (midx * PAD_K + cidx) * 2);
                ldsm_x4(al[0], al[1], al[2], al[3], stg + 1 * TILE_SMB + (midx * PAD_K + cidx) * 2);
#pragma unroll
                for (int nt = 0; nt < 4; ++nt) {
                    mma_bf16(acc[mt][nt], ah, bh[nt]);
                    mma_bf16(acc[mt][nt], ah, bl[nt]);
                    mma_bf16(acc[mt][nt], al, bh[nt]);
                }
            }
        }
        __syncthreads();
    }

#pragma unroll
    for (int mt = 0; mt < 4; ++mt) {
#pragma unroll
        for (int nt = 0; nt < 4; ++nt) {
            int r = bm + wm * 64 + mt * 16 + (lane >> 2);
            int c = bn + wn * 32 + nt * 8 + (lane & 3) * 2;
            if (SPLIT_OUT) {
                uint32_t hi0, lo0, hi1, lo1;
                split_pair(acc[mt][nt][0], acc[mt][nt][1], hi0, lo0);
                split_pair(acc[mt][nt][2], acc[mt][nt][3], hi1, lo1);
                *reinterpret_cast<uint32_t*>(&Chi[(size_t)r * N + c]) = hi0;
                *reinterpret_cast<uint32_t*>(&Clo[(size_t)r * N + c]) = lo0;
                *reinterpret_cast<uint32_t*>(&Chi[(size_t)(r + 8) * N + c]) = hi1;
                *reinterpret_cast<uint32_t*>(&Clo[(size_t)(r + 8) * N + c]) = lo1;
            } else {
                float b0 = 0.f, b1 = 0.f;
                if (HAS_BIAS) { b0 = bias[c]; b1 = bias[c + 1]; }
                *reinterpret_cast<float2*>(&C[(size_t)r * N + c]) =
                    make_float2(acc[mt][nt][0] + b0, acc[mt][nt][1] + b1);
                *reinterpret_cast<float2*>(&C[(size_t)(r + 8) * N + c]) =
                    make_float2(acc[mt][nt][2] + b0, acc[mt][nt][3] + b1);
            }
        }
    }
}

// ---------------------------------------------------------------------------
// HMMA split-bf16 causal flash attention.
// CTA: 128 q-rows x one (b,h). 8 warps, warp owns 16 rows. Bc=64.
// smem: Q staging 2x(128x72) overlaid on 2 KV stages of 4x(64x72).
// ---------------------------------------------------------------------------
#define ATT_PAD    72
#define ATT_ROWB   (ATT_PAD * 2)          // 144 B row stride
#define KV_TILE_B  (64 * ATT_ROWB)        // 9216
#define ATT_STAGE  (4 * KV_TILE_B)        // 36864
#define ATT_SMEM   (2 * ATT_STAGE)        // 73728

__global__ __launch_bounds__(256) void flash_attn_mma(
    const bf16* __restrict__ qkv_hi, const bf16* __restrict__ qkv_lo,
    bf16* __restrict__ ao_hi, bf16* __restrict__ ao_lo)
{
    extern __shared__ char smem[];
    const uint32_t sb = smem_u32(smem);
    const int tid = threadIdx.x, wid = tid >> 5, lane = tid & 31;
    const int qb = 15 - blockIdx.x;           // big q-blocks scheduled first
    const int bh = blockIdx.y;
    const int b = bh >> 4, h = bh & 15;
    const size_t tok0 = (size_t)b * S_LEN;

    const int lrow8 = lane & 7, lq = lane >> 3;
    const int a_roff = lrow8 + (lq & 1) * 8;
    const int a_coff = (lq >> 1) * 8;
    const int b_noff = lrow8 + (lq >> 1) * 8;
    const int b_coff = (lq & 1) * 8;
    const int v_roff = (lane & 7) + ((lane >> 3) & 1) * 8;   // trans: seq row
    const int v_coff = (lane >> 4) * 8;                      // trans: dh chunk

    // ---- stage Q (128 rows x 64, hi/lo) and pull fragments to registers
    {
        const size_t qrow0 = tok0 + (size_t)qb * 128;
#pragma unroll
        for (int arr = 0; arr < 2; ++arr) {
            const bf16* src = arr ? qkv_lo : qkv_hi;
            uint32_t dstb = sb + (uint32_t)arr * (128 * ATT_ROWB);
#pragma unroll
            for (int it = 0; it < 4; ++it) {
                int c = tid + it * 256;        // 0..1023
                int r = c >> 3, col = (c & 7) * 8;
                cp_async16(dstb + r * ATT_ROWB + col * 2,
                           src + (qrow0 + r) * QKV_LD + h * 192 + col);
            }
        }
        cp_commit();
        cp_wait<0>();
        __syncthreads();
    }
    uint32_t qh[4][4], ql[4][4];
#pragma unroll
    for (int j = 0; j < 4; ++j) {
        int rr = wid * 16 + a_roff;
        int cc = j * 16 + a_coff;
        ldsm_x4(qh[j][0], qh[j][1], qh[j][2], qh[j][3], sb + rr * ATT_ROWB + cc * 2);
        ldsm_x4(ql[j][0], ql[j][1], ql[j][2], ql[j][3],
                sb + 128 * ATT_ROWB + rr * ATT_ROWB + cc * 2);
    }
    __syncthreads();

    // KV stage loader: tiles t: 0=Khi 1=Klo 2=Vhi 3=Vlo (64 rows x 64)
    auto load_kv = [&](int s, int kb) {
        uint32_t base = sb + s * ATT_STAGE;
        const size_t krow0 = tok0 + (size_t)kb * 64;
#pragma unroll
        for (int t = 0; t < 4; ++t) {
            const bf16* src = (t & 1) ? qkv_lo : qkv_hi;
            int coloff = h * 192 + ((t < 2) ? 64 : 128);
            uint32_t tb = base + t * KV_TILE_B;
#pragma unroll
            for (int it = 0; it < 2; ++it) {
                int c = tid + it * 256;        // 0..511
                int r = c >> 3, col = (c & 7) * 8;
                cp_async16(tb + r * ATT_ROWB + col * 2,
                           src + (krow0 + r) * QKV_LD + coloff + col);
            }
        }
        cp_commit();
    };

    float o[8][4];
#pragma unroll
    for (int nt = 0; nt < 8; ++nt)
#pragma unroll
        for (int e = 0; e < 4; ++e) o[nt][e] = 0.f;
    float m0 = -1e30f, m1 = -1e30f, l0 = 0.f, l1 = 0.f;

    const int nkb = 2 * qb + 2;
    load_kv(0, 0);

    for (int kb = 0; kb < nkb; ++kb) {
        const int s = kb & 1;
        if (kb + 1 < nkb) { load_kv(s ^ 1, kb + 1); cp_wait<1>(); }
        else              { cp_wait<0>(); }
        __syncthreads();
        const uint32_t kbase = sb + s * ATT_STAGE;

        // ---- S = Q @ K^T (3-pass split)
        float sc[8][4];
#pragma unroll
        for (int nt = 0; nt < 8; ++nt)
#pragma unroll
            for (int e = 0; e < 4; ++e) sc[nt][e] = 0.f;

#pragma unroll
        for (int j = 0; j < 4; ++j) {
            uint32_t kfh[8][2], kfl[8][2];
#pragma unroll
            for (int p = 0; p < 4; ++p) {
                int nn = p * 16 + b_noff;
                int cc = j * 16 + b_coff;
                ldsm_x4(kfh[2 * p][0], kfh[2 * p][1], kfh[2 * p + 1][0], kfh[2 * p + 1][1],
                        kbase + 0 * KV_TILE_B + nn * ATT_ROWB + cc * 2);
                ldsm_x4(kfl[2 * p][0], kfl[2 * p][1], kfl[2 * p + 1][0], kfl[2 * p + 1][1],
                        kbase + 1 * KV_TILE_B + nn * ATT_ROWB + cc * 2);
            }
#pragma unroll
            for (int nt = 0; nt < 8; ++nt) {
                mma_bf16(sc[nt], qh[j], kfh[nt]);
                mma_bf16(sc[nt], ql[j], kfh[nt]);
                mma_bf16(sc[nt], qh[j], kfl[nt]);
            }
        }

        // scale + causal mask
#pragma unroll
        for (int nt = 0; nt < 8; ++nt)
#pragma unroll
            for (int e = 0; e < 4; ++e) sc[nt][e] *= 0.125f;

        if (kb >= 2 * qb) {
            const int gr0 = qb * 128 + wid * 16 + (lane >> 2);
#pragma unroll
            for (int nt = 0; nt < 8; ++nt) {
                int gc = kb * 64 + nt * 8 + (lane & 3) * 2;
                if (gc     > gr0)     sc[nt][0] = -1e30f;
                if (gc + 1 > gr0)     sc[nt][1] = -1e30f;
                if (gc     > gr0 + 8) sc[nt][2] = -1e30f;
                if (gc + 1 > gr0 + 8) sc[nt][3] = -1e30f;
            }
        }

        // ---- online softmax (rows: lane>>2 and +8; quad = 4 lanes share row)
        float mx0 = -1e30f, mx1 = -1e30f;
#pragma unroll
        for (int nt = 0; nt < 8; ++nt) {
            mx0 = fmaxf(mx0, fmaxf(sc[nt][0], sc[nt][1]));
            mx1 = fmaxf(mx1, fmaxf(sc[nt][2], sc[nt][3]));
        }
#pragma unroll
        for (int w = 1; w < 4; w <<= 1) {
            mx0 = fmaxf(mx0, __shfl_xor_sync(0xffffffffu, mx0, w));
            mx1 = fmaxf(mx1, __shfl_xor_sync(0xffffffffu, mx1, w));
        }
        float mn0 = fmaxf(m0, mx0), mn1 = fmaxf(m1, mx1);
        float c0 = __expf(m0 - mn0), c1 = __expf(m1 - mn1);
        m0 = mn0; m1 = mn1;
        float rs0 = 0.f, rs1 = 0.f;
#pragma unroll
        for (int nt = 0; nt < 8; ++nt) {
            sc[nt][0] = __expf(sc[nt][0] - mn0);
            sc[nt][1] = __expf(sc[nt][1] - mn0);
            sc[nt][2] = __expf(sc[nt][2] - mn1);
            sc[nt][3] = __expf(sc[nt][3] - mn1);
            rs0 += sc[nt][0] + sc[nt][1];
            rs1 += sc[nt][2] + sc[nt][3];
        }
#pragma unroll
        for (int w = 1; w < 4; w <<= 1) {
            rs0 += __shfl_xor_sync(0xffffffffu, rs0, w);
            rs1 += __shfl_xor_sync(0xffffffffu, rs1, w);
        }
        l0 = l0 * c0 + rs0;
        l1 = l1 * c1 + rs1;
#pragma unroll
        for (int nt = 0; nt < 8; ++nt) {
            o[nt][0] *= c0; o[nt][1] *= c0;
            o[nt][2] *= c1; o[nt][3] *= c1;
        }

        // ---- O += P @ V (3-pass split; P frags built from sc in registers)
#pragma unroll
        for (int j = 0; j < 4; ++j) {
            uint32_t ph[4], pl[4];
            split_pair(sc[2 * j][0],     sc[2 * j][1],     ph[0], pl[0]);
            split_pair(sc[2 * j][2],     sc[2 * j][3],     ph[1], pl[1]);
            split_pair(sc[2 * j + 1][0], sc[2 * j + 1][1], ph[2], pl[2]);
            split_pair(sc[2 * j + 1][2], sc[2 * j + 1][3], ph[3], pl[3]);

            uint32_t vfh[8][2], vfl[8][2];
#pragma unroll
            for (int p = 0; p < 4; ++p) {
                uint32_t ar = (j * 16 + v_roff) * ATT_ROWB + (p * 16 + v_coff) * 2;
                ldsm_x4_t(vfh[2 * p][0], vfh[2 * p][1], vfh[2 * p + 1][0], vfh[2 * p + 1][1],
                          kbase + 2 * KV_TILE_B + ar);
                ldsm_x4_t(vfl[2 * p][0], vfl[2 * p][1], vfl[2 * p + 1][0], vfl[2 * p + 1][1],
                          kbase + 3 * KV_TILE_B + ar);
            }
#pragma unroll
            for (int nt = 0; nt < 8; ++nt) {
                mma_bf16(o[nt], ph, vfh[nt]);
                mma_bf16(o[nt], pl, vfh[nt]);
                mma_bf16(o[nt], ph, vfl[nt]);
            }
        }
        __syncthreads();
    }

    // ---- normalize + write ao as bf16 hi/lo
    const float inv0 = 1.f / l0, inv1 = 1.f / l1;
    const int gr0 = qb * 128 + wid * 16 + (lane >> 2);
    const size_t row0 = (tok0 + gr0) * D_MODEL;
    const size_t row1 = (tok0 + gr0 + 8) * D_MODEL;
    const int colb = h * DH + (lane & 3) * 2;
#pragma unroll
    for (int nt = 0; nt < 8; ++nt) {
        int c = colb + nt * 8;
        uint32_t hi0, lo0, hi1, lo1;
        split_pair(o[nt][0] * inv0, o[nt][1] * inv0, hi0, lo0);
        split_pair(o[nt][2] * inv1, o[nt][3] * inv1, hi1, lo1);
        *reinterpret_cast<uint32_t*>(&ao_hi[row0 + c]) = hi0;
        *reinterpret_cast<uint32_t*>(&ao_lo[row0 + c]) = lo0;
        *reinterpret_cast<uint32_t*>(&ao_hi[row1 + c]) = hi1;
        *reinterpret_cast<uint32_t*>(&ao_lo[row1 + c]) = lo1;
    }
}

// ---------------------------------------------------------------------------
extern "C" void kernel_launch(void* const* d_in, const int* in_sizes, int n_in,
                              void* d_out, int out_size)
{
    (void)in_sizes; (void)n_in; (void)out_size;
    const float* x     = (const float*)d_in[0];
    const float* w_qkv = (const float*)d_in[1];
    const float* w_out = (const float*)d_in[2];
    const float* b_out = (const float*)d_in[3];
    float* out = (float*)d_out;

    bf16 *xhi, *xlo, *whi, *wlo, *qh, *qlv, *aohi, *aolo, *wohi, *wolo;
    cudaGetSymbolAddress((void**)&xhi, g_x_hi);
    cudaGetSymbolAddress((void**)&xlo, g_x_lo);
    cudaGetSymbolAddress((void**)&whi, g_wqkv_hi);
    cudaGetSymbolAddress((void**)&wlo, g_wqkv_lo);
    cudaGetSymbolAddress((void**)&qh,  g_qkv_hi);
    cudaGetSymbolAddress((void**)&qlv, g_qkv_lo);
    cudaGetSymbolAddress((void**)&aohi, g_ao_hi);
    cudaGetSymbolAddress((void**)&aolo, g_ao_lo);
    cudaGetSymbolAddress((void**)&wohi, g_wout_hi);
    cudaGetSymbolAddress((void**)&wolo, g_wout_lo);

    cudaFuncSetAttribute(gemm_mma<false, true>,
                         cudaFuncAttributeMaxDynamicSharedMemorySize, GEMM_SMEM);
    cudaFuncSetAttribute(gemm_mma<true, false>,
                         cudaFuncAttributeMaxDynamicSharedMemorySize, GEMM_SMEM);
    cudaFuncSetAttribute(flash_attn_mma,
                         cudaFuncAttributeMaxDynamicSharedMemorySize, ATT_SMEM);

    // 1) split-pack inputs
    {
        int n4 = M_TOK * D_MODEL / 4;
        pack_split<<<(n4 + 255) / 256, 256>>>(x, xhi, xlo, n4);
        n4 = QKV_LD * D_MODEL / 4;
        pack_split<<<(n4 + 255) / 256, 256>>>(w_qkv, whi, wlo, n4);
        n4 = D_MODEL * D_MODEL / 4;
        pack_split<<<(n4 + 255) / 256, 256>>>(w_out, wohi, wolo, n4);
    }

    // 2) QKV projection -> bf16 hi/lo directly
    gemm_mma<false, true><<<dim3(QKV_LD / 128, M_TOK / 128), 256, GEMM_SMEM>>>(
        xhi, xlo, whi, wlo, nullptr, nullptr, qh, qlv, M_TOK, QKV_LD, D_MODEL);

    // 3) causal flash attention on tensor cores -> ao bf16 hi/lo
    flash_attn_mma<<<dim3(S_LEN / 128, 2 * H_NUM), 256, ATT_SMEM>>>(qh, qlv, aohi, aolo);

    // 4) output projection + bias -> fp32 out
    gemm_mma<true, false><<<dim3(D_MODEL / 128, M_TOK / 128), 256, GEMM_SMEM>>>(
        aohi, aolo, wohi, wolo, b_out, out, nullptr, nullptr, M_TOK, D_MODEL, D_MODEL);
}

// round 7
// speedup vs baseline: 2.5152x; 1.0228x over previous
#include <cuda_runtime.h>
#include <cuda_bf16.h>
#include <cuda_fp16.h>
#include <cstdint>
#include <cstddef>

#define S_LEN   2048
#define D_MODEL 1024
#define H_NUM   16
#define DH      64
#define M_TOK   4096
#define QKV_LD  3072

// ---------------------------------------------------------------------------
// Device scratch (all 2-byte words; interpretation per kernel)
// ---------------------------------------------------------------------------
__device__ uint16_t g_x_hi   [(size_t)M_TOK * D_MODEL];   // bf16
__device__ uint16_t g_x_lo   [(size_t)M_TOK * D_MODEL];   // bf16
__device__ uint16_t g_wqkv_hi[(size_t)QKV_LD * D_MODEL];  // bf16
__device__ uint16_t g_wqkv_lo[(size_t)QKV_LD * D_MODEL];  // bf16
__device__ uint16_t g_qkv_hi [(size_t)M_TOK * QKV_LD];    // fp16
__device__ uint16_t g_qkv_lo [(size_t)M_TOK * QKV_LD];    // fp16
__device__ uint16_t g_ao_hi  [(size_t)M_TOK * D_MODEL];   // fp16
__device__ uint16_t g_ao_lo  [(size_t)M_TOK * D_MODEL];   // fp16
__device__ uint16_t g_wout_hi[(size_t)D_MODEL * D_MODEL]; // fp16 hi
__device__ uint16_t g_wout_lo[(size_t)D_MODEL * D_MODEL]; // fp16 lo

// ---------------------------------------------------------------------------
// PTX helpers
// ---------------------------------------------------------------------------
__device__ __forceinline__ uint32_t smem_u32(const void* p) {
    uint32_t a;
    asm("{ .reg .u64 t; cvta.to.shared.u64 t, %1; cvt.u32.u64 %0, t; }" : "=r"(a) : "l"(p));
    return a;
}
__device__ __forceinline__ void cp_async16(uint32_t dst, const void* src) {
    asm volatile("cp.async.cg.shared.global [%0], [%1], 16;" :: "r"(dst), "l"(src));
}
__device__ __forceinline__ void cp_commit() {
    asm volatile("cp.async.commit_group;" ::: "memory");
}
template <int N>
__device__ __forceinline__ void cp_wait() {
    asm volatile("cp.async.wait_group %0;" :: "n"(N) : "memory");
}
__device__ __forceinline__ void ldsm_x4(uint32_t& r0, uint32_t& r1, uint32_t& r2,
                                        uint32_t& r3, uint32_t a) {
    asm volatile("ldmatrix.sync.aligned.m8n8.x4.shared.b16 {%0,%1,%2,%3}, [%4];"
                 : "=r"(r0), "=r"(r1), "=r"(r2), "=r"(r3) : "r"(a));
}
__device__ __forceinline__ void ldsm_x4_t(uint32_t& r0, uint32_t& r1, uint32_t& r2,
                                          uint32_t& r3, uint32_t a) {
    asm volatile("ldmatrix.sync.aligned.m8n8.x4.trans.shared.b16 {%0,%1,%2,%3}, [%4];"
                 : "=r"(r0), "=r"(r1), "=r"(r2), "=r"(r3) : "r"(a));
}
__device__ __forceinline__ void mma_bf16(float* d, const uint32_t* a, const uint32_t* b) {
    asm volatile("mma.sync.aligned.m16n8k16.row.col.f32.bf16.bf16.f32 "
                 "{%0,%1,%2,%3}, {%4,%5,%6,%7}, {%8,%9}, {%0,%1,%2,%3};"
                 : "+f"(d[0]), "+f"(d[1]), "+f"(d[2]), "+f"(d[3])
                 : "r"(a[0]), "r"(a[1]), "r"(a[2]), "r"(a[3]), "r"(b[0]), "r"(b[1]));
}
__device__ __forceinline__ void mma_f16(float* d, const uint32_t* a, const uint32_t* b) {
    asm volatile("mma.sync.aligned.m16n8k16.row.col.f32.f16.f16.f32 "
                 "{%0,%1,%2,%3}, {%4,%5,%6,%7}, {%8,%9}, {%0,%1,%2,%3};"
                 : "+f"(d[0]), "+f"(d[1]), "+f"(d[2]), "+f"(d[3])
                 : "r"(a[0]), "r"(a[1]), "r"(a[2]), "r"(a[3]), "r"(b[0]), "r"(b[1]));
}
// fp32 pair -> bf16 hi/lo words
__device__ __forceinline__ void split_pair_bf(float a, float b, uint32_t& hi, uint32_t& lo) {
    __nv_bfloat16 ha = __float2bfloat16(a), hb = __float2bfloat16(b);
    hi = (uint32_t)__bfloat16_as_ushort(ha) | ((uint32_t)__bfloat16_as_ushort(hb) << 16);
    lo = (uint32_t)__bfloat16_as_ushort(__float2bfloat16(a - __bfloat162float(ha))) |
         ((uint32_t)__bfloat16_as_ushort(__float2bfloat16(b - __bfloat162float(hb))) << 16);
}
// fp32 pair -> fp16 hi/lo words
__device__ __forceinline__ void split_pair_h(float a, float b, uint32_t& hi, uint32_t& lo) {
    __half ha = __float2half_rn(a), hb = __float2half_rn(b);
    hi = (uint32_t)__half_as_ushort(ha) | ((uint32_t)__half_as_ushort(hb) << 16);
    lo = (uint32_t)__half_as_ushort(__float2half_rn(a - __half2float(ha))) |
         ((uint32_t)__half_as_ushort(__float2half_rn(b - __half2float(hb))) << 16);
}

// ---------------------------------------------------------------------------
// Packers
// ---------------------------------------------------------------------------
__global__ __launch_bounds__(256) void pack_split_bf(
    const float* __restrict__ in, uint16_t* __restrict__ hi,
    uint16_t* __restrict__ lo, int n4)
{
    int i = blockIdx.x * 256 + threadIdx.x;
    if (i >= n4) return;
    float4 v = reinterpret_cast<const float4*>(in)[i];
    uint32_t h0, l0, h1, l1;
    split_pair_bf(v.x, v.y, h0, l0);
    split_pair_bf(v.z, v.w, h1, l1);
    reinterpret_cast<uint2*>(hi)[i] = make_uint2(h0, h1);
    reinterpret_cast<uint2*>(lo)[i] = make_uint2(l0, l1);
}
__global__ __launch_bounds__(256) void pack_split_h(
    const float* __restrict__ in, uint16_t* __restrict__ hi,
    uint16_t* __restrict__ lo, int n4)
{
    int i = blockIdx.x * 256 + threadIdx.x;
    if (i >= n4) return;
    float4 v = reinterpret_cast<const float4*>(in)[i];
    uint32_t h0, l0, h1, l1;
    split_pair_h(v.x, v.y, h0, l0);
    split_pair_h(v.z, v.w, h1, l1);
    reinterpret_cast<uint2*>(hi)[i] = make_uint2(h0, h1);
    reinterpret_cast<uint2*>(lo)[i] = make_uint2(l0, l1);
}

// ---------------------------------------------------------------------------
// HMMA GEMM: C[M,N] = A @ B^T.
// 3-pass split: Ahi·Bhi + Alo·Bhi + Ahi·Blo (bf16 if !HALF, fp16 if HALF).
// CTA 128x128, BK=32, 8 warps (2x4), 3-stage cp.async pipeline.
// PAD_K = 40 elems -> 80 B row stride: multiple of 16 (cp.async legal) and
// conflict-free ldmatrix (banks step 20 mod 32, 8 distinct).
// ---------------------------------------------------------------------------
#define BK        32
#define PAD_K     40
#define TILE_SMB  (128 * PAD_K * 2)      // 10240 B

template <bool HAS_BIAS, bool SPLIT_OUT, bool HALF>
__global__ __launch_bounds__(256) void gemm_mma(
    const uint16_t* __restrict__ Ahi, const uint16_t* __restrict__ Alo,
    const uint16_t* __restrict__ Bhi, const uint16_t* __restrict__ Blo,
    const float* __restrict__ bias, float* __restrict__ C,
    uint16_t* __restrict__ Chi, uint16_t* __restrict__ Clo,
    int M, int N, int K)
{
    constexpr int STAGE_B = 4 * TILE_SMB;

    extern __shared__ char smem[];
    const uint32_t sb = smem_u32(smem);
    const int tid = threadIdx.x;
    const int wid = tid >> 5;
    const int lane = tid & 31;
    const int bm = blockIdx.y * 128;
    const int bn = blockIdx.x * 128;
    const int wm = wid >> 2;
    const int wn = wid & 3;
    const int nk = K / BK;

    const int r0 = tid >> 2, q0 = tid & 3;
    const int r1 = r0 + 64;

    const uint16_t* gA0 = Ahi + (size_t)bm * K;
    const uint16_t* gA1 = Alo + (size_t)bm * K;
    const uint16_t* gB0 = Bhi + (size_t)bn * K;
    const uint16_t* gB1 = Blo + (size_t)bn * K;

    auto load_stage = [&](int s, int k0) {
        uint32_t base = sb + s * STAGE_B;
        const uint32_t doff = (r0 * PAD_K + q0 * 8) * 2;
        const uint32_t doff1 = (r1 * PAD_K + q0 * 8) * 2;
        const size_t so0 = (size_t)r0 * K + k0 + q0 * 8;
        const size_t so1 = (size_t)r1 * K + k0 + q0 * 8;
        cp_async16(base + 0 * TILE_SMB + doff,  gA0 + so0);
        cp_async16(base + 0 * TILE_SMB + doff1, gA0 + so1);
        cp_async16(base + 1 * TILE_SMB + doff,  gA1 + so0);
        cp_async16(base + 1 * TILE_SMB + doff1, gA1 + so1);
        cp_async16(base + 2 * TILE_SMB + doff,  gB0 + so0);
        cp_async16(base + 2 * TILE_SMB + doff1, gB0 + so1);
        cp_async16(base + 3 * TILE_SMB + doff,  gB1 + so0);
        cp_async16(base + 3 * TILE_SMB + doff1, gB1 + so1);
        cp_commit();
    };

    float acc[4][4][4];
#pragma unroll
    for (int mt = 0; mt < 4; ++mt)
#pragma unroll
        for (int nt = 0; nt < 4; ++nt)
#pragma unroll
            for (int e = 0; e < 4; ++e) acc[mt][nt][e] = 0.f;

    const int lrow8 = lane & 7;
    const int lq    = lane >> 3;
    const int a_roff = lrow8 + (lq & 1) * 8;
    const int a_coff = (lq >> 1) * 8;
    const int b_noff = lrow8 + (lq >> 1) * 8;
    const int b_coff = (lq & 1) * 8;

    load_stage(0, 0);
    if (nk > 1) load_stage(1, BK);

    for (int i = 0; i < nk; ++i) {
        const int s = i % 3;
        if (i + 2 < nk) { load_stage((i + 2) % 3, (i + 2) * BK); cp_wait<2>(); }
        else if (i + 1 < nk) { cp_wait<1>(); }
        else { cp_wait<0>(); }
        __syncthreads();

        const uint32_t stg = sb + s * STAGE_B;
#pragma unroll
        for (int kk = 0; kk < BK; kk += 16) {
            uint32_t bh[4][2], bl[4][2];
#pragma unroll
            for (int ntp = 0; ntp < 2; ++ntp) {
                int nidx = wn * 32 + ntp * 16 + b_noff;
                int cidx = kk + b_coff;
                ldsm_x4(bh[2 * ntp][0], bh[2 * ntp][1], bh[2 * ntp + 1][0], bh[2 * ntp + 1][1],
                        stg + 2 * TILE_SMB + (nidx * PAD_K + cidx) * 2);
                ldsm_x4(bl[2 * ntp][0], bl[2 * ntp][1], bl[2 * ntp + 1][0], bl[2 * ntp + 1][1],
                        stg + 3 * TILE_SMB + (nidx * PAD_K + cidx) * 2);
            }
#pragma unroll
            for (int mt = 0; mt < 4; ++mt) {
                int midx = wm * 64 + mt * 16 + a_roff;
                int cidx = kk + a_coff;
                uint32_t ah[4], al[4];
                ldsm_x4(ah[0], ah[1], ah[2], ah[3], stg + 0 * TILE_SMB + (midx * PAD_K + cidx) * 2);
                ldsm_x4(al[0], al[1], al[2], al[3], stg + 1 * TILE_SMB + (midx * PAD_K + cidx) * 2);
#pragma unroll
                for (int nt = 0; nt < 4; ++nt) {
                    if (HALF) {
                        mma_f16(acc[mt][nt], ah, bh[nt]);
                        mma_f16(acc[mt][nt], al, bh[nt]);
                        mma_f16(acc[mt][nt], ah, bl[nt]);
                    } else {
                        mma_bf16(acc[mt][nt], ah, bh[nt]);
                        mma_bf16(acc[mt][nt], al, bh[nt]);
                        mma_bf16(acc[mt][nt], ah, bl[nt]);
                    }
                }
            }
        }
        __syncthreads();
    }

#pragma unroll
    for (int mt = 0; mt < 4; ++mt) {
#pragma unroll
        for (int nt = 0; nt < 4; ++nt) {
            int r = bm + wm * 64 + mt * 16 + (lane >> 2);
            int c = bn + wn * 32 + nt * 8 + (lane & 3) * 2;
            if (SPLIT_OUT) {
                uint32_t hi0, lo0, hi1, lo1;
                split_pair_h(acc[mt][nt][0], acc[mt][nt][1], hi0, lo0);
                split_pair_h(acc[mt][nt][2], acc[mt][nt][3], hi1, lo1);
                *reinterpret_cast<uint32_t*>(&Chi[(size_t)r * N + c]) = hi0;
                *reinterpret_cast<uint32_t*>(&Clo[(size_t)r * N + c]) = lo0;
                *reinterpret_cast<uint32_t*>(&Chi[(size_t)(r + 8) * N + c]) = hi1;
                *reinterpret_cast<uint32_t*>(&Clo[(size_t)(r + 8) * N + c]) = lo1;
            } else {
                float b0 = 0.f, b1 = 0.f;
                if (HAS_BIAS) { b0 = bias[c]; b1 = bias[c + 1]; }
                *reinterpret_cast<float2*>(&C[(size_t)r * N + c]) =
                    make_float2(acc[mt][nt][0] + b0, acc[mt][nt][1] + b1);
                *reinterpret_cast<float2*>(&C[(size_t)(r + 8) * N + c]) =
                    make_float2(acc[mt][nt][2] + b0, acc[mt][nt][3] + b1);
            }
        }
    }
}

// ---------------------------------------------------------------------------
// 2-pass fp16 causal flash attention.
// S = (Qhi+Qlo)·Khi ; O += (Phi+Plo)·Vhi.  K/V lo never loaded.
// CTA: 128 q-rows x (b,h). 8 warps. Bc=64. 3-stage KV pipeline.
// Row stride 144 B (multiple of 16).
// ---------------------------------------------------------------------------
#define ATT_PAD    72
#define ATT_ROWB   (ATT_PAD * 2)          // 144 B
#define KV_TILE_B  (64 * ATT_ROWB)        // 9216
#define ATT_STAGE  (2 * KV_TILE_B)        // 18432 (Khi, Vhi)
#define ATT_SMEM   (3 * ATT_STAGE)        // 55296

__global__ __launch_bounds__(256) void flash_attn_mma(
    const uint16_t* __restrict__ qkv_hi, const uint16_t* __restrict__ qkv_lo,
    uint16_t* __restrict__ ao_hi, uint16_t* __restrict__ ao_lo)
{
    extern __shared__ char smem[];
    const uint32_t sb = smem_u32(smem);
    const int tid = threadIdx.x, wid = tid >> 5, lane = tid & 31;
    const int qb = 15 - blockIdx.x;
    const int bh = blockIdx.y;
    const int b = bh >> 4, h = bh & 15;
    const size_t tok0 = (size_t)b * S_LEN;

    const int lrow8 = lane & 7, lq = lane >> 3;
    const int a_roff = lrow8 + (lq & 1) * 8;
    const int a_coff = (lq >> 1) * 8;
    const int b_noff = lrow8 + (lq >> 1) * 8;
    const int b_coff = (lq & 1) * 8;
    const int v_roff = (lane & 7) + ((lane >> 3) & 1) * 8;
    const int v_coff = (lane >> 4) * 8;

    // ---- stage Q (hi/lo) into smem; pull frags to regs
    {
        const size_t qrow0 = tok0 + (size_t)qb * 128;
#pragma unroll
        for (int arr = 0; arr < 2; ++arr) {
            const uint16_t* src = arr ? qkv_lo : qkv_hi;
            uint32_t dstb = sb + (uint32_t)arr * (128 * ATT_ROWB);
#pragma unroll
            for (int it = 0; it < 4; ++it) {
                int c = tid + it * 256;
                int r = c >> 3, col = (c & 7) * 8;
                cp_async16(dstb + r * ATT_ROWB + col * 2,
                           src + (qrow0 + r) * QKV_LD + h * 192 + col);
            }
        }
        cp_commit();
        cp_wait<0>();
        __syncthreads();
    }
    uint32_t qh[4][4], ql[4][4];
#pragma unroll
    for (int j = 0; j < 4; ++j) {
        int rr = wid * 16 + a_roff;
        int cc = j * 16 + a_coff;
        ldsm_x4(qh[j][0], qh[j][1], qh[j][2], qh[j][3], sb + rr * ATT_ROWB + cc * 2);
        ldsm_x4(ql[j][0], ql[j][1], ql[j][2], ql[j][3],
                sb + 128 * ATT_ROWB + rr * ATT_ROWB + cc * 2);
    }
    __syncthreads();

    // KV stage: Khi tile + Vhi tile
    auto load_kv = [&](int s, int kb) {
        uint32_t base = sb + s * ATT_STAGE;
        const size_t krow0 = tok0 + (size_t)kb * 64;
        const int koff = h * 192 + 64, voff = h * 192 + 128;
#pragma unroll
        for (int it = 0; it < 2; ++it) {
            int c = tid + it * 256;
            int r = c >> 3, col = (c & 7) * 8;
            const size_t go = (krow0 + r) * QKV_LD + col;
            cp_async16(base + r * ATT_ROWB + col * 2, qkv_hi + go + koff);
            cp_async16(base + KV_TILE_B + r * ATT_ROWB + col * 2, qkv_hi + go + voff);
        }
        cp_commit();
    };

    float o[8][4];
#pragma unroll
    for (int nt = 0; nt < 8; ++nt)
#pragma unroll
        for (int e = 0; e < 4; ++e) o[nt][e] = 0.f;
    float m0 = -1e30f, m1 = -1e30f, l0 = 0.f, l1 = 0.f;

    const int nkb = 2 * qb + 2;
    load_kv(0, 0);
    if (nkb > 1) load_kv(1, 1);

    for (int kb = 0; kb < nkb; ++kb) {
        const int s = kb % 3;
        if (kb + 2 < nkb) { load_kv((kb + 2) % 3, kb + 2); cp_wait<2>(); }
        else if (kb + 1 < nkb) { cp_wait<1>(); }
        else { cp_wait<0>(); }
        __syncthreads();
        const uint32_t kbase = sb + s * ATT_STAGE;

        // ---- S = Q @ Khi^T (2-pass)
        float sc[8][4];
#pragma unroll
        for (int nt = 0; nt < 8; ++nt)
#pragma unroll
            for (int e = 0; e < 4; ++e) sc[nt][e] = 0.f;

#pragma unroll
        for (int j = 0; j < 4; ++j) {
            uint32_t kf[8][2];
#pragma unroll
            for (int p = 0; p < 4; ++p) {
                int nn = p * 16 + b_noff;
                int cc = j * 16 + b_coff;
                ldsm_x4(kf[2 * p][0], kf[2 * p][1], kf[2 * p + 1][0], kf[2 * p + 1][1],
                        kbase + nn * ATT_ROWB + cc * 2);
            }
#pragma unroll
            for (int nt = 0; nt < 8; ++nt) {
                mma_f16(sc[nt], qh[j], kf[nt]);
                mma_f16(sc[nt], ql[j], kf[nt]);
            }
        }

#pragma unroll
        for (int nt = 0; nt < 8; ++nt)
#pragma unroll
            for (int e = 0; e < 4; ++e) sc[nt][e] *= 0.125f;

        if (kb >= 2 * qb) {
            const int gr0 = qb * 128 + wid * 16 + (lane >> 2);
#pragma unroll
            for (int nt = 0; nt < 8; ++nt) {
                int gc = kb * 64 + nt * 8 + (lane & 3) * 2;
                if (gc     > gr0)     sc[nt][0] = -1e30f;
                if (gc + 1 > gr0)     sc[nt][1] = -1e30f;
                if (gc     > gr0 + 8) sc[nt][2] = -1e30f;
                if (gc + 1 > gr0 + 8) sc[nt][3] = -1e30f;
            }
        }

        // ---- online softmax
        float mx0 = -1e30f, mx1 = -1e30f;
#pragma unroll
        for (int nt = 0; nt < 8; ++nt) {
            mx0 = fmaxf(mx0, fmaxf(sc[nt][0], sc[nt][1]));
            mx1 = fmaxf(mx1, fmaxf(sc[nt][2], sc[nt][3]));
        }
#pragma unroll
        for (int w = 1; w < 4; w <<= 1) {
            mx0 = fmaxf(mx0, __shfl_xor_sync(0xffffffffu, mx0, w));
            mx1 = fmaxf(mx1, __shfl_xor_sync(0xffffffffu, mx1, w));
        }
        float mn0 = fmaxf(m0, mx0), mn1 = fmaxf(m1, mx1);
        float c0 = __expf(m0 - mn0), c1 = __expf(m1 - mn1);
        m0 = mn0; m1 = mn1;
        float rs0 = 0.f, rs1 = 0.f;
#pragma unroll
        for (int nt = 0; nt < 8; ++nt) {
            sc[nt][0] = __expf(sc[nt][0] - mn0);
            sc[nt][1] = __expf(sc[nt][1] - mn0);
            sc[nt][2] = __expf(sc[nt][2] - mn1);
            sc[nt][3] = __expf(sc[nt][3] - mn1);
            rs0 += sc[nt][0] + sc[nt][1];
            rs1 += sc[nt][2] + sc[nt][3];
        }
#pragma unroll
        for (int w = 1; w < 4; w <<= 1) {
            rs0 += __shfl_xor_sync(0xffffffffu, rs0, w);
            rs1 += __shfl_xor_sync(0xffffffffu, rs1, w);
        }
        l0 = l0 * c0 + rs0;
        l1 = l1 * c1 + rs1;
#pragma unroll
        for (int nt = 0; nt < 8; ++nt) {
            o[nt][0] *= c0; o[nt][1] *= c0;
            o[nt][2] *= c1; o[nt][3] *= c1;
        }

        // ---- O += P @ Vhi (2-pass; P split fp16 in regs)
#pragma unroll
        for (int j = 0; j < 4; ++j) {
            uint32_t ph[4], pl[4];
            split_pair_h(sc[2 * j][0],     sc[2 * j][1],     ph[0], pl[0]);
            split_pair_h(sc[2 * j][2],     sc[2 * j][3],     ph[1], pl[1]);
            split_pair_h(sc[2 * j + 1][0], sc[2 * j + 1][1], ph[2], pl[2]);
            split_pair_h(sc[2 * j + 1][2], sc[2 * j + 1][3], ph[3], pl[3]);

            uint32_t vf[8][2];
#pragma unroll
            for (int p = 0; p < 4; ++p) {
                uint32_t ar = (j * 16 + v_roff) * ATT_ROWB + (p * 16 + v_coff) * 2;
                ldsm_x4_t(vf[2 * p][0], vf[2 * p][1], vf[2 * p + 1][0], vf[2 * p + 1][1],
                          kbase + KV_TILE_B + ar);
            }
#pragma unroll
            for (int nt = 0; nt < 8; ++nt) {
                mma_f16(o[nt], ph, vf[nt]);
                mma_f16(o[nt], pl, vf[nt]);
            }
        }
        __syncthreads();
    }

    // ---- normalize + write ao as fp16 hi/lo
    const float inv0 = 1.f / l0, inv1 = 1.f / l1;
    const int gr0 = qb * 128 + wid * 16 + (lane >> 2);
    const size_t row0 = (tok0 + gr0) * D_MODEL;
    const size_t row1 = (tok0 + gr0 + 8) * D_MODEL;
    const int colb = h * DH + (lane & 3) * 2;
#pragma unroll
    for (int nt = 0; nt < 8; ++nt) {
        int c = colb + nt * 8;
        uint32_t hi0, lo0, hi1, lo1;
        split_pair_h(o[nt][0] * inv0, o[nt][1] * inv0, hi0, lo0);
        split_pair_h(o[nt][2] * inv1, o[nt][3] * inv1, hi1, lo1);
        *reinterpret_cast<uint32_t*>(&ao_hi[row0 + c]) = hi0;
        *reinterpret_cast<uint32_t*>(&ao_lo[row0 + c]) = lo0;
        *reinterpret_cast<uint32_t*>(&ao_hi[row1 + c]) = hi1;
        *reinterpret_cast<uint32_t*>(&ao_lo[row1 + c]) = lo1;
    }
}

// ---------------------------------------------------------------------------
extern "C" void kernel_launch(void* const* d_in, const int* in_sizes, int n_in,
                              void* d_out, int out_size)
{
    (void)in_sizes; (void)n_in; (void)out_size;
    const float* x     = (const float*)d_in[0];
    const float* w_qkv = (const float*)d_in[1];
    const float* w_out = (const float*)d_in[2];
    const float* b_out = (const float*)d_in[3];
    float* out = (float*)d_out;

    uint16_t *xhi, *xlo, *whi, *wlo, *qh, *qlo, *aohi, *aolo, *wohi, *wolo;
    cudaGetSymbolAddress((void**)&xhi, g_x_hi);
    cudaGetSymbolAddress((void**)&xlo, g_x_lo);
    cudaGetSymbolAddress((void**)&whi, g_wqkv_hi);
    cudaGetSymbolAddress((void**)&wlo, g_wqkv_lo);
    cudaGetSymbolAddress((void**)&qh,  g_qkv_hi);
    cudaGetSymbolAddress((void**)&qlo, g_qkv_lo);
    cudaGetSymbolAddress((void**)&aohi, g_ao_hi);
    cudaGetSymbolAddress((void**)&aolo, g_ao_lo);
    cudaGetSymbolAddress((void**)&wohi, g_wout_hi);
    cudaGetSymbolAddress((void**)&wolo, g_wout_lo);

    constexpr int G_SMEM = 3 * 4 * TILE_SMB;   // 122880
    cudaFuncSetAttribute((gemm_mma<false, true, false>),
                         cudaFuncAttributeMaxDynamicSharedMemorySize, G_SMEM);
    cudaFuncSetAttribute((gemm_mma<true, false, true>),
                         cudaFuncAttributeMaxDynamicSharedMemorySize, G_SMEM);
    cudaFuncSetAttribute(flash_attn_mma,
                         cudaFuncAttributeMaxDynamicSharedMemorySize, ATT_SMEM);

    // 1) pack inputs: x, w_qkv -> bf16 hi/lo; w_out -> fp16 hi/lo
    {
        int n4 = M_TOK * D_MODEL / 4;
        pack_split_bf<<<(n4 + 255) / 256, 256>>>(x, xhi, xlo, n4);
        n4 = QKV_LD * D_MODEL / 4;
        pack_split_bf<<<(n4 + 255) / 256, 256>>>(w_qkv, whi, wlo, n4);
        n4 = D_MODEL * D_MODEL / 4;
        pack_split_h<<<(n4 + 255) / 256, 256>>>(w_out, wohi, wolo, n4);
    }

    // 2) QKV projection (3-pass bf16) -> qkv fp16 hi/lo
    gemm_mma<false, true, false><<<dim3(QKV_LD / 128, M_TOK / 128), 256, G_SMEM>>>(
        xhi, xlo, whi, wlo, nullptr, nullptr, qh, qlo, M_TOK, QKV_LD, D_MODEL);

    // 3) causal flash attention (2-pass fp16) -> ao fp16 hi/lo
    flash_attn_mma<<<dim3(S_LEN / 128, 2 * H_NUM), 256, ATT_SMEM>>>(qh, qlo, aohi, aolo);

    // 4) output projection (3-pass fp16) + bias -> fp32 out
    gemm_mma<true, false, true><<<dim3(D_MODEL / 128, M_TOK / 128), 256, G_SMEM>>>(
        aohi, aolo, wohi, wolo, b_out, out, nullptr, nullptr, M_TOK, D_MODEL, D_MODEL);
}

// round 8
// speedup vs baseline: 3.1875x; 1.2673x over previous
#include <cuda_runtime.h>
#include <cuda_bf16.h>
#include <cuda_fp16.h>
#include <cstdint>
#include <cstddef>

#define S_LEN   2048
#define D_MODEL 1024
#define H_NUM   16
#define DH      64
#define M_TOK   4096
#define QKV_LD  3072

// ---------------------------------------------------------------------------
// Device scratch (2-byte words, fp16 unless noted)
// ---------------------------------------------------------------------------
__device__ uint16_t g_x_hi  [(size_t)M_TOK * D_MODEL];
__device__ uint16_t g_x_lo  [(size_t)M_TOK * D_MODEL];
__device__ uint16_t g_wqkv_h[(size_t)QKV_LD * D_MODEL];   // single fp16
__device__ uint16_t g_qkv_hi[(size_t)M_TOK * QKV_LD];
__device__ uint16_t g_qkv_lo[(size_t)M_TOK * QKV_LD];
__device__ uint16_t g_ao_hi [(size_t)M_TOK * D_MODEL];
__device__ uint16_t g_ao_lo [(size_t)M_TOK * D_MODEL];
__device__ uint16_t g_wout_hi[(size_t)D_MODEL * D_MODEL];
__device__ uint16_t g_wout_lo[(size_t)D_MODEL * D_MODEL];

// ---------------------------------------------------------------------------
// PTX helpers
// ---------------------------------------------------------------------------
__device__ __forceinline__ uint32_t smem_u32(const void* p) {
    uint32_t a;
    asm("{ .reg .u64 t; cvta.to.shared.u64 t, %1; cvt.u32.u64 %0, t; }" : "=r"(a) : "l"(p));
    return a;
}
__device__ __forceinline__ void cp_async16(uint32_t dst, const void* src) {
    asm volatile("cp.async.cg.shared.global [%0], [%1], 16;" :: "r"(dst), "l"(src));
}
__device__ __forceinline__ void cp_commit() {
    asm volatile("cp.async.commit_group;" ::: "memory");
}
template <int N>
__device__ __forceinline__ void cp_wait() {
    asm volatile("cp.async.wait_group %0;" :: "n"(N) : "memory");
}
__device__ __forceinline__ void ldsm_x4(uint32_t& r0, uint32_t& r1, uint32_t& r2,
                                        uint32_t& r3, uint32_t a) {
    asm volatile("ldmatrix.sync.aligned.m8n8.x4.shared.b16 {%0,%1,%2,%3}, [%4];"
                 : "=r"(r0), "=r"(r1), "=r"(r2), "=r"(r3) : "r"(a));
}
__device__ __forceinline__ void ldsm_x4_t(uint32_t& r0, uint32_t& r1, uint32_t& r2,
                                          uint32_t& r3, uint32_t a) {
    asm volatile("ldmatrix.sync.aligned.m8n8.x4.trans.shared.b16 {%0,%1,%2,%3}, [%4];"
                 : "=r"(r0), "=r"(r1), "=r"(r2), "=r"(r3) : "r"(a));
}
__device__ __forceinline__ void mma_f16(float* d, const uint32_t* a, const uint32_t* b) {
    asm volatile("mma.sync.aligned.m16n8k16.row.col.f32.f16.f16.f32 "
                 "{%0,%1,%2,%3}, {%4,%5,%6,%7}, {%8,%9}, {%0,%1,%2,%3};"
                 : "+f"(d[0]), "+f"(d[1]), "+f"(d[2]), "+f"(d[3])
                 : "r"(a[0]), "r"(a[1]), "r"(a[2]), "r"(a[3]), "r"(b[0]), "r"(b[1]));
}
// fp32 pair -> fp16 hi/lo words
__device__ __forceinline__ void split_pair_h(float a, float b, uint32_t& hi, uint32_t& lo) {
    __half ha = __float2half_rn(a), hb = __float2half_rn(b);
    hi = (uint32_t)__half_as_ushort(ha) | ((uint32_t)__half_as_ushort(hb) << 16);
    lo = (uint32_t)__half_as_ushort(__float2half_rn(a - __half2float(ha))) |
         ((uint32_t)__half_as_ushort(__float2half_rn(b - __half2float(hb))) << 16);
}

// ---------------------------------------------------------------------------
// Packers
// ---------------------------------------------------------------------------
__global__ __launch_bounds__(256) void pack_split_h(
    const float* __restrict__ in, uint16_t* __restrict__ hi,
    uint16_t* __restrict__ lo, int n4)
{
    int i = blockIdx.x * 256 + threadIdx.x;
    if (i >= n4) return;
    float4 v = reinterpret_cast<const float4*>(in)[i];
    uint32_t h0, l0, h1, l1;
    split_pair_h(v.x, v.y, h0, l0);
    split_pair_h(v.z, v.w, h1, l1);
    reinterpret_cast<uint2*>(hi)[i] = make_uint2(h0, h1);
    reinterpret_cast<uint2*>(lo)[i] = make_uint2(l0, l1);
}
__global__ __launch_bounds__(256) void pack_h16(
    const float* __restrict__ in, uint16_t* __restrict__ hi, int n4)
{
    int i = blockIdx.x * 256 + threadIdx.x;
    if (i >= n4) return;
    float4 v = reinterpret_cast<const float4*>(in)[i];
    uint32_t h0 = (uint32_t)__half_as_ushort(__float2half_rn(v.x)) |
                  ((uint32_t)__half_as_ushort(__float2half_rn(v.y)) << 16);
    uint32_t h1 = (uint32_t)__half_as_ushort(__float2half_rn(v.z)) |
                  ((uint32_t)__half_as_ushort(__float2half_rn(v.w)) << 16);
    reinterpret_cast<uint2*>(hi)[i] = make_uint2(h0, h1);
}

// ---------------------------------------------------------------------------
// HMMA fp16 GEMM: C[M,N] = A @ B^T.
// PASSES=2: (Ahi+Alo)·Bhi (3 smem tiles). PASSES=3: + Ahi·Blo (4 tiles).
// CTA 128x128, BK=32, 8 warps (2x4), 2-stage cp.async pipeline (2 CTAs/SM).
// PAD_K=40 -> 80 B rows (16B-aligned, conflict-free ldmatrix).
// ---------------------------------------------------------------------------
#define BK        32
#define PAD_K     40
#define TILE_SMB  (128 * PAD_K * 2)      // 10240 B

template <int PASSES, bool HAS_BIAS, bool SPLIT_OUT>
__global__ __launch_bounds__(256) void gemm_mma(
    const uint16_t* __restrict__ Ahi, const uint16_t* __restrict__ Alo,
    const uint16_t* __restrict__ Bhi, const uint16_t* __restrict__ Blo,
    const float* __restrict__ bias, float* __restrict__ C,
    uint16_t* __restrict__ Chi, uint16_t* __restrict__ Clo,
    int M, int N, int K)
{
    constexpr int TC = (PASSES == 3) ? 4 : 3;
    constexpr int STAGE_B = TC * TILE_SMB;

    extern __shared__ char smem[];
    const uint32_t sb = smem_u32(smem);
    const int tid = threadIdx.x;
    const int wid = tid >> 5;
    const int lane = tid & 31;
    const int bm = blockIdx.y * 128;
    const int bn = blockIdx.x * 128;
    const int wm = wid >> 2;
    const int wn = wid & 3;
    const int nk = K / BK;

    const int r0 = tid >> 2, q0 = tid & 3;
    const int r1 = r0 + 64;

    const uint16_t* gA0 = Ahi + (size_t)bm * K;
    const uint16_t* gA1 = Alo + (size_t)bm * K;
    const uint16_t* gB0 = Bhi + (size_t)bn * K;
    const uint16_t* gB1 = (PASSES == 3) ? (Blo + (size_t)bn * K) : nullptr;

    auto load_stage = [&](int s, int k0) {
        uint32_t base = sb + s * STAGE_B;
        const uint32_t doff = (r0 * PAD_K + q0 * 8) * 2;
        const uint32_t doff1 = (r1 * PAD_K + q0 * 8) * 2;
        const size_t so0 = (size_t)r0 * K + k0 + q0 * 8;
        const size_t so1 = (size_t)r1 * K + k0 + q0 * 8;
        cp_async16(base + 0 * TILE_SMB + doff,  gA0 + so0);
        cp_async16(base + 0 * TILE_SMB + doff1, gA0 + so1);
        cp_async16(base + 1 * TILE_SMB + doff,  gA1 + so0);
        cp_async16(base + 1 * TILE_SMB + doff1, gA1 + so1);
        cp_async16(base + 2 * TILE_SMB + doff,  gB0 + so0);
        cp_async16(base + 2 * TILE_SMB + doff1, gB0 + so1);
        if (PASSES == 3) {
            cp_async16(base + 3 * TILE_SMB + doff,  gB1 + so0);
            cp_async16(base + 3 * TILE_SMB + doff1, gB1 + so1);
        }
        cp_commit();
    };

    float acc[4][4][4];
#pragma unroll
    for (int mt = 0; mt < 4; ++mt)
#pragma unroll
        for (int nt = 0; nt < 4; ++nt)
#pragma unroll
            for (int e = 0; e < 4; ++e) acc[mt][nt][e] = 0.f;

    const int lrow8 = lane & 7;
    const int lq    = lane >> 3;
    const int a_roff = lrow8 + (lq & 1) * 8;
    const int a_coff = (lq >> 1) * 8;
    const int b_noff = lrow8 + (lq >> 1) * 8;
    const int b_coff = (lq & 1) * 8;

    load_stage(0, 0);

    for (int i = 0; i < nk; ++i) {
        const int s = i & 1;
        if (i + 1 < nk) { load_stage(s ^ 1, (i + 1) * BK); cp_wait<1>(); }
        else            { cp_wait<0>(); }
        __syncthreads();

        const uint32_t stg = sb + s * STAGE_B;
#pragma unroll
        for (int kk = 0; kk < BK; kk += 16) {
            uint32_t bh[4][2], bl[4][2];
#pragma unroll
            for (int ntp = 0; ntp < 2; ++ntp) {
                int nidx = wn * 32 + ntp * 16 + b_noff;
                int cidx = kk + b_coff;
                ldsm_x4(bh[2 * ntp][0], bh[2 * ntp][1], bh[2 * ntp + 1][0], bh[2 * ntp + 1][1],
                        stg + 2 * TILE_SMB + (nidx * PAD_K + cidx) * 2);
                if (PASSES == 3)
                    ldsm_x4(bl[2 * ntp][0], bl[2 * ntp][1], bl[2 * ntp + 1][0], bl[2 * ntp + 1][1],
                            stg + 3 * TILE_SMB + (nidx * PAD_K + cidx) * 2);
            }
#pragma unroll
            for (int mt = 0; mt < 4; ++mt) {
                int midx = wm * 64 + mt * 16 + a_roff;
                int cidx = kk + a_coff;
                uint32_t ah[4], al[4];
                ldsm_x4(ah[0], ah[1], ah[2], ah[3], stg + 0 * TILE_SMB + (midx * PAD_K + cidx) * 2);
                ldsm_x4(al[0], al[1], al[2], al[3], stg + 1 * TILE_SMB + (midx * PAD_K + cidx) * 2);
#pragma unroll
                for (int nt = 0; nt < 4; ++nt) {
                    mma_f16(acc[mt][nt], ah, bh[nt]);
                    mma_f16(acc[mt][nt], al, bh[nt]);
                    if (PASSES == 3) mma_f16(acc[mt][nt], ah, bl[nt]);
                }
            }
        }
        __syncthreads();
    }

#pragma unroll
    for (int mt = 0; mt < 4; ++mt) {
#pragma unroll
        for (int nt = 0; nt < 4; ++nt) {
            int r = bm + wm * 64 + mt * 16 + (lane >> 2);
            int c = bn + wn * 32 + nt * 8 + (lane & 3) * 2;
            if (SPLIT_OUT) {
                uint32_t hi0, lo0, hi1, lo1;
                split_pair_h(acc[mt][nt][0], acc[mt][nt][1], hi0, lo0);
                split_pair_h(acc[mt][nt][2], acc[mt][nt][3], hi1, lo1);
                *reinterpret_cast<uint32_t*>(&Chi[(size_t)r * N + c]) = hi0;
                *reinterpret_cast<uint32_t*>(&Clo[(size_t)r * N + c]) = lo0;
                *reinterpret_cast<uint32_t*>(&Chi[(size_t)(r + 8) * N + c]) = hi1;
                *reinterpret_cast<uint32_t*>(&Clo[(size_t)(r + 8) * N + c]) = lo1;
            } else {
                float b0 = 0.f, b1 = 0.f;
                if (HAS_BIAS) { b0 = bias[c]; b1 = bias[c + 1]; }
                *reinterpret_cast<float2*>(&C[(size_t)r * N + c]) =
                    make_float2(acc[mt][nt][0] + b0, acc[mt][nt][1] + b1);
                *reinterpret_cast<float2*>(&C[(size_t)(r + 8) * N + c]) =
                    make_float2(acc[mt][nt][2] + b0, acc[mt][nt][3] + b1);
            }
        }
    }
}

// ---------------------------------------------------------------------------
// 2-pass fp16 causal flash attention (unchanged from R7 — passing).
// ---------------------------------------------------------------------------
#define ATT_PAD    72
#define ATT_ROWB   (ATT_PAD * 2)          // 144 B
#define KV_TILE_B  (64 * ATT_ROWB)        // 9216
#define ATT_STAGE  (2 * KV_TILE_B)        // 18432 (Khi, Vhi)
#define ATT_SMEM   (3 * ATT_STAGE)        // 55296

__global__ __launch_bounds__(256) void flash_attn_mma(
    const uint16_t* __restrict__ qkv_hi, const uint16_t* __restrict__ qkv_lo,
    uint16_t* __restrict__ ao_hi, uint16_t* __restrict__ ao_lo)
{
    extern __shared__ char smem[];
    const uint32_t sb = smem_u32(smem);
    const int tid = threadIdx.x, wid = tid >> 5, lane = tid & 31;
    const int qb = 15 - blockIdx.x;
    const int bh = blockIdx.y;
    const int b = bh >> 4, h = bh & 15;
    const size_t tok0 = (size_t)b * S_LEN;

    const int lrow8 = lane & 7, lq = lane >> 3;
    const int a_roff = lrow8 + (lq & 1) * 8;
    const int a_coff = (lq >> 1) * 8;
    const int b_noff = lrow8 + (lq >> 1) * 8;
    const int b_coff = (lq & 1) * 8;
    const int v_roff = (lane & 7) + ((lane >> 3) & 1) * 8;
    const int v_coff = (lane >> 4) * 8;

    // ---- stage Q (hi/lo) into smem; pull frags to regs
    {
        const size_t qrow0 = tok0 + (size_t)qb * 128;
#pragma unroll
        for (int arr = 0; arr < 2; ++arr) {
            const uint16_t* src = arr ? qkv_lo : qkv_hi;
            uint32_t dstb = sb + (uint32_t)arr * (128 * ATT_ROWB);
#pragma unroll
            for (int it = 0; it < 4; ++it) {
                int c = tid + it * 256;
                int r = c >> 3, col = (c & 7) * 8;
                cp_async16(dstb + r * ATT_ROWB + col * 2,
                           src + (qrow0 + r) * QKV_LD + h * 192 + col);
            }
        }
        cp_commit();
        cp_wait<0>();
        __syncthreads();
    }
    uint32_t qh[4][4], ql[4][4];
#pragma unroll
    for (int j = 0; j < 4; ++j) {
        int rr = wid * 16 + a_roff;
        int cc = j * 16 + a_coff;
        ldsm_x4(qh[j][0], qh[j][1], qh[j][2], qh[j][3], sb + rr * ATT_ROWB + cc * 2);
        ldsm_x4(ql[j][0], ql[j][1], ql[j][2], ql[j][3],
                sb + 128 * ATT_ROWB + rr * ATT_ROWB + cc * 2);
    }
    __syncthreads();

    // KV stage: Khi tile + Vhi tile
    auto load_kv = [&](int s, int kb) {
        uint32_t base = sb + s * ATT_STAGE;
        const size_t krow0 = tok0 + (size_t)kb * 64;
        const int koff = h * 192 + 64, voff = h * 192 + 128;
#pragma unroll
        for (int it = 0; it < 2; ++it) {
            int c = tid + it * 256;
            int r = c >> 3, col = (c & 7) * 8;
            const size_t go = (krow0 + r) * QKV_LD + col;
            cp_async16(base + r * ATT_ROWB + col * 2, qkv_hi + go + koff);
            cp_async16(base + KV_TILE_B + r * ATT_ROWB + col * 2, qkv_hi + go + voff);
        }
        cp_commit();
    };

    float o[8][4];
#pragma unroll
    for (int nt = 0; nt < 8; ++nt)
#pragma unroll
        for (int e = 0; e < 4; ++e) o[nt][e] = 0.f;
    float m0 = -1e30f, m1 = -1e30f, l0 = 0.f, l1 = 0.f;

    const int nkb = 2 * qb + 2;
    load_kv(0, 0);
    if (nkb > 1) load_kv(1, 1);

    for (int kb = 0; kb < nkb; ++kb) {
        const int s = kb % 3;
        if (kb + 2 < nkb) { load_kv((kb + 2) % 3, kb + 2); cp_wait<2>(); }
        else if (kb + 1 < nkb) { cp_wait<1>(); }
        else { cp_wait<0>(); }
        __syncthreads();
        const uint32_t kbase = sb + s * ATT_STAGE;

        // ---- S = Q @ Khi^T (2-pass)
        float sc[8][4];
#pragma unroll
        for (int nt = 0; nt < 8; ++nt)
#pragma unroll
            for (int e = 0; e < 4; ++e) sc[nt][e] = 0.f;

#pragma unroll
        for (int j = 0; j < 4; ++j) {
            uint32_t kf[8][2];
#pragma unroll
            for (int p = 0; p < 4; ++p) {
                int nn = p * 16 + b_noff;
                int cc = j * 16 + b_coff;
                ldsm_x4(kf[2 * p][0], kf[2 * p][1], kf[2 * p + 1][0], kf[2 * p + 1][1],
                        kbase + nn * ATT_ROWB + cc * 2);
            }
#pragma unroll
            for (int nt = 0; nt < 8; ++nt) {
                mma_f16(sc[nt], qh[j], kf[nt]);
                mma_f16(sc[nt], ql[j], kf[nt]);
            }
        }

#pragma unroll
        for (int nt = 0; nt < 8; ++nt)
#pragma unroll
            for (int e = 0; e < 4; ++e) sc[nt][e] *= 0.125f;

        if (kb >= 2 * qb) {
            const int gr0 = qb * 128 + wid * 16 + (lane >> 2);
#pragma unroll
            for (int nt = 0; nt < 8; ++nt) {
                int gc = kb * 64 + nt * 8 + (lane & 3) * 2;
                if (gc     > gr0)     sc[nt][0] = -1e30f;
                if (gc + 1 > gr0)     sc[nt][1] = -1e30f;
                if (gc     > gr0 + 8) sc[nt][2] = -1e30f;
                if (gc + 1 > gr0 + 8) sc[nt][3] = -1e30f;
            }
        }

        // ---- online softmax
        float mx0 = -1e30f, mx1 = -1e30f;
#pragma unroll
        for (int nt = 0; nt < 8; ++nt) {
            mx0 = fmaxf(mx0, fmaxf(sc[nt][0], sc[nt][1]));
            mx1 = fmaxf(mx1, fmaxf(sc[nt][2], sc[nt][3]));
        }
#pragma unroll
        for (int w = 1; w < 4; w <<= 1) {
            mx0 = fmaxf(mx0, __shfl_xor_sync(0xffffffffu, mx0, w));
            mx1 = fmaxf(mx1, __shfl_xor_sync(0xffffffffu, mx1, w));
        }
        float mn0 = fmaxf(m0, mx0), mn1 = fmaxf(m1, mx1);
        float c0 = __expf(m0 - mn0), c1 = __expf(m1 - mn1);
        m0 = mn0; m1 = mn1;
        float rs0 = 0.f, rs1 = 0.f;
#pragma unroll
        for (int nt = 0; nt < 8; ++nt) {
            sc[nt][0] = __expf(sc[nt][0] - mn0);
            sc[nt][1] = __expf(sc[nt][1] - mn0);
            sc[nt][2] = __expf(sc[nt][2] - mn1);
            sc[nt][3] = __expf(sc[nt][3] - mn1);
            rs0 += sc[nt][0] + sc[nt][1];
            rs1 += sc[nt][2] + sc[nt][3];
        }
#pragma unroll
        for (int w = 1; w < 4; w <<= 1) {
            rs0 += __shfl_xor_sync(0xffffffffu, rs0, w);
            rs1 += __shfl_xor_sync(0xffffffffu, rs1, w);
        }
        l0 = l0 * c0 + rs0;
        l1 = l1 * c1 + rs1;
#pragma unroll
        for (int nt = 0; nt < 8; ++nt) {
            o[nt][0] *= c0; o[nt][1] *= c0;
            o[nt][2] *= c1; o[nt][3] *= c1;
        }

        // ---- O += P @ Vhi (2-pass; P split fp16 in regs)
#pragma unroll
        for (int j = 0; j < 4; ++j) {
            uint32_t ph[4], pl[4];
            split_pair_h(sc[2 * j][0],     sc[2 * j][1],     ph[0], pl[0]);
            split_pair_h(sc[2 * j][2],     sc[2 * j][3],     ph[1], pl[1]);
            split_pair_h(sc[2 * j + 1][0], sc[2 * j + 1][1], ph[2], pl[2]);
            split_pair_h(sc[2 * j + 1][2], sc[2 * j + 1][3], ph[3], pl[3]);

            uint32_t vf[8][2];
#pragma unroll
            for (int p = 0; p < 4; ++p) {
                uint32_t ar = (j * 16 + v_roff) * ATT_ROWB + (p * 16 + v_coff) * 2;
                ldsm_x4_t(vf[2 * p][0], vf[2 * p][1], vf[2 * p + 1][0], vf[2 * p + 1][1],
                          kbase + KV_TILE_B + ar);
            }
#pragma unroll
            for (int nt = 0; nt < 8; ++nt) {
                mma_f16(o[nt], ph, vf[nt]);
                mma_f16(o[nt], pl, vf[nt]);
            }
        }
        __syncthreads();
    }

    // ---- normalize + write ao as fp16 hi/lo
    const float inv0 = 1.f / l0, inv1 = 1.f / l1;
    const int gr0 = qb * 128 + wid * 16 + (lane >> 2);
    const size_t row0 = (tok0 + gr0) * D_MODEL;
    const size_t row1 = (tok0 + gr0 + 8) * D_MODEL;
    const int colb = h * DH + (lane & 3) * 2;
#pragma unroll
    for (int nt = 0; nt < 8; ++nt) {
        int c = colb + nt * 8;
        uint32_t hi0, lo0, hi1, lo1;
        split_pair_h(o[nt][0] * inv0, o[nt][1] * inv0, hi0, lo0);
        split_pair_h(o[nt][2] * inv1, o[nt][3] * inv1, hi1, lo1);
        *reinterpret_cast<uint32_t*>(&ao_hi[row0 + c]) = hi0;
        *reinterpret_cast<uint32_t*>(&ao_lo[row0 + c]) = lo0;
        *reinterpret_cast<uint32_t*>(&ao_hi[row1 + c]) = hi1;
        *reinterpret_cast<uint32_t*>(&ao_lo[row1 + c]) = lo1;
    }
}

// ---------------------------------------------------------------------------
extern "C" void kernel_launch(void* const* d_in, const int* in_sizes, int n_in,
                              void* d_out, int out_size)
{
    (void)in_sizes; (void)n_in; (void)out_size;
    const float* x     = (const float*)d_in[0];
    const float* w_qkv = (const float*)d_in[1];
    const float* w_out = (const float*)d_in[2];
    const float* b_out = (const float*)d_in[3];
    float* out = (float*)d_out;

    uint16_t *xhi, *xlo, *wq, *qh, *qlo, *aohi, *aolo, *wohi, *wolo;
    cudaGetSymbolAddress((void**)&xhi, g_x_hi);
    cudaGetSymbolAddress((void**)&xlo, g_x_lo);
    cudaGetSymbolAddress((void**)&wq,  g_wqkv_h);
    cudaGetSymbolAddress((void**)&qh,  g_qkv_hi);
    cudaGetSymbolAddress((void**)&qlo, g_qkv_lo);
    cudaGetSymbolAddress((void**)&aohi, g_ao_hi);
    cudaGetSymbolAddress((void**)&aolo, g_ao_lo);
    cudaGetSymbolAddress((void**)&wohi, g_wout_hi);
    cudaGetSymbolAddress((void**)&wolo, g_wout_lo);

    constexpr int G1_SMEM = 2 * 3 * TILE_SMB;   // 61440  (2-pass)
    constexpr int G2_SMEM = 2 * 4 * TILE_SMB;   // 81920  (3-pass)
    cudaFuncSetAttribute((gemm_mma<2, false, true>),
                         cudaFuncAttributeMaxDynamicSharedMemorySize, G1_SMEM);
    cudaFuncSetAttribute((gemm_mma<3, true, false>),
                         cudaFuncAttributeMaxDynamicSharedMemorySize, G2_SMEM);
    cudaFuncSetAttribute(flash_attn_mma,
                         cudaFuncAttributeMaxDynamicSharedMemorySize, ATT_SMEM);

    // 1) pack inputs: x -> fp16 hi/lo; w_qkv -> fp16 single; w_out -> fp16 hi/lo
    {
        int n4 = M_TOK * D_MODEL / 4;
        pack_split_h<<<(n4 + 255) / 256, 256>>>(x, xhi, xlo, n4);
        n4 = QKV_LD * D_MODEL / 4;
        pack_h16<<<(n4 + 255) / 256, 256>>>(w_qkv, wq, n4);
        n4 = D_MODEL * D_MODEL / 4;
        pack_split_h<<<(n4 + 255) / 256, 256>>>(w_out, wohi, wolo, n4);
    }

    // 2) QKV projection (2-pass fp16) -> qkv fp16 hi/lo
    gemm_mma<2, false, true><<<dim3(QKV_LD / 128, M_TOK / 128), 256, G1_SMEM>>>(
        xhi, xlo, wq, nullptr, nullptr, nullptr, qh, qlo, M_TOK, QKV_LD, D_MODEL);

    // 3) causal flash attention (2-pass fp16) -> ao fp16 hi/lo
    flash_attn_mma<<<dim3(S_LEN / 128, 2 * H_NUM), 256, ATT_SMEM>>>(qh, qlo, aohi, aolo);

    // 4) output projection (3-pass fp16) + bias -> fp32 out
    gemm_mma<3, true, false><<<dim3(D_MODEL / 128, M_TOK / 128), 256, G2_SMEM>>>(
        aohi, aolo, wohi, wolo, b_out, out, nullptr, nullptr, M_TOK, D_MODEL, D_MODEL);
}

// round 11
// speedup vs baseline: 3.6098x; 1.1325x over previous
#include <cuda_runtime.h>
#include <cuda_fp16.h>
#include <cstdint>
#include <cstddef>

#define S_LEN   2048
#define D_MODEL 1024
#define H_NUM   16
#define DH      64
#define M_TOK   4096
#define QKV_LD  3072

// ---------------------------------------------------------------------------
// Device scratch (fp16 words)
// ---------------------------------------------------------------------------
__device__ uint16_t g_x_hi  [(size_t)M_TOK * D_MODEL];
__device__ uint16_t g_x_lo  [(size_t)M_TOK * D_MODEL];
__device__ uint16_t g_wqkv_h[(size_t)QKV_LD * D_MODEL];   // single fp16
__device__ uint16_t g_qkv_h [(size_t)M_TOK * QKV_LD];     // single fp16
__device__ uint16_t g_ao_hi [(size_t)M_TOK * D_MODEL];
__device__ uint16_t g_ao_lo [(size_t)M_TOK * D_MODEL];
__device__ uint16_t g_wout_h[(size_t)D_MODEL * D_MODEL];  // single fp16

// ---------------------------------------------------------------------------
// PTX helpers
// ---------------------------------------------------------------------------
__device__ __forceinline__ uint32_t smem_u32(const void* p) {
    uint32_t a;
    asm("{ .reg .u64 t; cvta.to.shared.u64 t, %1; cvt.u32.u64 %0, t; }" : "=r"(a) : "l"(p));
    return a;
}
__device__ __forceinline__ void cp_async16(uint32_t dst, const void* src) {
    asm volatile("cp.async.cg.shared.global [%0], [%1], 16;" :: "r"(dst), "l"(src));
}
__device__ __forceinline__ void cp_commit() {
    asm volatile("cp.async.commit_group;" ::: "memory");
}
template <int N>
__device__ __forceinline__ void cp_wait() {
    asm volatile("cp.async.wait_group %0;" :: "n"(N) : "memory");
}
__device__ __forceinline__ void ldsm_x4(uint32_t& r0, uint32_t& r1, uint32_t& r2,
                                        uint32_t& r3, uint32_t a) {
    asm volatile("ldmatrix.sync.aligned.m8n8.x4.shared.b16 {%0,%1,%2,%3}, [%4];"
                 : "=r"(r0), "=r"(r1), "=r"(r2), "=r"(r3) : "r"(a));
}
__device__ __forceinline__ void ldsm_x4_t(uint32_t& r0, uint32_t& r1, uint32_t& r2,
                                          uint32_t& r3, uint32_t a) {
    asm volatile("ldmatrix.sync.aligned.m8n8.x4.trans.shared.b16 {%0,%1,%2,%3}, [%4];"
                 : "=r"(r0), "=r"(r1), "=r"(r2), "=r"(r3) : "r"(a));
}
__device__ __forceinline__ void mma_f16(float* d, const uint32_t* a, const uint32_t* b) {
    asm volatile("mma.sync.aligned.m16n8k16.row.col.f32.f16.f16.f32 "
                 "{%0,%1,%2,%3}, {%4,%5,%6,%7}, {%8,%9}, {%0,%1,%2,%3};"
                 : "+f"(d[0]), "+f"(d[1]), "+f"(d[2]), "+f"(d[3])
                 : "r"(a[0]), "r"(a[1]), "r"(a[2]), "r"(a[3]), "r"(b[0]), "r"(b[1]));
}
// fp32 pair -> fp16 hi/lo words
__device__ __forceinline__ void split_pair_h(float a, float b, uint32_t& hi, uint32_t& lo) {
    __half ha = __float2half_rn(a), hb = __float2half_rn(b);
    hi = (uint32_t)__half_as_ushort(ha) | ((uint32_t)__half_as_ushort(hb) << 16);
    lo = (uint32_t)__half_as_ushort(__float2half_rn(a - __half2float(ha))) |
         ((uint32_t)__half_as_ushort(__float2half_rn(b - __half2float(hb))) << 16);
}
__device__ __forceinline__ uint32_t pack_pair_h(float a, float b) {
    return (uint32_t)__half_as_ushort(__float2half_rn(a)) |
           ((uint32_t)__half_as_ushort(__float2half_rn(b)) << 16);
}

// ---------------------------------------------------------------------------
// Packers
// ---------------------------------------------------------------------------
__global__ __launch_bounds__(256) void pack_split_h(
    const float* __restrict__ in, uint16_t* __restrict__ hi,
    uint16_t* __restrict__ lo, int n4)
{
    int i = blockIdx.x * 256 + threadIdx.x;
    if (i >= n4) return;
    float4 v = reinterpret_cast<const float4*>(in)[i];
    uint32_t h0, l0, h1, l1;
    split_pair_h(v.x, v.y, h0, l0);
    split_pair_h(v.z, v.w, h1, l1);
    reinterpret_cast<uint2*>(hi)[i] = make_uint2(h0, h1);
    reinterpret_cast<uint2*>(lo)[i] = make_uint2(l0, l1);
}
__global__ __launch_bounds__(256) void pack_h16(
    const float* __restrict__ in, uint16_t* __restrict__ hi, int n4)
{
    int i = blockIdx.x * 256 + threadIdx.x;
    if (i >= n4) return;
    float4 v = reinterpret_cast<const float4*>(in)[i];
    reinterpret_cast<uint2*>(hi)[i] =
        make_uint2(pack_pair_h(v.x, v.y), pack_pair_h(v.z, v.w));
}

// ---------------------------------------------------------------------------
// HMMA fp16 GEMM: C[M,N] = (Ahi+Alo) @ Bhi^T (+bias). 2-pass, 3 smem tiles.
// CTA 128x128, BK=32, 8 warps (2x4), 3-stage cp.async pipeline.
// Stage = 30720 B, 3 stages = 92160 B -> 2 CTAs/SM (227 KB limit).
// PAD_K=40 -> 80 B rows (16B-aligned, conflict-free ldmatrix).
// SPLIT_OUT: write single fp16 (hi only) to Chi.
// ---------------------------------------------------------------------------
#define BK        32
#define PAD_K     40
#define TILE_SMB  (128 * PAD_K * 2)      // 10240 B
#define STAGE_B   (3 * TILE_SMB)         // 30720 B
#define G_SMEM    (3 * STAGE_B)          // 92160 B

template <bool HAS_BIAS, bool SPLIT_OUT>
__global__ __launch_bounds__(256) void gemm_mma(
    const uint16_t* __restrict__ Ahi, const uint16_t* __restrict__ Alo,
    const uint16_t* __restrict__ Bhi,
    const float* __restrict__ bias, float* __restrict__ C,
    uint16_t* __restrict__ Chi,
    int M, int N, int K)
{
    extern __shared__ char smem[];
    const uint32_t sb = smem_u32(smem);
    const int tid = threadIdx.x;
    const int wid = tid >> 5;
    const int lane = tid & 31;
    const int bm = blockIdx.y * 128;
    const int bn = blockIdx.x * 128;
    const int wm = wid >> 2;
    const int wn = wid & 3;
    const int nk = K / BK;

    const int r0 = tid >> 2, q0 = tid & 3;
    const int r1 = r0 + 64;

    const uint16_t* gA0 = Ahi + (size_t)bm * K;
    const uint16_t* gA1 = Alo + (size_t)bm * K;
    const uint16_t* gB0 = Bhi + (size_t)bn * K;

    auto load_stage = [&](int s, int k0) {
        uint32_t base = sb + s * STAGE_B;
        const uint32_t doff = (r0 * PAD_K + q0 * 8) * 2;
        const uint32_t doff1 = (r1 * PAD_K + q0 * 8) * 2;
        const size_t so0 = (size_t)r0 * K + k0 + q0 * 8;
        const size_t so1 = (size_t)r1 * K + k0 + q0 * 8;
        cp_async16(base + 0 * TILE_SMB + doff,  gA0 + so0);
        cp_async16(base + 0 * TILE_SMB + doff1, gA0 + so1);
        cp_async16(base + 1 * TILE_SMB + doff,  gA1 + so0);
        cp_async16(base + 1 * TILE_SMB + doff1, gA1 + so1);
        cp_async16(base + 2 * TILE_SMB + doff,  gB0 + so0);
        cp_async16(base + 2 * TILE_SMB + doff1, gB0 + so1);
        cp_commit();
    };

    float acc[4][4][4];
#pragma unroll
    for (int mt = 0; mt < 4; ++mt)
#pragma unroll
        for (int nt = 0; nt < 4; ++nt)
#pragma unroll
            for (int e = 0; e < 4; ++e) acc[mt][nt][e] = 0.f;

    const int lrow8 = lane & 7;
    const int lq    = lane >> 3;
    const int a_roff = lrow8 + (lq & 1) * 8;
    const int a_coff = (lq >> 1) * 8;
    const int b_noff = lrow8 + (lq >> 1) * 8;
    const int b_coff = (lq & 1) * 8;

    load_stage(0, 0);
    if (nk > 1) load_stage(1, BK);

    for (int i = 0; i < nk; ++i) {
        const int s = i % 3;
        if (i + 2 < nk) { load_stage((i + 2) % 3, (i + 2) * BK); cp_wait<2>(); }
        else if (i + 1 < nk) { cp_wait<1>(); }
        else { cp_wait<0>(); }
        __syncthreads();

        const uint32_t stg = sb + s * STAGE_B;
#pragma unroll
        for (int kk = 0; kk < BK; kk += 16) {
            uint32_t bh[4][2];
#pragma unroll
            for (int ntp = 0; ntp < 2; ++ntp) {
                int nidx = wn * 32 + ntp * 16 + b_noff;
                int cidx = kk + b_coff;
                ldsm_x4(bh[2 * ntp][0], bh[2 * ntp][1], bh[2 * ntp + 1][0], bh[2 * ntp + 1][1],
                        stg + 2 * TILE_SMB + (nidx * PAD_K + cidx) * 2);
            }
#pragma unroll
            for (int mt = 0; mt < 4; ++mt) {
                int midx = wm * 64 + mt * 16 + a_roff;
                int cidx = kk + a_coff;
                uint32_t ah[4], al[4];
                ldsm_x4(ah[0], ah[1], ah[2], ah[3], stg + 0 * TILE_SMB + (midx * PAD_K + cidx) * 2);
                ldsm_x4(al[0], al[1], al[2], al[3], stg + 1 * TILE_SMB + (midx * PAD_K + cidx) * 2);
#pragma unroll
                for (int nt = 0; nt < 4; ++nt) {
                    mma_f16(acc[mt][nt], ah, bh[nt]);
                    mma_f16(acc[mt][nt], al, bh[nt]);
                }
            }
        }
        __syncthreads();
    }

#pragma unroll
    for (int mt = 0; mt < 4; ++mt) {
#pragma unroll
        for (int nt = 0; nt < 4; ++nt) {
            int r = bm + wm * 64 + mt * 16 + (lane >> 2);
            int c = bn + wn * 32 + nt * 8 + (lane & 3) * 2;
            if (SPLIT_OUT) {
                *reinterpret_cast<uint32_t*>(&Chi[(size_t)r * N + c]) =
                    pack_pair_h(acc[mt][nt][0], acc[mt][nt][1]);
                *reinterpret_cast<uint32_t*>(&Chi[(size_t)(r + 8) * N + c]) =
                    pack_pair_h(acc[mt][nt][2], acc[mt][nt][3]);
            } else {
                float b0 = 0.f, b1 = 0.f;
                if (HAS_BIAS) { b0 = bias[c]; b1 = bias[c + 1]; }
                *reinterpret_cast<float2*>(&C[(size_t)r * N + c]) =
                    make_float2(acc[mt][nt][0] + b0, acc[mt][nt][1] + b1);
                *reinterpret_cast<float2*>(&C[(size_t)(r + 8) * N + c]) =
                    make_float2(acc[mt][nt][2] + b0, acc[mt][nt][3] + b1);
            }
        }
    }
}

// ---------------------------------------------------------------------------
// fp16 causal flash attention.
// S = Qhi·Khi (single pass); O += (Phi+Plo)·Vhi (P split in regs, exact).
// CTA: 128 q-rows x (b,h). 8 warps. Bc=64. 3-stage KV pipeline.
// ---------------------------------------------------------------------------
#define ATT_PAD    72
#define ATT_ROWB   (ATT_PAD * 2)          // 144 B
#define KV_TILE_B  (64 * ATT_ROWB)        // 9216
#define ATT_STAGE  (2 * KV_TILE_B)        // 18432 (Khi, Vhi)
#define ATT_SMEM   (3 * ATT_STAGE)        // 55296

__global__ __launch_bounds__(256) void flash_attn_mma(
    const uint16_t* __restrict__ qkv_h,
    uint16_t* __restrict__ ao_hi, uint16_t* __restrict__ ao_lo)
{
    extern __shared__ char smem[];
    const uint32_t sb = smem_u32(smem);
    const int tid = threadIdx.x, wid = tid >> 5, lane = tid & 31;
    const int qb = 15 - blockIdx.x;
    const int bh = blockIdx.y;
    const int b = bh >> 4, h = bh & 15;
    const size_t tok0 = (size_t)b * S_LEN;

    const int lrow8 = lane & 7, lq = lane >> 3;
    const int a_roff = lrow8 + (lq & 1) * 8;
    const int a_coff = (lq >> 1) * 8;
    const int b_noff = lrow8 + (lq >> 1) * 8;
    const int b_coff = (lq & 1) * 8;
    const int v_roff = (lane & 7) + ((lane >> 3) & 1) * 8;
    const int v_coff = (lane >> 4) * 8;

    // ---- stage Q (hi only) into smem; pull frags to regs
    {
        const size_t qrow0 = tok0 + (size_t)qb * 128;
#pragma unroll
        for (int it = 0; it < 4; ++it) {
            int c = tid + it * 256;
            int r = c >> 3, col = (c & 7) * 8;
            cp_async16(sb + r * ATT_ROWB + col * 2,
                       qkv_h + (qrow0 + r) * QKV_LD + h * 192 + col);
        }
        cp_commit();
        cp_wait<0>();
        __syncthreads();
    }
    uint32_t qh[4][4];
#pragma unroll
    for (int j = 0; j < 4; ++j) {
        int rr = wid * 16 + a_roff;
        int cc = j * 16 + a_coff;
        ldsm_x4(qh[j][0], qh[j][1], qh[j][2], qh[j][3], sb + rr * ATT_ROWB + cc * 2);
    }
    __syncthreads();

    // KV stage: Khi tile + Vhi tile
    auto load_kv = [&](int s, int kb) {
        uint32_t base = sb + s * ATT_STAGE;
        const size_t krow0 = tok0 + (size_t)kb * 64;
        const int koff = h * 192 + 64, voff = h * 192 + 128;
#pragma unroll
        for (int it = 0; it < 2; ++it) {
            int c = tid + it * 256;
            int r = c >> 3, col = (c & 7) * 8;
            const size_t go = (krow0 + r) * QKV_LD + col;
            cp_async16(base + r * ATT_ROWB + col * 2, qkv_h + go + koff);
            cp_async16(base + KV_TILE_B + r * ATT_ROWB + col * 2, qkv_h + go + voff);
        }
        cp_commit();
    };

    float o[8][4];
#pragma unroll
    for (int nt = 0; nt < 8; ++nt)
#pragma unroll
        for (int e = 0; e < 4; ++e) o[nt][e] = 0.f;
    float m0 = -1e30f, m1 = -1e30f, l0 = 0.f, l1 = 0.f;

    const int nkb = 2 * qb + 2;
    load_kv(0, 0);
    if (nkb > 1) load_kv(1, 1);

    for (int kb = 0; kb < nkb; ++kb) {
        const int s = kb % 3;
        if (kb + 2 < nkb) { load_kv((kb + 2) % 3, kb + 2); cp_wait<2>(); }
        else if (kb + 1 < nkb) { cp_wait<1>(); }
        else { cp_wait<0>(); }
        __syncthreads();
        const uint32_t kbase = sb + s * ATT_STAGE;

        // ---- S = Qhi @ Khi^T (single pass)
        float sc[8][4];
#pragma unroll
        for (int nt = 0; nt < 8; ++nt)
#pragma unroll
            for (int e = 0; e < 4; ++e) sc[nt][e] = 0.f;

#pragma unroll
        for (int j = 0; j < 4; ++j) {
            uint32_t kf[8][2];
#pragma unroll
            for (int p = 0; p < 4; ++p) {
                int nn = p * 16 + b_noff;
                int cc = j * 16 + b_coff;
                ldsm_x4(kf[2 * p][0], kf[2 * p][1], kf[2 * p + 1][0], kf[2 * p + 1][1],
                        kbase + nn * ATT_ROWB + cc * 2);
            }
#pragma unroll
            for (int nt = 0; nt < 8; ++nt)
                mma_f16(sc[nt], qh[j], kf[nt]);
        }

#pragma unroll
        for (int nt = 0; nt < 8; ++nt)
#pragma unroll
            for (int e = 0; e < 4; ++e) sc[nt][e] *= 0.125f;

        if (kb >= 2 * qb) {
            const int gr0 = qb * 128 + wid * 16 + (lane >> 2);
#pragma unroll
            for (int nt = 0; nt < 8; ++nt) {
                int gc = kb * 64 + nt * 8 + (lane & 3) * 2;
                if (gc     > gr0)     sc[nt][0] = -1e30f;
                if (gc + 1 > gr0)     sc[nt][1] = -1e30f;
                if (gc     > gr0 + 8) sc[nt][2] = -1e30f;
                if (gc + 1 > gr0 + 8) sc[nt][3] = -1e30f;
            }
        }

        // ---- online softmax
        float mx0 = -1e30f, mx1 = -1e30f;
#pragma unroll
        for (int nt = 0; nt < 8; ++nt) {
            mx0 = fmaxf(mx0, fmaxf(sc[nt][0], sc[nt][1]));
            mx1 = fmaxf(mx1, fmaxf(sc[nt][2], sc[nt][3]));
        }
#pragma unroll
        for (int w = 1; w < 4; w <<= 1) {
            mx0 = fmaxf(mx0, __shfl_xor_sync(0xffffffffu, mx0, w));
            mx1 = fmaxf(mx1, __shfl_xor_sync(0xffffffffu, mx1, w));
        }
        float mn0 = fmaxf(m0, mx0), mn1 = fmaxf(m1, mx1);
        float c0 = __expf(m0 - mn0), c1 = __expf(m1 - mn1);
        m0 = mn0; m1 = mn1;
        float rs0 = 0.f, rs1 = 0.f;
#pragma unroll
        for (int nt = 0; nt < 8; ++nt) {
            sc[nt][0] = __expf(sc[nt][0] - mn0);
            sc[nt][1] = __expf(sc[nt][1] - mn0);
            sc[nt][2] = __expf(sc[nt][2] - mn1);
            sc[nt][3] = __expf(sc[nt][3] - mn1);
            rs0 += sc[nt][0] + sc[nt][1];
            rs1 += sc[nt][2] + sc[nt][3];
        }
#pragma unroll
        for (int w = 1; w < 4; w <<= 1) {
            rs0 += __shfl_xor_sync(0xffffffffu, rs0, w);
            rs1 += __shfl_xor_sync(0xffffffffu, rs1, w);
        }
        l0 = l0 * c0 + rs0;
        l1 = l1 * c1 + rs1;
#pragma unroll
        for (int nt = 0; nt < 8; ++nt) {
            o[nt][0] *= c0; o[nt][1] *= c0;
            o[nt][2] *= c1; o[nt][3] *= c1;
        }

        // ---- O += (Phi+Plo) @ Vhi (P split fp16 in regs)
#pragma unroll
        for (int j = 0; j < 4; ++j) {
            uint32_t ph[4], pl[4];
            split_pair_h(sc[2 * j][0],     sc[2 * j][1],     ph[0], pl[0]);
            split_pair_h(sc[2 * j][2],     sc[2 * j][3],     ph[1], pl[1]);
            split_pair_h(sc[2 * j + 1][0], sc[2 * j + 1][1], ph[2], pl[2]);
            split_pair_h(sc[2 * j + 1][2], sc[2 * j + 1][3], ph[3], pl[3]);

            uint32_t vf[8][2];
#pragma unroll
            for (int p = 0; p < 4; ++p) {
                uint32_t ar = (j * 16 + v_roff) * ATT_ROWB + (p * 16 + v_coff) * 2;
                ldsm_x4_t(vf[2 * p][0], vf[2 * p][1], vf[2 * p + 1][0], vf[2 * p + 1][1],
                          kbase + KV_TILE_B + ar);
            }
#pragma unroll
            for (int nt = 0; nt < 8; ++nt) {
                mma_f16(o[nt], ph, vf[nt]);
                mma_f16(o[nt], pl, vf[nt]);
            }
        }
        __syncthreads();
    }

    // ---- normalize + write ao as fp16 hi/lo
    const float inv0 = 1.f / l0, inv1 = 1.f / l1;
    const int gr0 = qb * 128 + wid * 16 + (lane >> 2);
    const size_t row0 = (tok0 + gr0) * D_MODEL;
    const size_t row1 = (tok0 + gr0 + 8) * D_MODEL;
    const int colb = h * DH + (lane & 3) * 2;
#pragma unroll
    for (int nt = 0; nt < 8; ++nt) {
        int c = colb + nt * 8;
        uint32_t hi0, lo0, hi1, lo1;
        split_pair_h(o[nt][0] * inv0, o[nt][1] * inv0, hi0, lo0);
        split_pair_h(o[nt][2] * inv1, o[nt][3] * inv1, hi1, lo1);
        *reinterpret_cast<uint32_t*>(&ao_hi[row0 + c]) = hi0;
        *reinterpret_cast<uint32_t*>(&ao_lo[row0 + c]) = lo0;
        *reinterpret_cast<uint32_t*>(&ao_hi[row1 + c]) = hi1;
        *reinterpret_cast<uint32_t*>(&ao_lo[row1 + c]) = lo1;
    }
}

// ---------------------------------------------------------------------------
extern "C" void kernel_launch(void* const* d_in, const int* in_sizes, int n_in,
                              void* d_out, int out_size)
{
    (void)in_sizes; (void)n_in; (void)out_size;
    const float* x     = (const float*)d_in[0];
    const float* w_qkv = (const float*)d_in[1];
    const float* w_out = (const float*)d_in[2];
    const float* b_out = (const float*)d_in[3];
    float* out = (float*)d_out;

    uint16_t *xhi, *xlo, *wq, *qkvh, *aohi, *aolo, *woh;
    cudaGetSymbolAddress((void**)&xhi, g_x_hi);
    cudaGetSymbolAddress((void**)&xlo, g_x_lo);
    cudaGetSymbolAddress((void**)&wq,  g_wqkv_h);
    cudaGetSymbolAddress((void**)&qkvh, g_qkv_h);
    cudaGetSymbolAddress((void**)&aohi, g_ao_hi);
    cudaGetSymbolAddress((void**)&aolo, g_ao_lo);
    cudaGetSymbolAddress((void**)&woh, g_wout_h);

    cudaFuncSetAttribute((gemm_mma<false, true>),
                         cudaFuncAttributeMaxDynamicSharedMemorySize, G_SMEM);
    cudaFuncSetAttribute((gemm_mma<true, false>),
                         cudaFuncAttributeMaxDynamicSharedMemorySize, G_SMEM);
    cudaFuncSetAttribute(flash_attn_mma,
                         cudaFuncAttributeMaxDynamicSharedMemorySize, ATT_SMEM);

    // 1) pack inputs: x -> fp16 hi/lo; w_qkv, w_out -> fp16 single
    {
        int n4 = M_TOK * D_MODEL / 4;
        pack_split_h<<<(n4 + 255) / 256, 256>>>(x, xhi, xlo, n4);
        n4 = QKV_LD * D_MODEL / 4;
        pack_h16<<<(n4 + 255) / 256, 256>>>(w_qkv, wq, n4);
        n4 = D_MODEL * D_MODEL / 4;
        pack_h16<<<(n4 + 255) / 256, 256>>>(w_out, woh, n4);
    }

    // 2) QKV projection (2-pass fp16) -> qkv fp16 (hi only)
    //    gemm_mma(Ahi, Alo, Bhi, bias, C, Chi, M, N, K)
    gemm_mma<false, true><<<dim3(QKV_LD / 128, M_TOK / 128), 256, G_SMEM>>>(
        xhi, xlo, wq, nullptr, nullptr, qkvh, M_TOK, QKV_LD, D_MODEL);

    // 3) causal flash attention -> ao fp16 hi/lo
    flash_attn_mma<<<dim3(S_LEN / 128, 2 * H_NUM), 256, ATT_SMEM>>>(qkvh, aohi, aolo);

    // 4) output projection (2-pass fp16) + bias -> fp32 out
    gemm_mma<true, false><<<dim3(D_MODEL / 128, M_TOK / 128), 256, G_SMEM>>>(
        aohi, aolo, woh, b_out, out, nullptr, M_TOK, D_MODEL, D_MODEL);
}

// round 12
// speedup vs baseline: 4.4001x; 1.2189x over previous
#include <cuda_runtime.h>
#include <cuda_fp16.h>
#include <cstdint>
#include <cstddef>

#define S_LEN   2048
#define D_MODEL 1024
#define H_NUM   16
#define DH      64
#define M_TOK   4096
#define QKV_LD  3072

// ---------------------------------------------------------------------------
// Device scratch (fp16 words)
// ---------------------------------------------------------------------------
__device__ uint16_t g_x_hi  [(size_t)M_TOK * D_MODEL];
__device__ uint16_t g_x_lo  [(size_t)M_TOK * D_MODEL];
__device__ uint16_t g_wqkv_h[(size_t)QKV_LD * D_MODEL];   // single fp16
__device__ uint16_t g_qkv_h [(size_t)M_TOK * QKV_LD];     // single fp16
__device__ uint16_t g_ao_hi [(size_t)M_TOK * D_MODEL];
__device__ uint16_t g_ao_lo [(size_t)M_TOK * D_MODEL];
__device__ uint16_t g_wout_h[(size_t)D_MODEL * D_MODEL];  // single fp16

// ---------------------------------------------------------------------------
// PTX helpers
// ---------------------------------------------------------------------------
__device__ __forceinline__ uint32_t smem_u32(const void* p) {
    uint32_t a;
    asm("{ .reg .u64 t; cvta.to.shared.u64 t, %1; cvt.u32.u64 %0, t; }" : "=r"(a) : "l"(p));
    return a;
}
__device__ __forceinline__ void cp_async16(uint32_t dst, const void* src) {
    asm volatile("cp.async.cg.shared.global [%0], [%1], 16;" :: "r"(dst), "l"(src));
}
__device__ __forceinline__ void cp_commit() {
    asm volatile("cp.async.commit_group;" ::: "memory");
}
template <int N>
__device__ __forceinline__ void cp_wait() {
    asm volatile("cp.async.wait_group %0;" :: "n"(N) : "memory");
}
__device__ __forceinline__ void ldsm_x4(uint32_t& r0, uint32_t& r1, uint32_t& r2,
                                        uint32_t& r3, uint32_t a) {
    asm volatile("ldmatrix.sync.aligned.m8n8.x4.shared.b16 {%0,%1,%2,%3}, [%4];"
                 : "=r"(r0), "=r"(r1), "=r"(r2), "=r"(r3) : "r"(a));
}
__device__ __forceinline__ void ldsm_x4_t(uint32_t& r0, uint32_t& r1, uint32_t& r2,
                                          uint32_t& r3, uint32_t a) {
    asm volatile("ldmatrix.sync.aligned.m8n8.x4.trans.shared.b16 {%0,%1,%2,%3}, [%4];"
                 : "=r"(r0), "=r"(r1), "=r"(r2), "=r"(r3) : "r"(a));
}
__device__ __forceinline__ void mma_f16(float* d, const uint32_t* a, const uint32_t* b) {
    asm volatile("mma.sync.aligned.m16n8k16.row.col.f32.f16.f16.f32 "
                 "{%0,%1,%2,%3}, {%4,%5,%6,%7}, {%8,%9}, {%0,%1,%2,%3};"
                 : "+f"(d[0]), "+f"(d[1]), "+f"(d[2]), "+f"(d[3])
                 : "r"(a[0]), "r"(a[1]), "r"(a[2]), "r"(a[3]), "r"(b[0]), "r"(b[1]));
}
// fp32 pair -> fp16 hi/lo words
__device__ __forceinline__ void split_pair_h(float a, float b, uint32_t& hi, uint32_t& lo) {
    __half ha = __float2half_rn(a), hb = __float2half_rn(b);
    hi = (uint32_t)__half_as_ushort(ha) | ((uint32_t)__half_as_ushort(hb) << 16);
    lo = (uint32_t)__half_as_ushort(__float2half_rn(a - __half2float(ha))) |
         ((uint32_t)__half_as_ushort(__float2half_rn(b - __half2float(hb))) << 16);
}
__device__ __forceinline__ uint32_t pack_pair_h(float a, float b) {
    return (uint32_t)__half_as_ushort(__float2half_rn(a)) |
           ((uint32_t)__half_as_ushort(__float2half_rn(b)) << 16);
}

// ---------------------------------------------------------------------------
// Packers
// ---------------------------------------------------------------------------
__global__ __launch_bounds__(256) void pack_split_h(
    const float* __restrict__ in, uint16_t* __restrict__ hi,
    uint16_t* __restrict__ lo, int n4)
{
    int i = blockIdx.x * 256 + threadIdx.x;
    if (i >= n4) return;
    float4 v = reinterpret_cast<const float4*>(in)[i];
    uint32_t h0, l0, h1, l1;
    split_pair_h(v.x, v.y, h0, l0);
    split_pair_h(v.z, v.w, h1, l1);
    reinterpret_cast<uint2*>(hi)[i] = make_uint2(h0, h1);
    reinterpret_cast<uint2*>(lo)[i] = make_uint2(l0, l1);
}
__global__ __launch_bounds__(256) void pack_h16(
    const float* __restrict__ in, uint16_t* __restrict__ hi, int n4)
{
    int i = blockIdx.x * 256 + threadIdx.x;
    if (i >= n4) return;
    float4 v = reinterpret_cast<const float4*>(in)[i];
    reinterpret_cast<uint2*>(hi)[i] =
        make_uint2(pack_pair_h(v.x, v.y), pack_pair_h(v.z, v.w));
}

// ---------------------------------------------------------------------------
// HMMA fp16 GEMM: C[M,N] = (Ahi+Alo) @ Bhi^T (+bias). 2-pass, 3 smem tiles.
// CTA 128x128, BK=64, 8 warps (2x4), 2-stage cp.async pipeline.
// Tile = 128 x 72(pad) fp16 = 18432 B; stage = 55296 B; 2 stages = 110592 B
// -> 2 CTAs/SM. 144 B rows: 16B-aligned, ldmatrix conflict-free
// (bank start step 4 mod 32 across 8 rows).
// ---------------------------------------------------------------------------
#define BK        64
#define PAD_K     72
#define TILE_SMB  (128 * PAD_K * 2)      // 18432 B
#define STAGE_B   (3 * TILE_SMB)         // 55296 B
#define G_SMEM    (2 * STAGE_B)          // 110592 B

template <bool HAS_BIAS, bool SPLIT_OUT>
__global__ __launch_bounds__(256) void gemm_mma(
    const uint16_t* __restrict__ Ahi, const uint16_t* __restrict__ Alo,
    const uint16_t* __restrict__ Bhi,
    const float* __restrict__ bias, float* __restrict__ C,
    uint16_t* __restrict__ Chi,
    int M, int N, int K)
{
    extern __shared__ char smem[];
    const uint32_t sb = smem_u32(smem);
    const int tid = threadIdx.x;
    const int wid = tid >> 5;
    const int lane = tid & 31;
    const int bm = blockIdx.y * 128;
    const int bn = blockIdx.x * 128;
    const int wm = wid >> 2;
    const int wn = wid & 3;
    const int nk = K / BK;

    const uint16_t* gA0 = Ahi + (size_t)bm * K;
    const uint16_t* gA1 = Alo + (size_t)bm * K;
    const uint16_t* gB0 = Bhi + (size_t)bn * K;

    // 1024 16B-chunks per tile; 256 threads x 4 chunks
    auto load_stage = [&](int s, int k0) {
        uint32_t base = sb + s * STAGE_B;
        const uint16_t* g[3] = { gA0, gA1, gB0 };
#pragma unroll
        for (int t = 0; t < 3; ++t) {
            uint32_t tb = base + t * TILE_SMB;
#pragma unroll
            for (int it = 0; it < 4; ++it) {
                int c = tid + it * 256;          // 0..1023
                int r = c >> 3, col = (c & 7) * 8;
                cp_async16(tb + r * (PAD_K * 2) + col * 2,
                           g[t] + (size_t)r * K + k0 + col);
            }
        }
        cp_commit();
    };

    float acc[4][4][4];
#pragma unroll
    for (int mt = 0; mt < 4; ++mt)
#pragma unroll
        for (int nt = 0; nt < 4; ++nt)
#pragma unroll
            for (int e = 0; e < 4; ++e) acc[mt][nt][e] = 0.f;

    const int lrow8 = lane & 7;
    const int lq    = lane >> 3;
    const int a_roff = lrow8 + (lq & 1) * 8;
    const int a_coff = (lq >> 1) * 8;
    const int b_noff = lrow8 + (lq >> 1) * 8;
    const int b_coff = (lq & 1) * 8;

    load_stage(0, 0);

    for (int i = 0; i < nk; ++i) {
        const int s = i & 1;
        if (i + 1 < nk) { load_stage(s ^ 1, (i + 1) * BK); cp_wait<1>(); }
        else            { cp_wait<0>(); }
        __syncthreads();

        const uint32_t stg = sb + s * STAGE_B;
#pragma unroll
        for (int kk = 0; kk < BK; kk += 16) {
            uint32_t bh[4][2];
#pragma unroll
            for (int ntp = 0; ntp < 2; ++ntp) {
                int nidx = wn * 32 + ntp * 16 + b_noff;
                int cidx = kk + b_coff;
                ldsm_x4(bh[2 * ntp][0], bh[2 * ntp][1], bh[2 * ntp + 1][0], bh[2 * ntp + 1][1],
                        stg + 2 * TILE_SMB + (nidx * PAD_K + cidx) * 2);
            }
#pragma unroll
            for (int mt = 0; mt < 4; ++mt) {
                int midx = wm * 64 + mt * 16 + a_roff;
                int cidx = kk + a_coff;
                uint32_t ah[4], al[4];
                ldsm_x4(ah[0], ah[1], ah[2], ah[3], stg + 0 * TILE_SMB + (midx * PAD_K + cidx) * 2);
                ldsm_x4(al[0], al[1], al[2], al[3], stg + 1 * TILE_SMB + (midx * PAD_K + cidx) * 2);
#pragma unroll
                for (int nt = 0; nt < 4; ++nt) {
                    mma_f16(acc[mt][nt], ah, bh[nt]);
                    mma_f16(acc[mt][nt], al, bh[nt]);
                }
            }
        }
        __syncthreads();
    }

#pragma unroll
    for (int mt = 0; mt < 4; ++mt) {
#pragma unroll
        for (int nt = 0; nt < 4; ++nt) {
            int r = bm + wm * 64 + mt * 16 + (lane >> 2);
            int c = bn + wn * 32 + nt * 8 + (lane & 3) * 2;
            if (SPLIT_OUT) {
                *reinterpret_cast<uint32_t*>(&Chi[(size_t)r * N + c]) =
                    pack_pair_h(acc[mt][nt][0], acc[mt][nt][1]);
                *reinterpret_cast<uint32_t*>(&Chi[(size_t)(r + 8) * N + c]) =
                    pack_pair_h(acc[mt][nt][2], acc[mt][nt][3]);
            } else {
                float b0 = 0.f, b1 = 0.f;
                if (HAS_BIAS) { b0 = bias[c]; b1 = bias[c + 1]; }
                *reinterpret_cast<float2*>(&C[(size_t)r * N + c]) =
                    make_float2(acc[mt][nt][0] + b0, acc[mt][nt][1] + b1);
                *reinterpret_cast<float2*>(&C[(size_t)(r + 8) * N + c]) =
                    make_float2(acc[mt][nt][2] + b0, acc[mt][nt][3] + b1);
            }
        }
    }
}

// ---------------------------------------------------------------------------
// fp16 causal flash attention.
// S = Qhi·Khi (single pass); O += Phi·Vhi (single pass).
// CTA: 128 q-rows x (b,h). 8 warps. Bc=64. 3-stage KV pipeline.
// ---------------------------------------------------------------------------
#define ATT_PAD    72
#define ATT_ROWB   (ATT_PAD * 2)          // 144 B
#define KV_TILE_B  (64 * ATT_ROWB)        // 9216
#define ATT_STAGE  (2 * KV_TILE_B)        // 18432 (Khi, Vhi)
#define ATT_SMEM   (3 * ATT_STAGE)        // 55296

__global__ __launch_bounds__(256) void flash_attn_mma(
    const uint16_t* __restrict__ qkv_h,
    uint16_t* __restrict__ ao_hi, uint16_t* __restrict__ ao_lo)
{
    extern __shared__ char smem[];
    const uint32_t sb = smem_u32(smem);
    const int tid = threadIdx.x, wid = tid >> 5, lane = tid & 31;
    const int qb = 15 - blockIdx.x;
    const int bh = blockIdx.y;
    const int b = bh >> 4, h = bh & 15;
    const size_t tok0 = (size_t)b * S_LEN;

    const int lrow8 = lane & 7, lq = lane >> 3;
    const int a_roff = lrow8 + (lq & 1) * 8;
    const int a_coff = (lq >> 1) * 8;
    const int b_noff = lrow8 + (lq >> 1) * 8;
    const int b_coff = (lq & 1) * 8;
    const int v_roff = (lane & 7) + ((lane >> 3) & 1) * 8;
    const int v_coff = (lane >> 4) * 8;

    // ---- stage Q (hi only) into smem; pull frags to regs
    {
        const size_t qrow0 = tok0 + (size_t)qb * 128;
#pragma unroll
        for (int it = 0; it < 4; ++it) {
            int c = tid + it * 256;
            int r = c >> 3, col = (c & 7) * 8;
            cp_async16(sb + r * ATT_ROWB + col * 2,
                       qkv_h + (qrow0 + r) * QKV_LD + h * 192 + col);
        }
        cp_commit();
        cp_wait<0>();
        __syncthreads();
    }
    uint32_t qh[4][4];
#pragma unroll
    for (int j = 0; j < 4; ++j) {
        int rr = wid * 16 + a_roff;
        int cc = j * 16 + a_coff;
        ldsm_x4(qh[j][0], qh[j][1], qh[j][2], qh[j][3], sb + rr * ATT_ROWB + cc * 2);
    }
    __syncthreads();

    // KV stage: Khi tile + Vhi tile
    auto load_kv = [&](int s, int kb) {
        uint32_t base = sb + s * ATT_STAGE;
        const size_t krow0 = tok0 + (size_t)kb * 64;
        const int koff = h * 192 + 64, voff = h * 192 + 128;
#pragma unroll
        for (int it = 0; it < 2; ++it) {
            int c = tid + it * 256;
            int r = c >> 3, col = (c & 7) * 8;
            const size_t go = (krow0 + r) * QKV_LD + col;
            cp_async16(base + r * ATT_ROWB + col * 2, qkv_h + go + koff);
            cp_async16(base + KV_TILE_B + r * ATT_ROWB + col * 2, qkv_h + go + voff);
        }
        cp_commit();
    };

    float o[8][4];
#pragma unroll
    for (int nt = 0; nt < 8; ++nt)
#pragma unroll
        for (int e = 0; e < 4; ++e) o[nt][e] = 0.f;
    float m0 = -1e30f, m1 = -1e30f, l0 = 0.f, l1 = 0.f;

    const int nkb = 2 * qb + 2;
    load_kv(0, 0);
    if (nkb > 1) load_kv(1, 1);

    for (int kb = 0; kb < nkb; ++kb) {
        const int s = kb % 3;
        if (kb + 2 < nkb) { load_kv((kb + 2) % 3, kb + 2); cp_wait<2>(); }
        else if (kb + 1 < nkb) { cp_wait<1>(); }
        else { cp_wait<0>(); }
        __syncthreads();
        const uint32_t kbase = sb + s * ATT_STAGE;

        // ---- S = Qhi @ Khi^T (single pass)
        float sc[8][4];
#pragma unroll
        for (int nt = 0; nt < 8; ++nt)
#pragma unroll
            for (int e = 0; e < 4; ++e) sc[nt][e] = 0.f;

#pragma unroll
        for (int j = 0; j < 4; ++j) {
            uint32_t kf[8][2];
#pragma unroll
            for (int p = 0; p < 4; ++p) {
                int nn = p * 16 + b_noff;
                int cc = j * 16 + b_coff;
                ldsm_x4(kf[2 * p][0], kf[2 * p][1], kf[2 * p + 1][0], kf[2 * p + 1][1],
                        kbase + nn * ATT_ROWB + cc * 2);
            }
#pragma unroll
            for (int nt = 0; nt < 8; ++nt)
                mma_f16(sc[nt], qh[j], kf[nt]);
        }

#pragma unroll
        for (int nt = 0; nt < 8; ++nt)
#pragma unroll
            for (int e = 0; e < 4; ++e) sc[nt][e] *= 0.125f;

        if (kb >= 2 * qb) {
            const int gr0 = qb * 128 + wid * 16 + (lane >> 2);
#pragma unroll
            for (int nt = 0; nt < 8; ++nt) {
                int gc = kb * 64 + nt * 8 + (lane & 3) * 2;
                if (gc     > gr0)     sc[nt][0] = -1e30f;
                if (gc + 1 > gr0)     sc[nt][1] = -1e30f;
                if (gc     > gr0 + 8) sc[nt][2] = -1e30f;
                if (gc + 1 > gr0 + 8) sc[nt][3] = -1e30f;
            }
        }

        // ---- online softmax
        float mx0 = -1e30f, mx1 = -1e30f;
#pragma unroll
        for (int nt = 0; nt < 8; ++nt) {
            mx0 = fmaxf(mx0, fmaxf(sc[nt][0], sc[nt][1]));
            mx1 = fmaxf(mx1, fmaxf(sc[nt][2], sc[nt][3]));
        }
#pragma unroll
        for (int w = 1; w < 4; w <<= 1) {
            mx0 = fmaxf(mx0, __shfl_xor_sync(0xffffffffu, mx0, w));
            mx1 = fmaxf(mx1, __shfl_xor_sync(0xffffffffu, mx1, w));
        }
        float mn0 = fmaxf(m0, mx0), mn1 = fmaxf(m1, mx1);
        float c0 = __expf(m0 - mn0), c1 = __expf(m1 - mn1);
        m0 = mn0; m1 = mn1;
        float rs0 = 0.f, rs1 = 0.f;
#pragma unroll
        for (int nt = 0; nt < 8; ++nt) {
            sc[nt][0] = __expf(sc[nt][0] - mn0);
            sc[nt][1] = __expf(sc[nt][1] - mn0);
            sc[nt][2] = __expf(sc[nt][2] - mn1);
            sc[nt][3] = __expf(sc[nt][3] - mn1);
            rs0 += sc[nt][0] + sc[nt][1];
            rs1 += sc[nt][2] + sc[nt][3];
        }
#pragma unroll
        for (int w = 1; w < 4; w <<= 1) {
            rs0 += __shfl_xor_sync(0xffffffffu, rs0, w);
            rs1 += __shfl_xor_sync(0xffffffffu, rs1, w);
        }
        l0 = l0 * c0 + rs0;
        l1 = l1 * c1 + rs1;
#pragma unroll
        for (int nt = 0; nt < 8; ++nt) {
            o[nt][0] *= c0; o[nt][1] *= c0;
            o[nt][2] *= c1; o[nt][3] *= c1;
        }

        // ---- O += Phi @ Vhi (single pass; P packed fp16 in regs)
#pragma unroll
        for (int j = 0; j < 4; ++j) {
            uint32_t ph[4];
            ph[0] = pack_pair_h(sc[2 * j][0],     sc[2 * j][1]);
            ph[1] = pack_pair_h(sc[2 * j][2],     sc[2 * j][3]);
            ph[2] = pack_pair_h(sc[2 * j + 1][0], sc[2 * j + 1][1]);
            ph[3] = pack_pair_h(sc[2 * j + 1][2], sc[2 * j + 1][3]);

            uint32_t vf[8][2];
#pragma unroll
            for (int p = 0; p < 4; ++p) {
                uint32_t ar = (j * 16 + v_roff) * ATT_ROWB + (p * 16 + v_coff) * 2;
                ldsm_x4_t(vf[2 * p][0], vf[2 * p][1], vf[2 * p + 1][0], vf[2 * p + 1][1],
                          kbase + KV_TILE_B + ar);
            }
#pragma unroll
            for (int nt = 0; nt < 8; ++nt)
                mma_f16(o[nt], ph, vf[nt]);
        }
        __syncthreads();
    }

    // ---- normalize + write ao as fp16 hi/lo
    const float inv0 = 1.f / l0, inv1 = 1.f / l1;
    const int gr0 = qb * 128 + wid * 16 + (lane >> 2);
    const size_t row0 = (tok0 + gr0) * D_MODEL;
    const size_t row1 = (tok0 + gr0 + 8) * D_MODEL;
    const int colb = h * DH + (lane & 3) * 2;
#pragma unroll
    for (int nt = 0; nt < 8; ++nt) {
        int c = colb + nt * 8;
        uint32_t hi0, lo0, hi1, lo1;
        split_pair_h(o[nt][0] * inv0, o[nt][1] * inv0, hi0, lo0);
        split_pair_h(o[nt][2] * inv1, o[nt][3] * inv1, hi1, lo1);
        *reinterpret_cast<uint32_t*>(&ao_hi[row0 + c]) = hi0;
        *reinterpret_cast<uint32_t*>(&ao_lo[row0 + c]) = lo0;
        *reinterpret_cast<uint32_t*>(&ao_hi[row1 + c]) = hi1;
        *reinterpret_cast<uint32_t*>(&ao_lo[row1 + c]) = lo1;
    }
}

// ---------------------------------------------------------------------------
extern "C" void kernel_launch(void* const* d_in, const int* in_sizes, int n_in,
                              void* d_out, int out_size)
{
    (void)in_sizes; (void)n_in; (void)out_size;
    const float* x     = (const float*)d_in[0];
    const float* w_qkv = (const float*)d_in[1];
    const float* w_out = (const float*)d_in[2];
    const float* b_out = (const float*)d_in[3];
    float* out = (float*)d_out;

    uint16_t *xhi, *xlo, *wq, *qkvh, *aohi, *aolo, *woh;
    cudaGetSymbolAddress((void**)&xhi, g_x_hi);
    cudaGetSymbolAddress((void**)&xlo, g_x_lo);
    cudaGetSymbolAddress((void**)&wq,  g_wqkv_h);
    cudaGetSymbolAddress((void**)&qkvh, g_qkv_h);
    cudaGetSymbolAddress((void**)&aohi, g_ao_hi);
    cudaGetSymbolAddress((void**)&aolo, g_ao_lo);
    cudaGetSymbolAddress((void**)&woh, g_wout_h);

    cudaFuncSetAttribute((gemm_mma<false, true>),
                         cudaFuncAttributeMaxDynamicSharedMemorySize, G_SMEM);
    cudaFuncSetAttribute((gemm_mma<true, false>),
                         cudaFuncAttributeMaxDynamicSharedMemorySize, G_SMEM);
    cudaFuncSetAttribute(flash_attn_mma,
                         cudaFuncAttributeMaxDynamicSharedMemorySize, ATT_SMEM);

    // 1) pack inputs: x -> fp16 hi/lo; w_qkv, w_out -> fp16 single
    {
        int n4 = M_TOK * D_MODEL / 4;
        pack_split_h<<<(n4 + 255) / 256, 256>>>(x, xhi, xlo, n4);
        n4 = QKV_LD * D_MODEL / 4;
        pack_h16<<<(n4 + 255) / 256, 256>>>(w_qkv, wq, n4);
        n4 = D_MODEL * D_MODEL / 4;
        pack_h16<<<(n4 + 255) / 256, 256>>>(w_out, woh, n4);
    }

    // 2) QKV projection (2-pass fp16) -> qkv fp16 (hi only)
    //    gemm_mma(Ahi, Alo, Bhi, bias, C, Chi, M, N, K)
    gemm_mma<false, true><<<dim3(QKV_LD / 128, M_TOK / 128), 256, G_SMEM>>>(
        xhi, xlo, wq, nullptr, nullptr, qkvh, M_TOK, QKV_LD, D_MODEL);

    // 3) causal flash attention -> ao fp16 hi/lo
    flash_attn_mma<<<dim3(S_LEN / 128, 2 * H_NUM), 256, ATT_SMEM>>>(qkvh, aohi, aolo);

    // 4) output projection (2-pass fp16) + bias -> fp32 out
    gemm_mma<true, false><<<dim3(D_MODEL / 128, M_TOK / 128), 256, G_SMEM>>>(
        aohi, aolo, woh, b_out, out, nullptr, M_TOK, D_MODEL, D_MODEL);
}

// round 13
// speedup vs baseline: 5.3915x; 1.2253x over previous
#include <cuda_runtime.h>
#include <cuda_fp16.h>
#include <cstdint>
#include <cstddef>

#define S_LEN   2048
#define D_MODEL 1024
#define H_NUM   16
#define DH      64
#define M_TOK   4096
#define QKV_LD  3072

// ---------------------------------------------------------------------------
// Device scratch (fp16 words)
// ---------------------------------------------------------------------------
__device__ uint16_t g_x_h   [(size_t)M_TOK * D_MODEL];    // single fp16
__device__ uint16_t g_wqkv_h[(size_t)QKV_LD * D_MODEL];   // single fp16
__device__ uint16_t g_qkv_h [(size_t)M_TOK * QKV_LD];     // single fp16
__device__ uint16_t g_ao_hi [(size_t)M_TOK * D_MODEL];
__device__ uint16_t g_ao_lo [(size_t)M_TOK * D_MODEL];
__device__ uint16_t g_wout_h[(size_t)D_MODEL * D_MODEL];  // single fp16

// ---------------------------------------------------------------------------
// PTX helpers
// ---------------------------------------------------------------------------
__device__ __forceinline__ uint32_t smem_u32(const void* p) {
    uint32_t a;
    asm("{ .reg .u64 t; cvta.to.shared.u64 t, %1; cvt.u32.u64 %0, t; }" : "=r"(a) : "l"(p));
    return a;
}
__device__ __forceinline__ void cp_async16(uint32_t dst, const void* src) {
    asm volatile("cp.async.cg.shared.global [%0], [%1], 16;" :: "r"(dst), "l"(src));
}
__device__ __forceinline__ void cp_commit() {
    asm volatile("cp.async.commit_group;" ::: "memory");
}
template <int N>
__device__ __forceinline__ void cp_wait() {
    asm volatile("cp.async.wait_group %0;" :: "n"(N) : "memory");
}
__device__ __forceinline__ void ldsm_x4(uint32_t& r0, uint32_t& r1, uint32_t& r2,
                                        uint32_t& r3, uint32_t a) {
    asm volatile("ldmatrix.sync.aligned.m8n8.x4.shared.b16 {%0,%1,%2,%3}, [%4];"
                 : "=r"(r0), "=r"(r1), "=r"(r2), "=r"(r3) : "r"(a));
}
__device__ __forceinline__ void ldsm_x4_t(uint32_t& r0, uint32_t& r1, uint32_t& r2,
                                          uint32_t& r3, uint32_t a) {
    asm volatile("ldmatrix.sync.aligned.m8n8.x4.trans.shared.b16 {%0,%1,%2,%3}, [%4];"
                 : "=r"(r0), "=r"(r1), "=r"(r2), "=r"(r3) : "r"(a));
}
__device__ __forceinline__ void mma_f16(float* d, const uint32_t* a, const uint32_t* b) {
    asm volatile("mma.sync.aligned.m16n8k16.row.col.f32.f16.f16.f32 "
                 "{%0,%1,%2,%3}, {%4,%5,%6,%7}, {%8,%9}, {%0,%1,%2,%3};"
                 : "+f"(d[0]), "+f"(d[1]), "+f"(d[2]), "+f"(d[3])
                 : "r"(a[0]), "r"(a[1]), "r"(a[2]), "r"(a[3]), "r"(b[0]), "r"(b[1]));
}
// fp32 pair -> fp16 hi/lo words
__device__ __forceinline__ void split_pair_h(float a, float b, uint32_t& hi, uint32_t& lo) {
    __half ha = __float2half_rn(a), hb = __float2half_rn(b);
    hi = (uint32_t)__half_as_ushort(ha) | ((uint32_t)__half_as_ushort(hb) << 16);
    lo = (uint32_t)__half_as_ushort(__float2half_rn(a - __half2float(ha))) |
         ((uint32_t)__half_as_ushort(__float2half_rn(b - __half2float(hb))) << 16);
}
__device__ __forceinline__ uint32_t pack_pair_h(float a, float b) {
    return (uint32_t)__half_as_ushort(__float2half_rn(a)) |
           ((uint32_t)__half_as_ushort(__float2half_rn(b)) << 16);
}

// ---------------------------------------------------------------------------
// Packers
// ---------------------------------------------------------------------------
__global__ __launch_bounds__(256) void pack_h16(
    const float* __restrict__ in, uint16_t* __restrict__ hi, int n4)
{
    int i = blockIdx.x * 256 + threadIdx.x;
    if (i >= n4) return;
    float4 v = reinterpret_cast<const float4*>(in)[i];
    reinterpret_cast<uint2*>(hi)[i] =
        make_uint2(pack_pair_h(v.x, v.y), pack_pair_h(v.z, v.w));
}

// ---------------------------------------------------------------------------
// HMMA fp16 GEMM: C[M,N] = A @ Bhi^T (+bias).
// PASSES=1: A single (2 smem tiles/stage). PASSES=2: A = Ahi+Alo (3 tiles).
// CTA 128x128, BK=64, 8 warps (2x4), 2-stage cp.async pipeline.
// Tile = 128 x 72(pad) fp16 = 18432 B. 144 B rows: 16B-aligned, conflict-free.
// SPLIT_OUT: write single fp16 to Chi.
// ---------------------------------------------------------------------------
#define BK        64
#define PAD_K     72
#define TILE_SMB  (128 * PAD_K * 2)      // 18432 B

template <int PASSES, bool HAS_BIAS, bool SPLIT_OUT>
__global__ __launch_bounds__(256) void gemm_mma(
    const uint16_t* __restrict__ Ahi, const uint16_t* __restrict__ Alo,
    const uint16_t* __restrict__ Bhi,
    const float* __restrict__ bias, float* __restrict__ C,
    uint16_t* __restrict__ Chi,
    int M, int N, int K)
{
    constexpr int NT = PASSES + 1;          // tiles per stage
    constexpr int BTILE = PASSES;           // B tile index
    constexpr int STAGE_B = NT * TILE_SMB;

    extern __shared__ char smem[];
    const uint32_t sb = smem_u32(smem);
    const int tid = threadIdx.x;
    const int wid = tid >> 5;
    const int lane = tid & 31;
    const int bm = blockIdx.y * 128;
    const int bn = blockIdx.x * 128;
    const int wm = wid >> 2;
    const int wn = wid & 3;
    const int nk = K / BK;

    const uint16_t* gA0 = Ahi + (size_t)bm * K;
    const uint16_t* gA1 = (PASSES == 2) ? (Alo + (size_t)bm * K) : nullptr;
    const uint16_t* gB0 = Bhi + (size_t)bn * K;

    auto load_tile = [&](uint32_t tb, const uint16_t* g, int k0) {
#pragma unroll
        for (int it = 0; it < 4; ++it) {
            int c = tid + it * 256;          // 0..1023
            int r = c >> 3, col = (c & 7) * 8;
            cp_async16(tb + r * (PAD_K * 2) + col * 2, g + (size_t)r * K + k0 + col);
        }
    };
    auto load_stage = [&](int s, int k0) {
        uint32_t base = sb + s * STAGE_B;
        load_tile(base + 0 * TILE_SMB, gA0, k0);
        if (PASSES == 2) load_tile(base + 1 * TILE_SMB, gA1, k0);
        load_tile(base + BTILE * TILE_SMB, gB0, k0);
        cp_commit();
    };

    float acc[4][4][4];
#pragma unroll
    for (int mt = 0; mt < 4; ++mt)
#pragma unroll
        for (int nt = 0; nt < 4; ++nt)
#pragma unroll
            for (int e = 0; e < 4; ++e) acc[mt][nt][e] = 0.f;

    const int lrow8 = lane & 7;
    const int lq    = lane >> 3;
    const int a_roff = lrow8 + (lq & 1) * 8;
    const int a_coff = (lq >> 1) * 8;
    const int b_noff = lrow8 + (lq >> 1) * 8;
    const int b_coff = (lq & 1) * 8;

    load_stage(0, 0);

    for (int i = 0; i < nk; ++i) {
        const int s = i & 1;
        if (i + 1 < nk) { load_stage(s ^ 1, (i + 1) * BK); cp_wait<1>(); }
        else            { cp_wait<0>(); }
        __syncthreads();

        const uint32_t stg = sb + s * STAGE_B;
#pragma unroll
        for (int kk = 0; kk < BK; kk += 16) {
            uint32_t bh[4][2];
#pragma unroll
            for (int ntp = 0; ntp < 2; ++ntp) {
                int nidx = wn * 32 + ntp * 16 + b_noff;
                int cidx = kk + b_coff;
                ldsm_x4(bh[2 * ntp][0], bh[2 * ntp][1], bh[2 * ntp + 1][0], bh[2 * ntp + 1][1],
                        stg + BTILE * TILE_SMB + (nidx * PAD_K + cidx) * 2);
            }
#pragma unroll
            for (int mt = 0; mt < 4; ++mt) {
                int midx = wm * 64 + mt * 16 + a_roff;
                int cidx = kk + a_coff;
                uint32_t ah[4];
                ldsm_x4(ah[0], ah[1], ah[2], ah[3], stg + 0 * TILE_SMB + (midx * PAD_K + cidx) * 2);
                uint32_t al[4];
                if (PASSES == 2)
                    ldsm_x4(al[0], al[1], al[2], al[3],
                            stg + 1 * TILE_SMB + (midx * PAD_K + cidx) * 2);
#pragma unroll
                for (int nt = 0; nt < 4; ++nt) {
                    mma_f16(acc[mt][nt], ah, bh[nt]);
                    if (PASSES == 2) mma_f16(acc[mt][nt], al, bh[nt]);
                }
            }
        }
        __syncthreads();
    }

#pragma unroll
    for (int mt = 0; mt < 4; ++mt) {
#pragma unroll
        for (int nt = 0; nt < 4; ++nt) {
            int r = bm + wm * 64 + mt * 16 + (lane >> 2);
            int c = bn + wn * 32 + nt * 8 + (lane & 3) * 2;
            if (SPLIT_OUT) {
                *reinterpret_cast<uint32_t*>(&Chi[(size_t)r * N + c]) =
                    pack_pair_h(acc[mt][nt][0], acc[mt][nt][1]);
                *reinterpret_cast<uint32_t*>(&Chi[(size_t)(r + 8) * N + c]) =
                    pack_pair_h(acc[mt][nt][2], acc[mt][nt][3]);
            } else {
                float b0 = 0.f, b1 = 0.f;
                if (HAS_BIAS) { b0 = bias[c]; b1 = bias[c + 1]; }
                *reinterpret_cast<float2*>(&C[(size_t)r * N + c]) =
                    make_float2(acc[mt][nt][0] + b0, acc[mt][nt][1] + b1);
                *reinterpret_cast<float2*>(&C[(size_t)(r + 8) * N + c]) =
                    make_float2(acc[mt][nt][2] + b0, acc[mt][nt][3] + b1);
            }
        }
    }
}

// ---------------------------------------------------------------------------
// fp16 causal flash attention.
// S = Qhi·Khi (single pass); O += Phi·Vhi (single pass).
// CTA: 128 q-rows x (b,h). 8 warps. Bc=64. 3-stage KV pipeline.
// ---------------------------------------------------------------------------
#define ATT_PAD    72
#define ATT_ROWB   (ATT_PAD * 2)          // 144 B
#define KV_TILE_B  (64 * ATT_ROWB)        // 9216
#define ATT_STAGE  (2 * KV_TILE_B)        // 18432 (Khi, Vhi)
#define ATT_SMEM   (3 * ATT_STAGE)        // 55296

__global__ __launch_bounds__(256) void flash_attn_mma(
    const uint16_t* __restrict__ qkv_h,
    uint16_t* __restrict__ ao_hi, uint16_t* __restrict__ ao_lo)
{
    extern __shared__ char smem[];
    const uint32_t sb = smem_u32(smem);
    const int tid = threadIdx.x, wid = tid >> 5, lane = tid & 31;
    const int qb = 15 - blockIdx.x;
    const int bh = blockIdx.y;
    const int b = bh >> 4, h = bh & 15;
    const size_t tok0 = (size_t)b * S_LEN;

    const int lrow8 = lane & 7, lq = lane >> 3;
    const int a_roff = lrow8 + (lq & 1) * 8;
    const int a_coff = (lq >> 1) * 8;
    const int b_noff = lrow8 + (lq >> 1) * 8;
    const int b_coff = (lq & 1) * 8;
    const int v_roff = (lane & 7) + ((lane >> 3) & 1) * 8;
    const int v_coff = (lane >> 4) * 8;

    // ---- stage Q into smem; pull frags to regs
    {
        const size_t qrow0 = tok0 + (size_t)qb * 128;
#pragma unroll
        for (int it = 0; it < 4; ++it) {
            int c = tid + it * 256;
            int r = c >> 3, col = (c & 7) * 8;
            cp_async16(sb + r * ATT_ROWB + col * 2,
                       qkv_h + (qrow0 + r) * QKV_LD + h * 192 + col);
        }
        cp_commit();
        cp_wait<0>();
        __syncthreads();
    }
    uint32_t qh[4][4];
#pragma unroll
    for (int j = 0; j < 4; ++j) {
        int rr = wid * 16 + a_roff;
        int cc = j * 16 + a_coff;
        ldsm_x4(qh[j][0], qh[j][1], qh[j][2], qh[j][3], sb + rr * ATT_ROWB + cc * 2);
    }
    __syncthreads();

    // KV stage: Khi tile + Vhi tile
    auto load_kv = [&](int s, int kb) {
        uint32_t base = sb + s * ATT_STAGE;
        const size_t krow0 = tok0 + (size_t)kb * 64;
        const int koff = h * 192 + 64, voff = h * 192 + 128;
#pragma unroll
        for (int it = 0; it < 2; ++it) {
            int c = tid + it * 256;
            int r = c >> 3, col = (c & 7) * 8;
            const size_t go = (krow0 + r) * QKV_LD + col;
            cp_async16(base + r * ATT_ROWB + col * 2, qkv_h + go + koff);
            cp_async16(base + KV_TILE_B + r * ATT_ROWB + col * 2, qkv_h + go + voff);
        }
        cp_commit();
    };

    float o[8][4];
#pragma unroll
    for (int nt = 0; nt < 8; ++nt)
#pragma unroll
        for (int e = 0; e < 4; ++e) o[nt][e] = 0.f;
    float m0 = -1e30f, m1 = -1e30f, l0 = 0.f, l1 = 0.f;

    const int nkb = 2 * qb + 2;
    load_kv(0, 0);
    if (nkb > 1) load_kv(1, 1);

    for (int kb = 0; kb < nkb; ++kb) {
        const int s = kb % 3;
        if (kb + 2 < nkb) { load_kv((kb + 2) % 3, kb + 2); cp_wait<2>(); }
        else if (kb + 1 < nkb) { cp_wait<1>(); }
        else { cp_wait<0>(); }
        __syncthreads();
        const uint32_t kbase = sb + s * ATT_STAGE;

        // ---- S = Qhi @ Khi^T
        float sc[8][4];
#pragma unroll
        for (int nt = 0; nt < 8; ++nt)
#pragma unroll
            for (int e = 0; e < 4; ++e) sc[nt][e] = 0.f;

#pragma unroll
        for (int j = 0; j < 4; ++j) {
            uint32_t kf[8][2];
#pragma unroll
            for (int p = 0; p < 4; ++p) {
                int nn = p * 16 + b_noff;
                int cc = j * 16 + b_coff;
                ldsm_x4(kf[2 * p][0], kf[2 * p][1], kf[2 * p + 1][0], kf[2 * p + 1][1],
                        kbase + nn * ATT_ROWB + cc * 2);
            }
#pragma unroll
            for (int nt = 0; nt < 8; ++nt)
                mma_f16(sc[nt], qh[j], kf[nt]);
        }

#pragma unroll
        for (int nt = 0; nt < 8; ++nt)
#pragma unroll
            for (int e = 0; e < 4; ++e) sc[nt][e] *= 0.125f;

        if (kb >= 2 * qb) {
            const int gr0 = qb * 128 + wid * 16 + (lane >> 2);
#pragma unroll
            for (int nt = 0; nt < 8; ++nt) {
                int gc = kb * 64 + nt * 8 + (lane & 3) * 2;
                if (gc     > gr0)     sc[nt][0] = -1e30f;
                if (gc + 1 > gr0)     sc[nt][1] = -1e30f;
                if (gc     > gr0 + 8) sc[nt][2] = -1e30f;
                if (gc + 1 > gr0 + 8) sc[nt][3] = -1e30f;
            }
        }

        // ---- online softmax
        float mx0 = -1e30f, mx1 = -1e30f;
#pragma unroll
        for (int nt = 0; nt < 8; ++nt) {
            mx0 = fmaxf(mx0, fmaxf(sc[nt][0], sc[nt][1]));
            mx1 = fmaxf(mx1, fmaxf(sc[nt][2], sc[nt][3]));
        }
#pragma unroll
        for (int w = 1; w < 4; w <<= 1) {
            mx0 = fmaxf(mx0, __shfl_xor_sync(0xffffffffu, mx0, w));
            mx1 = fmaxf(mx1, __shfl_xor_sync(0xffffffffu, mx1, w));
        }
        float mn0 = fmaxf(m0, mx0), mn1 = fmaxf(m1, mx1);
        float c0 = __expf(m0 - mn0), c1 = __expf(m1 - mn1);
        m0 = mn0; m1 = mn1;
        float rs0 = 0.f, rs1 = 0.f;
#pragma unroll
        for (int nt = 0; nt < 8; ++nt) {
            sc[nt][0] = __expf(sc[nt][0] - mn0);
            sc[nt][1] = __expf(sc[nt][1] - mn0);
            sc[nt][2] = __expf(sc[nt][2] - mn1);
            sc[nt][3] = __expf(sc[nt][3] - mn1);
            rs0 += sc[nt][0] + sc[nt][1];
            rs1 += sc[nt][2] + sc[nt][3];
        }
#pragma unroll
        for (int w = 1; w < 4; w <<= 1) {
            rs0 += __shfl_xor_sync(0xffffffffu, rs0, w);
            rs1 += __shfl_xor_sync(0xffffffffu, rs1, w);
        }
        l0 = l0 * c0 + rs0;
        l1 = l1 * c1 + rs1;
#pragma unroll
        for (int nt = 0; nt < 8; ++nt) {
            o[nt][0] *= c0; o[nt][1] *= c0;
            o[nt][2] *= c1; o[nt][3] *= c1;
        }

        // ---- O += Phi @ Vhi
#pragma unroll
        for (int j = 0; j < 4; ++j) {
            uint32_t ph[4];
            ph[0] = pack_pair_h(sc[2 * j][0],     sc[2 * j][1]);
            ph[1] = pack_pair_h(sc[2 * j][2],     sc[2 * j][3]);
            ph[2] = pack_pair_h(sc[2 * j + 1][0], sc[2 * j + 1][1]);
            ph[3] = pack_pair_h(sc[2 * j + 1][2], sc[2 * j + 1][3]);

            uint32_t vf[8][2];
#pragma unroll
            for (int p = 0; p < 4; ++p) {
                uint32_t ar = (j * 16 + v_roff) * ATT_ROWB + (p * 16 + v_coff) * 2;
                ldsm_x4_t(vf[2 * p][0], vf[2 * p][1], vf[2 * p + 1][0], vf[2 * p + 1][1],
                          kbase + KV_TILE_B + ar);
            }
#pragma unroll
            for (int nt = 0; nt < 8; ++nt)
                mma_f16(o[nt], ph, vf[nt]);
        }
        __syncthreads();
    }

    // ---- normalize + write ao as fp16 hi/lo
    const float inv0 = 1.f / l0, inv1 = 1.f / l1;
    const int gr0 = qb * 128 + wid * 16 + (lane >> 2);
    const size_t row0 = (tok0 + gr0) * D_MODEL;
    const size_t row1 = (tok0 + gr0 + 8) * D_MODEL;
    const int colb = h * DH + (lane & 3) * 2;
#pragma unroll
    for (int nt = 0; nt < 8; ++nt) {
        int c = colb + nt * 8;
        uint32_t hi0, lo0, hi1, lo1;
        split_pair_h(o[nt][0] * inv0, o[nt][1] * inv0, hi0, lo0);
        split_pair_h(o[nt][2] * inv1, o[nt][3] * inv1, hi1, lo1);
        *reinterpret_cast<uint32_t*>(&ao_hi[row0 + c]) = hi0;
        *reinterpret_cast<uint32_t*>(&ao_lo[row0 + c]) = lo0;
        *reinterpret_cast<uint32_t*>(&ao_hi[row1 + c]) = hi1;
        *reinterpret_cast<uint32_t*>(&ao_lo[row1 + c]) = lo1;
    }
}

// ---------------------------------------------------------------------------
extern "C" void kernel_launch(void* const* d_in, const int* in_sizes, int n_in,
                              void* d_out, int out_size)
{
    (void)in_sizes; (void)n_in; (void)out_size;
    const float* x     = (const float*)d_in[0];
    const float* w_qkv = (const float*)d_in[1];
    const float* w_out = (const float*)d_in[2];
    const float* b_out = (const float*)d_in[3];
    float* out = (float*)d_out;

    uint16_t *xh, *wq, *qkvh, *aohi, *aolo, *woh;
    cudaGetSymbolAddress((void**)&xh,  g_x_h);
    cudaGetSymbolAddress((void**)&wq,  g_wqkv_h);
    cudaGetSymbolAddress((void**)&qkvh, g_qkv_h);
    cudaGetSymbolAddress((void**)&aohi, g_ao_hi);
    cudaGetSymbolAddress((void**)&aolo, g_ao_lo);
    cudaGetSymbolAddress((void**)&woh, g_wout_h);

    constexpr int G1_SMEM = 2 * 2 * TILE_SMB;   // 73728  (single-pass)
    constexpr int G2_SMEM = 2 * 3 * TILE_SMB;   // 110592 (2-pass)
    cudaFuncSetAttribute((gemm_mma<1, false, true>),
                         cudaFuncAttributeMaxDynamicSharedMemorySize, G1_SMEM);
    cudaFuncSetAttribute((gemm_mma<2, true, false>),
                         cudaFuncAttributeMaxDynamicSharedMemorySize, G2_SMEM);
    cudaFuncSetAttribute(flash_attn_mma,
                         cudaFuncAttributeMaxDynamicSharedMemorySize, ATT_SMEM);

    // 1) pack inputs: x, w_qkv, w_out -> fp16 single
    {
        int n4 = M_TOK * D_MODEL / 4;
        pack_h16<<<(n4 + 255) / 256, 256>>>(x, xh, n4);
        n4 = QKV_LD * D_MODEL / 4;
        pack_h16<<<(n4 + 255) / 256, 256>>>(w_qkv, wq, n4);
        n4 = D_MODEL * D_MODEL / 4;
        pack_h16<<<(n4 + 255) / 256, 256>>>(w_out, woh, n4);
    }

    // 2) QKV projection (single-pass fp16) -> qkv fp16
    //    gemm_mma<PASSES,HAS_BIAS,SPLIT_OUT>(Ahi, Alo, Bhi, bias, C, Chi, M, N, K)
    gemm_mma<1, false, true><<<dim3(QKV_LD / 128, M_TOK / 128), 256, G1_SMEM>>>(
        xh, nullptr, wq, nullptr, nullptr, qkvh, M_TOK, QKV_LD, D_MODEL);

    // 3) causal flash attention -> ao fp16 hi/lo
    flash_attn_mma<<<dim3(S_LEN / 128, 2 * H_NUM), 256, ATT_SMEM>>>(qkvh, aohi, aolo);

    // 4) output projection (2-pass fp16) + bias -> fp32 out
    gemm_mma<2, true, false><<<dim3(D_MODEL / 128, M_TOK / 128), 256, G2_SMEM>>>(
        aohi, aolo, woh, b_out, out, nullptr, M_TOK, D_MODEL, D_MODEL);
}

// round 14
// speedup vs baseline: 6.0281x; 1.1181x over previous
#include <cuda_runtime.h>
#include <cuda_fp16.h>
#include <cstdint>
#include <cstddef>

#define S_LEN   2048
#define D_MODEL 1024
#define H_NUM   16
#define DH      64
#define M_TOK   4096
#define QKV_LD  3072

// ---------------------------------------------------------------------------
// Device scratch (fp16 words)
// ---------------------------------------------------------------------------
__device__ uint16_t g_x_h   [(size_t)M_TOK * D_MODEL];
__device__ uint16_t g_wqkv_h[(size_t)QKV_LD * D_MODEL];
__device__ uint16_t g_qkv_h [(size_t)M_TOK * QKV_LD];
__device__ uint16_t g_ao_h  [(size_t)M_TOK * D_MODEL];
__device__ uint16_t g_wout_h[(size_t)D_MODEL * D_MODEL];

// ---------------------------------------------------------------------------
// PTX helpers
// ---------------------------------------------------------------------------
__device__ __forceinline__ uint32_t smem_u32(const void* p) {
    uint32_t a;
    asm("{ .reg .u64 t; cvta.to.shared.u64 t, %1; cvt.u32.u64 %0, t; }" : "=r"(a) : "l"(p));
    return a;
}
__device__ __forceinline__ void cp_async16(uint32_t dst, const void* src) {
    asm volatile("cp.async.cg.shared.global [%0], [%1], 16;" :: "r"(dst), "l"(src));
}
__device__ __forceinline__ void cp_commit() {
    asm volatile("cp.async.commit_group;" ::: "memory");
}
template <int N>
__device__ __forceinline__ void cp_wait() {
    asm volatile("cp.async.wait_group %0;" :: "n"(N) : "memory");
}
__device__ __forceinline__ void ldsm_x4(uint32_t& r0, uint32_t& r1, uint32_t& r2,
                                        uint32_t& r3, uint32_t a) {
    asm volatile("ldmatrix.sync.aligned.m8n8.x4.shared.b16 {%0,%1,%2,%3}, [%4];"
                 : "=r"(r0), "=r"(r1), "=r"(r2), "=r"(r3) : "r"(a));
}
__device__ __forceinline__ void ldsm_x4_t(uint32_t& r0, uint32_t& r1, uint32_t& r2,
                                          uint32_t& r3, uint32_t a) {
    asm volatile("ldmatrix.sync.aligned.m8n8.x4.trans.shared.b16 {%0,%1,%2,%3}, [%4];"
                 : "=r"(r0), "=r"(r1), "=r"(r2), "=r"(r3) : "r"(a));
}
__device__ __forceinline__ void mma_f16(float* d, const uint32_t* a, const uint32_t* b) {
    asm volatile("mma.sync.aligned.m16n8k16.row.col.f32.f16.f16.f32 "
                 "{%0,%1,%2,%3}, {%4,%5,%6,%7}, {%8,%9}, {%0,%1,%2,%3};"
                 : "+f"(d[0]), "+f"(d[1]), "+f"(d[2]), "+f"(d[3])
                 : "r"(a[0]), "r"(a[1]), "r"(a[2]), "r"(a[3]), "r"(b[0]), "r"(b[1]));
}
__device__ __forceinline__ void split_pair_h(float a, float b, uint32_t& hi, uint32_t& lo) {
    __half ha = __float2half_rn(a), hb = __float2half_rn(b);
    hi = (uint32_t)__half_as_ushort(ha) | ((uint32_t)__half_as_ushort(hb) << 16);
    lo = (uint32_t)__half_as_ushort(__float2half_rn(a - __half2float(ha))) |
         ((uint32_t)__half_as_ushort(__float2half_rn(b - __half2float(hb))) << 16);
}
__device__ __forceinline__ uint32_t pack_pair_h(float a, float b) {
    return (uint32_t)__half_as_ushort(__float2half_rn(a)) |
           ((uint32_t)__half_as_ushort(__float2half_rn(b)) << 16);
}

// ---------------------------------------------------------------------------
// Packer
// ---------------------------------------------------------------------------
__global__ __launch_bounds__(256) void pack_h16(
    const float* __restrict__ in, uint16_t* __restrict__ hi, int n4)
{
    int i = blockIdx.x * 256 + threadIdx.x;
    if (i >= n4) return;
    float4 v = reinterpret_cast<const float4*>(in)[i];
    reinterpret_cast<uint2*>(hi)[i] =
        make_uint2(pack_pair_h(v.x, v.y), pack_pair_h(v.z, v.w));
}

// ---------------------------------------------------------------------------
// HMMA fp16 GEMM: C[M,N] = A @ Bhi^T (+bias).
// PASSES=1: A single (2 smem tiles/stage). PASSES=2: A = Ahi+Alo (3 tiles).
// CTA 128x128, BK=64, 8 warps (2x4), 2-stage cp.async pipeline.
// ---------------------------------------------------------------------------
#define BK        64
#define PAD_K     72
#define TILE_SMB  (128 * PAD_K * 2)      // 18432 B

template <int PASSES, bool HAS_BIAS, bool SPLIT_OUT>
__global__ __launch_bounds__(256) void gemm_mma(
    const uint16_t* __restrict__ Ahi, const uint16_t* __restrict__ Alo,
    const uint16_t* __restrict__ Bhi,
    const float* __restrict__ bias, float* __restrict__ C,
    uint16_t* __restrict__ Chi,
    int M, int N, int K)
{
    constexpr int NT = PASSES + 1;
    constexpr int BTILE = PASSES;
    constexpr int STAGE_B = NT * TILE_SMB;

    extern __shared__ char smem[];
    const uint32_t sb = smem_u32(smem);
    const int tid = threadIdx.x;
    const int wid = tid >> 5;
    const int lane = tid & 31;
    const int bm = blockIdx.y * 128;
    const int bn = blockIdx.x * 128;
    const int wm = wid >> 2;
    const int wn = wid & 3;
    const int nk = K / BK;

    const uint16_t* gA0 = Ahi + (size_t)bm * K;
    const uint16_t* gA1 = (PASSES == 2) ? (Alo + (size_t)bm * K) : nullptr;
    const uint16_t* gB0 = Bhi + (size_t)bn * K;

    auto load_tile = [&](uint32_t tb, const uint16_t* g, int k0) {
#pragma unroll
        for (int it = 0; it < 4; ++it) {
            int c = tid + it * 256;
            int r = c >> 3, col = (c & 7) * 8;
            cp_async16(tb + r * (PAD_K * 2) + col * 2, g + (size_t)r * K + k0 + col);
        }
    };
    auto load_stage = [&](int s, int k0) {
        uint32_t base = sb + s * STAGE_B;
        load_tile(base + 0 * TILE_SMB, gA0, k0);
        if (PASSES == 2) load_tile(base + 1 * TILE_SMB, gA1, k0);
        load_tile(base + BTILE * TILE_SMB, gB0, k0);
        cp_commit();
    };

    float acc[4][4][4];
#pragma unroll
    for (int mt = 0; mt < 4; ++mt)
#pragma unroll
        for (int nt = 0; nt < 4; ++nt)
#pragma unroll
            for (int e = 0; e < 4; ++e) acc[mt][nt][e] = 0.f;

    const int lrow8 = lane & 7;
    const int lq    = lane >> 3;
    const int a_roff = lrow8 + (lq & 1) * 8;
    const int a_coff = (lq >> 1) * 8;
    const int b_noff = lrow8 + (lq >> 1) * 8;
    const int b_coff = (lq & 1) * 8;

    load_stage(0, 0);

    for (int i = 0; i < nk; ++i) {
        const int s = i & 1;
        if (i + 1 < nk) { load_stage(s ^ 1, (i + 1) * BK); cp_wait<1>(); }
        else            { cp_wait<0>(); }
        __syncthreads();

        const uint32_t stg = sb + s * STAGE_B;
#pragma unroll
        for (int kk = 0; kk < BK; kk += 16) {
            uint32_t bh[4][2];
#pragma unroll
            for (int ntp = 0; ntp < 2; ++ntp) {
                int nidx = wn * 32 + ntp * 16 + b_noff;
                int cidx = kk + b_coff;
                ldsm_x4(bh[2 * ntp][0], bh[2 * ntp][1], bh[2 * ntp + 1][0], bh[2 * ntp + 1][1],
                        stg + BTILE * TILE_SMB + (nidx * PAD_K + cidx) * 2);
            }
#pragma unroll
            for (int mt = 0; mt < 4; ++mt) {
                int midx = wm * 64 + mt * 16 + a_roff;
                int cidx = kk + a_coff;
                uint32_t ah[4];
                ldsm_x4(ah[0], ah[1], ah[2], ah[3], stg + 0 * TILE_SMB + (midx * PAD_K + cidx) * 2);
                uint32_t al[4];
                if (PASSES == 2)
                    ldsm_x4(al[0], al[1], al[2], al[3],
                            stg + 1 * TILE_SMB + (midx * PAD_K + cidx) * 2);
#pragma unroll
                for (int nt = 0; nt < 4; ++nt) {
                    mma_f16(acc[mt][nt], ah, bh[nt]);
                    if (PASSES == 2) mma_f16(acc[mt][nt], al, bh[nt]);
                }
            }
        }
        __syncthreads();
    }

#pragma unroll
    for (int mt = 0; mt < 4; ++mt) {
#pragma unroll
        for (int nt = 0; nt < 4; ++nt) {
            int r = bm + wm * 64 + mt * 16 + (lane >> 2);
            int c = bn + wn * 32 + nt * 8 + (lane & 3) * 2;
            if (SPLIT_OUT) {
                *reinterpret_cast<uint32_t*>(&Chi[(size_t)r * N + c]) =
                    pack_pair_h(acc[mt][nt][0], acc[mt][nt][1]);
                *reinterpret_cast<uint32_t*>(&Chi[(size_t)(r + 8) * N + c]) =
                    pack_pair_h(acc[mt][nt][2], acc[mt][nt][3]);
            } else {
                float b0 = 0.f, b1 = 0.f;
                if (HAS_BIAS) { b0 = bias[c]; b1 = bias[c + 1]; }
                *reinterpret_cast<float2*>(&C[(size_t)r * N + c]) =
                    make_float2(acc[mt][nt][0] + b0, acc[mt][nt][1] + b1);
                *reinterpret_cast<float2*>(&C[(size_t)(r + 8) * N + c]) =
                    make_float2(acc[mt][nt][2] + b0, acc[mt][nt][3] + b1);
            }
        }
    }
}

// ---------------------------------------------------------------------------
// fp16 causal flash attention, 32 q-rows per warp.
// CTA: 128 q-rows x (b,h), 4 warps (block=128). Bc=64. 3-stage KV pipeline.
// Each warp: 2 m-tiles of 16 rows; K/V fragments loaded once, used twice.
// S = Q·K^T, O += P·V, all single-pass fp16. Output ao single fp16.
// ---------------------------------------------------------------------------
#define ATT_PAD    72
#define ATT_ROWB   (ATT_PAD * 2)          // 144 B
#define KV_TILE_B  (64 * ATT_ROWB)        // 9216
#define ATT_STAGE  (2 * KV_TILE_B)        // 18432 (K, V)
#define ATT_SMEM   (3 * ATT_STAGE)        // 55296

__global__ __launch_bounds__(128) void flash_attn_mma(
    const uint16_t* __restrict__ qkv_h, uint16_t* __restrict__ ao_h)
{
    extern __shared__ char smem[];
    const uint32_t sb = smem_u32(smem);
    const int tid = threadIdx.x, wid = tid >> 5, lane = tid & 31;
    const int qb = 15 - blockIdx.x;
    const int bh = blockIdx.y;
    const int b = bh >> 4, h = bh & 15;
    const size_t tok0 = (size_t)b * S_LEN;

    const int lrow8 = lane & 7, lq = lane >> 3;
    const int a_roff = lrow8 + (lq & 1) * 8;
    const int a_coff = (lq >> 1) * 8;
    const int b_noff = lrow8 + (lq >> 1) * 8;
    const int b_coff = (lq & 1) * 8;
    const int v_roff = (lane & 7) + ((lane >> 3) & 1) * 8;
    const int v_coff = (lane >> 4) * 8;

    // ---- stage Q (128 rows x 64) into smem; pull both m-tiles to regs
    {
        const size_t qrow0 = tok0 + (size_t)qb * 128;
#pragma unroll
        for (int it = 0; it < 8; ++it) {
            int c = tid + it * 128;         // 0..1023
            int r = c >> 3, col = (c & 7) * 8;
            cp_async16(sb + r * ATT_ROWB + col * 2,
                       qkv_h + (qrow0 + r) * QKV_LD + h * 192 + col);
        }
        cp_commit();
        cp_wait<0>();
        __syncthreads();
    }
    uint32_t qh[2][4][4];
#pragma unroll
    for (int mt = 0; mt < 2; ++mt)
#pragma unroll
        for (int j = 0; j < 4; ++j) {
            int rr = wid * 32 + mt * 16 + a_roff;
            int cc = j * 16 + a_coff;
            ldsm_x4(qh[mt][j][0], qh[mt][j][1], qh[mt][j][2], qh[mt][j][3],
                    sb + rr * ATT_ROWB + cc * 2);
        }
    __syncthreads();

    // KV stage loader: K tile + V tile (each 64 x 64)
    auto load_kv = [&](int s, int kb) {
        uint32_t base = sb + s * ATT_STAGE;
        const size_t krow0 = tok0 + (size_t)kb * 64;
        const int koff = h * 192 + 64, voff = h * 192 + 128;
#pragma unroll
        for (int it = 0; it < 4; ++it) {
            int c = tid + it * 128;         // 0..511
            int r = c >> 3, col = (c & 7) * 8;
            const size_t go = (krow0 + r) * QKV_LD + col;
            cp_async16(base + r * ATT_ROWB + col * 2, qkv_h + go + koff);
            cp_async16(base + KV_TILE_B + r * ATT_ROWB + col * 2, qkv_h + go + voff);
        }
        cp_commit();
    };

    float o[2][8][4];
#pragma unroll
    for (int mt = 0; mt < 2; ++mt)
#pragma unroll
        for (int nt = 0; nt < 8; ++nt)
#pragma unroll
            for (int e = 0; e < 4; ++e) o[mt][nt][e] = 0.f;
    float mx[2][2], lsum[2][2];
#pragma unroll
    for (int mt = 0; mt < 2; ++mt) {
        mx[mt][0] = -1e30f; mx[mt][1] = -1e30f;
        lsum[mt][0] = 0.f;  lsum[mt][1] = 0.f;
    }

    const int nkb = 2 * qb + 2;
    load_kv(0, 0);
    if (nkb > 1) load_kv(1, 1);

    for (int kb = 0; kb < nkb; ++kb) {
        const int s = kb % 3;
        if (kb + 2 < nkb) { load_kv((kb + 2) % 3, kb + 2); cp_wait<2>(); }
        else if (kb + 1 < nkb) { cp_wait<1>(); }
        else { cp_wait<0>(); }
        __syncthreads();
        const uint32_t kbase = sb + s * ATT_STAGE;

        // ---- S = Q @ K^T for both m-tiles (K frags loaded once)
        float sc[2][8][4];
#pragma unroll
        for (int mt = 0; mt < 2; ++mt)
#pragma unroll
            for (int nt = 0; nt < 8; ++nt)
#pragma unroll
                for (int e = 0; e < 4; ++e) sc[mt][nt][e] = 0.f;

#pragma unroll
        for (int j = 0; j < 4; ++j) {
            uint32_t kf[8][2];
#pragma unroll
            for (int p = 0; p < 4; ++p) {
                int nn = p * 16 + b_noff;
                int cc = j * 16 + b_coff;
                ldsm_x4(kf[2 * p][0], kf[2 * p][1], kf[2 * p + 1][0], kf[2 * p + 1][1],
                        kbase + nn * ATT_ROWB + cc * 2);
            }
#pragma unroll
            for (int mt = 0; mt < 2; ++mt)
#pragma unroll
                for (int nt = 0; nt < 8; ++nt)
                    mma_f16(sc[mt][nt], qh[mt][j], kf[nt]);
        }

#pragma unroll
        for (int mt = 0; mt < 2; ++mt)
#pragma unroll
            for (int nt = 0; nt < 8; ++nt)
#pragma unroll
                for (int e = 0; e < 4; ++e) sc[mt][nt][e] *= 0.125f;

        if (kb >= 2 * qb) {
#pragma unroll
            for (int mt = 0; mt < 2; ++mt) {
                const int gr0 = qb * 128 + wid * 32 + mt * 16 + (lane >> 2);
#pragma unroll
                for (int nt = 0; nt < 8; ++nt) {
                    int gc = kb * 64 + nt * 8 + (lane & 3) * 2;
                    if (gc     > gr0)     sc[mt][nt][0] = -1e30f;
                    if (gc + 1 > gr0)     sc[mt][nt][1] = -1e30f;
                    if (gc     > gr0 + 8) sc[mt][nt][2] = -1e30f;
                    if (gc + 1 > gr0 + 8) sc[mt][nt][3] = -1e30f;
                }
            }
        }

        // ---- online softmax per m-tile
#pragma unroll
        for (int mt = 0; mt < 2; ++mt) {
            float mx0 = -1e30f, mx1 = -1e30f;
#pragma unroll
            for (int nt = 0; nt < 8; ++nt) {
                mx0 = fmaxf(mx0, fmaxf(sc[mt][nt][0], sc[mt][nt][1]));
                mx1 = fmaxf(mx1, fmaxf(sc[mt][nt][2], sc[mt][nt][3]));
            }
#pragma unroll
            for (int w = 1; w < 4; w <<= 1) {
                mx0 = fmaxf(mx0, __shfl_xor_sync(0xffffffffu, mx0, w));
                mx1 = fmaxf(mx1, __shfl_xor_sync(0xffffffffu, mx1, w));
            }
            float mn0 = fmaxf(mx[mt][0], mx0), mn1 = fmaxf(mx[mt][1], mx1);
            float c0 = __expf(mx[mt][0] - mn0), c1 = __expf(mx[mt][1] - mn1);
            mx[mt][0] = mn0; mx[mt][1] = mn1;
            float rs0 = 0.f, rs1 = 0.f;
#pragma unroll
            for (int nt = 0; nt < 8; ++nt) {
                sc[mt][nt][0] = __expf(sc[mt][nt][0] - mn0);
                sc[mt][nt][1] = __expf(sc[mt][nt][1] - mn0);
                sc[mt][nt][2] = __expf(sc[mt][nt][2] - mn1);
                sc[mt][nt][3] = __expf(sc[mt][nt][3] - mn1);
                rs0 += sc[mt][nt][0] + sc[mt][nt][1];
                rs1 += sc[mt][nt][2] + sc[mt][nt][3];
            }
#pragma unroll
            for (int w = 1; w < 4; w <<= 1) {
                rs0 += __shfl_xor_sync(0xffffffffu, rs0, w);
                rs1 += __shfl_xor_sync(0xffffffffu, rs1, w);
            }
            lsum[mt][0] = lsum[mt][0] * c0 + rs0;
            lsum[mt][1] = lsum[mt][1] * c1 + rs1;
#pragma unroll
            for (int nt = 0; nt < 8; ++nt) {
                o[mt][nt][0] *= c0; o[mt][nt][1] *= c0;
                o[mt][nt][2] *= c1; o[mt][nt][3] *= c1;
            }
        }

        // ---- O += P @ V (V frags loaded once, used for both m-tiles)
#pragma unroll
        for (int j = 0; j < 4; ++j) {
            uint32_t ph[2][4];
#pragma unroll
            for (int mt = 0; mt < 2; ++mt) {
                ph[mt][0] = pack_pair_h(sc[mt][2 * j][0],     sc[mt][2 * j][1]);
                ph[mt][1] = pack_pair_h(sc[mt][2 * j][2],     sc[mt][2 * j][3]);
                ph[mt][2] = pack_pair_h(sc[mt][2 * j + 1][0], sc[mt][2 * j + 1][1]);
                ph[mt][3] = pack_pair_h(sc[mt][2 * j + 1][2], sc[mt][2 * j + 1][3]);
            }
            uint32_t vf[8][2];
#pragma unroll
            for (int p = 0; p < 4; ++p) {
                uint32_t ar = (j * 16 + v_roff) * ATT_ROWB + (p * 16 + v_coff) * 2;
                ldsm_x4_t(vf[2 * p][0], vf[2 * p][1], vf[2 * p + 1][0], vf[2 * p + 1][1],
                          kbase + KV_TILE_B + ar);
            }
#pragma unroll
            for (int mt = 0; mt < 2; ++mt)
#pragma unroll
                for (int nt = 0; nt < 8; ++nt)
                    mma_f16(o[mt][nt], ph[mt], vf[nt]);
        }
        __syncthreads();
    }

    // ---- normalize + write ao (single fp16)
#pragma unroll
    for (int mt = 0; mt < 2; ++mt) {
        const float inv0 = 1.f / lsum[mt][0], inv1 = 1.f / lsum[mt][1];
        const int gr0 = qb * 128 + wid * 32 + mt * 16 + (lane >> 2);
        const size_t row0 = (tok0 + gr0) * D_MODEL;
        const size_t row1 = (tok0 + gr0 + 8) * D_MODEL;
        const int colb = h * DH + (lane & 3) * 2;
#pragma unroll
        for (int nt = 0; nt < 8; ++nt) {
            int c = colb + nt * 8;
            *reinterpret_cast<uint32_t*>(&ao_h[row0 + c]) =
                pack_pair_h(o[mt][nt][0] * inv0, o[mt][nt][1] * inv0);
            *reinterpret_cast<uint32_t*>(&ao_h[row1 + c]) =
                pack_pair_h(o[mt][nt][2] * inv1, o[mt][nt][3] * inv1);
        }
    }
}

// ---------------------------------------------------------------------------
extern "C" void kernel_launch(void* const* d_in, const int* in_sizes, int n_in,
                              void* d_out, int out_size)
{
    (void)in_sizes; (void)n_in; (void)out_size;
    const float* x     = (const float*)d_in[0];
    const float* w_qkv = (const float*)d_in[1];
    const float* w_out = (const float*)d_in[2];
    const float* b_out = (const float*)d_in[3];
    float* out = (float*)d_out;

    uint16_t *xh, *wq, *qkvh, *aoh, *woh;
    cudaGetSymbolAddress((void**)&xh,  g_x_h);
    cudaGetSymbolAddress((void**)&wq,  g_wqkv_h);
    cudaGetSymbolAddress((void**)&qkvh, g_qkv_h);
    cudaGetSymbolAddress((void**)&aoh, g_ao_h);
    cudaGetSymbolAddress((void**)&woh, g_wout_h);

    constexpr int G1_SMEM = 2 * 2 * TILE_SMB;   // 73728 (single-pass)
    cudaFuncSetAttribute((gemm_mma<1, false, true>),
                         cudaFuncAttributeMaxDynamicSharedMemorySize, G1_SMEM);
    cudaFuncSetAttribute((gemm_mma<1, true, false>),
                         cudaFuncAttributeMaxDynamicSharedMemorySize, G1_SMEM);
    cudaFuncSetAttribute(flash_attn_mma,
                         cudaFuncAttributeMaxDynamicSharedMemorySize, ATT_SMEM);

    // 1) pack inputs -> fp16 single
    {
        int n4 = M_TOK * D_MODEL / 4;
        pack_h16<<<(n4 + 255) / 256, 256>>>(x, xh, n4);
        n4 = QKV_LD * D_MODEL / 4;
        pack_h16<<<(n4 + 255) / 256, 256>>>(w_qkv, wq, n4);
        n4 = D_MODEL * D_MODEL / 4;
        pack_h16<<<(n4 + 255) / 256, 256>>>(w_out, woh, n4);
    }

    // 2) QKV projection (single-pass fp16) -> qkv fp16
    //    gemm_mma<PASSES,HAS_BIAS,SPLIT_OUT>(Ahi, Alo, Bhi, bias, C, Chi, M, N, K)
    gemm_mma<1, false, true><<<dim3(QKV_LD / 128, M_TOK / 128), 256, G1_SMEM>>>(
        xh, nullptr, wq, nullptr, nullptr, qkvh, M_TOK, QKV_LD, D_MODEL);

    // 3) causal flash attention -> ao fp16 (4 warps, 32 rows/warp)
    flash_attn_mma<<<dim3(S_LEN / 128, 2 * H_NUM), 128, ATT_SMEM>>>(qkvh, aoh);

    // 4) output projection (single-pass fp16) + bias -> fp32 out
    gemm_mma<1, true, false><<<dim3(D_MODEL / 128, M_TOK / 128), 256, G1_SMEM>>>(
        aoh, nullptr, woh, b_out, out, nullptr, M_TOK, D_MODEL, D_MODEL);
}

// round 15
// speedup vs baseline: 6.2721x; 1.0405x over previous
#include <cuda_runtime.h>
#include <cuda_fp16.h>
#include <cstdint>
#include <cstddef>

#define S_LEN   2048
#define D_MODEL 1024
#define H_NUM   16
#define DH      64
#define M_TOK   4096
#define QKV_LD  3072

// ---------------------------------------------------------------------------
// Device scratch (fp16 words)
// ---------------------------------------------------------------------------
__device__ uint16_t g_x_h   [(size_t)M_TOK * D_MODEL];
__device__ uint16_t g_wqkv_h[(size_t)QKV_LD * D_MODEL];
__device__ uint16_t g_qkv_h [(size_t)M_TOK * QKV_LD];
__device__ uint16_t g_ao_h  [(size_t)M_TOK * D_MODEL];
__device__ uint16_t g_wout_h[(size_t)D_MODEL * D_MODEL];

// ---------------------------------------------------------------------------
// PTX helpers
// ---------------------------------------------------------------------------
__device__ __forceinline__ uint32_t smem_u32(const void* p) {
    uint32_t a;
    asm("{ .reg .u64 t; cvta.to.shared.u64 t, %1; cvt.u32.u64 %0, t; }" : "=r"(a) : "l"(p));
    return a;
}
__device__ __forceinline__ void cp_async16(uint32_t dst, const void* src) {
    asm volatile("cp.async.cg.shared.global [%0], [%1], 16;" :: "r"(dst), "l"(src));
}
__device__ __forceinline__ void cp_commit() {
    asm volatile("cp.async.commit_group;" ::: "memory");
}
template <int N>
__device__ __forceinline__ void cp_wait() {
    asm volatile("cp.async.wait_group %0;" :: "n"(N) : "memory");
}
__device__ __forceinline__ void ldsm_x4(uint32_t& r0, uint32_t& r1, uint32_t& r2,
                                        uint32_t& r3, uint32_t a) {
    asm volatile("ldmatrix.sync.aligned.m8n8.x4.shared.b16 {%0,%1,%2,%3}, [%4];"
                 : "=r"(r0), "=r"(r1), "=r"(r2), "=r"(r3) : "r"(a));
}
__device__ __forceinline__ void ldsm_x4_t(uint32_t& r0, uint32_t& r1, uint32_t& r2,
                                          uint32_t& r3, uint32_t a) {
    asm volatile("ldmatrix.sync.aligned.m8n8.x4.trans.shared.b16 {%0,%1,%2,%3}, [%4];"
                 : "=r"(r0), "=r"(r1), "=r"(r2), "=r"(r3) : "r"(a));
}
__device__ __forceinline__ void mma_f16(float* d, const uint32_t* a, const uint32_t* b) {
    asm volatile("mma.sync.aligned.m16n8k16.row.col.f32.f16.f16.f32 "
                 "{%0,%1,%2,%3}, {%4,%5,%6,%7}, {%8,%9}, {%0,%1,%2,%3};"
                 : "+f"(d[0]), "+f"(d[1]), "+f"(d[2]), "+f"(d[3])
                 : "r"(a[0]), "r"(a[1]), "r"(a[2]), "r"(a[3]), "r"(b[0]), "r"(b[1]));
}
__device__ __forceinline__ uint32_t pack_pair_h(float a, float b) {
    return (uint32_t)__half_as_ushort(__float2half_rn(a)) |
           ((uint32_t)__half_as_ushort(__float2half_rn(b)) << 16);
}

// ---------------------------------------------------------------------------
// Packer
// ---------------------------------------------------------------------------
__global__ __launch_bounds__(256) void pack_h16(
    const float* __restrict__ in, uint16_t* __restrict__ hi, int n4)
{
    int i = blockIdx.x * 256 + threadIdx.x;
    if (i >= n4) return;
    float4 v = reinterpret_cast<const float4*>(in)[i];
    reinterpret_cast<uint2*>(hi)[i] =
        make_uint2(pack_pair_h(v.x, v.y), pack_pair_h(v.z, v.w));
}

// ---------------------------------------------------------------------------
// HMMA fp16 GEMM: C[M,N] = A @ B^T (+bias), single-pass fp16.
// CTA 128x128, BK=64, 4 warps (2x2), warp tile 64x64, 2-stage cp.async.
// smem: 2 stages x (A tile + B tile) x 18432 B = 73728 B.
// ldsm:mma per kk = 8:32 (was 6:16) -> per-CTA smem traffic x2/3.
// ---------------------------------------------------------------------------
#define BK        64
#define PAD_K     72
#define TILE_SMB  (128 * PAD_K * 2)      // 18432 B
#define STAGE_B   (2 * TILE_SMB)         // 36864 B
#define G_SMEM    (2 * STAGE_B)          // 73728 B

template <bool HAS_BIAS, bool SPLIT_OUT>
__global__ __launch_bounds__(128) void gemm_mma(
    const uint16_t* __restrict__ A, const uint16_t* __restrict__ B,
    const float* __restrict__ bias, float* __restrict__ C,
    uint16_t* __restrict__ Ch,
    int M, int N, int K)
{
    extern __shared__ char smem[];
    const uint32_t sb = smem_u32(smem);
    const int tid = threadIdx.x;
    const int wid = tid >> 5;
    const int lane = tid & 31;
    const int bm = blockIdx.y * 128;
    const int bn = blockIdx.x * 128;
    const int wm = wid >> 1;             // 0..1 -> rows wm*64
    const int wn = wid & 1;              // 0..1 -> cols wn*64
    const int nk = K / BK;

    const uint16_t* gA = A + (size_t)bm * K;
    const uint16_t* gB = B + (size_t)bn * K;

    auto load_tile = [&](uint32_t tb, const uint16_t* g, int k0) {
#pragma unroll
        for (int it = 0; it < 8; ++it) {
            int c = tid + it * 128;          // 0..1023
            int r = c >> 3, col = (c & 7) * 8;
            cp_async16(tb + r * (PAD_K * 2) + col * 2, g + (size_t)r * K + k0 + col);
        }
    };
    auto load_stage = [&](int s, int k0) {
        uint32_t base = sb + s * STAGE_B;
        load_tile(base, gA, k0);
        load_tile(base + TILE_SMB, gB, k0);
        cp_commit();
    };

    float acc[4][8][4];
#pragma unroll
    for (int mt = 0; mt < 4; ++mt)
#pragma unroll
        for (int nt = 0; nt < 8; ++nt)
#pragma unroll
            for (int e = 0; e < 4; ++e) acc[mt][nt][e] = 0.f;

    const int lrow8 = lane & 7;
    const int lq    = lane >> 3;
    const int a_roff = lrow8 + (lq & 1) * 8;
    const int a_coff = (lq >> 1) * 8;
    const int b_noff = lrow8 + (lq >> 1) * 8;
    const int b_coff = (lq & 1) * 8;

    load_stage(0, 0);

    for (int i = 0; i < nk; ++i) {
        const int s = i & 1;
        if (i + 1 < nk) { load_stage(s ^ 1, (i + 1) * BK); cp_wait<1>(); }
        else            { cp_wait<0>(); }
        __syncthreads();

        const uint32_t stg = sb + s * STAGE_B;
#pragma unroll
        for (int kk = 0; kk < BK; kk += 16) {
            uint32_t bh[8][2];
#pragma unroll
            for (int ntp = 0; ntp < 4; ++ntp) {
                int nidx = wn * 64 + ntp * 16 + b_noff;
                int cidx = kk + b_coff;
                ldsm_x4(bh[2 * ntp][0], bh[2 * ntp][1], bh[2 * ntp + 1][0], bh[2 * ntp + 1][1],
                        stg + TILE_SMB + (nidx * PAD_K + cidx) * 2);
            }
#pragma unroll
            for (int mt = 0; mt < 4; ++mt) {
                int midx = wm * 64 + mt * 16 + a_roff;
                int cidx = kk + a_coff;
                uint32_t ah[4];
                ldsm_x4(ah[0], ah[1], ah[2], ah[3], stg + (midx * PAD_K + cidx) * 2);
#pragma unroll
                for (int nt = 0; nt < 8; ++nt)
                    mma_f16(acc[mt][nt], ah, bh[nt]);
            }
        }
        __syncthreads();
    }

#pragma unroll
    for (int mt = 0; mt < 4; ++mt) {
#pragma unroll
        for (int nt = 0; nt < 8; ++nt) {
            int r = bm + wm * 64 + mt * 16 + (lane >> 2);
            int c = bn + wn * 64 + nt * 8 + (lane & 3) * 2;
            if (SPLIT_OUT) {
                *reinterpret_cast<uint32_t*>(&Ch[(size_t)r * N + c]) =
                    pack_pair_h(acc[mt][nt][0], acc[mt][nt][1]);
                *reinterpret_cast<uint32_t*>(&Ch[(size_t)(r + 8) * N + c]) =
                    pack_pair_h(acc[mt][nt][2], acc[mt][nt][3]);
            } else {
                float b0 = 0.f, b1 = 0.f;
                if (HAS_BIAS) { b0 = bias[c]; b1 = bias[c + 1]; }
                *reinterpret_cast<float2*>(&C[(size_t)r * N + c]) =
                    make_float2(acc[mt][nt][0] + b0, acc[mt][nt][1] + b1);
                *reinterpret_cast<float2*>(&C[(size_t)(r + 8) * N + c]) =
                    make_float2(acc[mt][nt][2] + b0, acc[mt][nt][3] + b1);
            }
        }
    }
}

// ---------------------------------------------------------------------------
// fp16 causal flash attention, 32 q-rows per warp (unchanged from R14).
// CTA: 128 q-rows x (b,h), 4 warps. Bc=64. 3-stage KV pipeline.
// ---------------------------------------------------------------------------
#define ATT_PAD    72
#define ATT_ROWB   (ATT_PAD * 2)          // 144 B
#define KV_TILE_B  (64 * ATT_ROWB)        // 9216
#define ATT_STAGE  (2 * KV_TILE_B)        // 18432 (K, V)
#define ATT_SMEM   (3 * ATT_STAGE)        // 55296

__global__ __launch_bounds__(128) void flash_attn_mma(
    const uint16_t* __restrict__ qkv_h, uint16_t* __restrict__ ao_h)
{
    extern __shared__ char smem[];
    const uint32_t sb = smem_u32(smem);
    const int tid = threadIdx.x, wid = tid >> 5, lane = tid & 31;
    const int qb = 15 - blockIdx.x;
    const int bh = blockIdx.y;
    const int b = bh >> 4, h = bh & 15;
    const size_t tok0 = (size_t)b * S_LEN;

    const int lrow8 = lane & 7, lq = lane >> 3;
    const int a_roff = lrow8 + (lq & 1) * 8;
    const int a_coff = (lq >> 1) * 8;
    const int b_noff = lrow8 + (lq >> 1) * 8;
    const int b_coff = (lq & 1) * 8;
    const int v_roff = (lane & 7) + ((lane >> 3) & 1) * 8;
    const int v_coff = (lane >> 4) * 8;

    // ---- stage Q (128 rows x 64) into smem; pull both m-tiles to regs
    {
        const size_t qrow0 = tok0 + (size_t)qb * 128;
#pragma unroll
        for (int it = 0; it < 8; ++it) {
            int c = tid + it * 128;
            int r = c >> 3, col = (c & 7) * 8;
            cp_async16(sb + r * ATT_ROWB + col * 2,
                       qkv_h + (qrow0 + r) * QKV_LD + h * 192 + col);
        }
        cp_commit();
        cp_wait<0>();
        __syncthreads();
    }
    uint32_t qh[2][4][4];
#pragma unroll
    for (int mt = 0; mt < 2; ++mt)
#pragma unroll
        for (int j = 0; j < 4; ++j) {
            int rr = wid * 32 + mt * 16 + a_roff;
            int cc = j * 16 + a_coff;
            ldsm_x4(qh[mt][j][0], qh[mt][j][1], qh[mt][j][2], qh[mt][j][3],
                    sb + rr * ATT_ROWB + cc * 2);
        }
    __syncthreads();

    auto load_kv = [&](int s, int kb) {
        uint32_t base = sb + s * ATT_STAGE;
        const size_t krow0 = tok0 + (size_t)kb * 64;
        const int koff = h * 192 + 64, voff = h * 192 + 128;
#pragma unroll
        for (int it = 0; it < 4; ++it) {
            int c = tid + it * 128;
            int r = c >> 3, col = (c & 7) * 8;
            const size_t go = (krow0 + r) * QKV_LD + col;
            cp_async16(base + r * ATT_ROWB + col * 2, qkv_h + go + koff);
            cp_async16(base + KV_TILE_B + r * ATT_ROWB + col * 2, qkv_h + go + voff);
        }
        cp_commit();
    };

    float o[2][8][4];
#pragma unroll
    for (int mt = 0; mt < 2; ++mt)
#pragma unroll
        for (int nt = 0; nt < 8; ++nt)
#pragma unroll
            for (int e = 0; e < 4; ++e) o[mt][nt][e] = 0.f;
    float mx[2][2], lsum[2][2];
#pragma unroll
    for (int mt = 0; mt < 2; ++mt) {
        mx[mt][0] = -1e30f; mx[mt][1] = -1e30f;
        lsum[mt][0] = 0.f;  lsum[mt][1] = 0.f;
    }

    const int nkb = 2 * qb + 2;
    load_kv(0, 0);
    if (nkb > 1) load_kv(1, 1);

    for (int kb = 0; kb < nkb; ++kb) {
        const int s = kb % 3;
        if (kb + 2 < nkb) { load_kv((kb + 2) % 3, kb + 2); cp_wait<2>(); }
        else if (kb + 1 < nkb) { cp_wait<1>(); }
        else { cp_wait<0>(); }
        __syncthreads();
        const uint32_t kbase = sb + s * ATT_STAGE;

        float sc[2][8][4];
#pragma unroll
        for (int mt = 0; mt < 2; ++mt)
#pragma unroll
            for (int nt = 0; nt < 8; ++nt)
#pragma unroll
                for (int e = 0; e < 4; ++e) sc[mt][nt][e] = 0.f;

#pragma unroll
        for (int j = 0; j < 4; ++j) {
            uint32_t kf[8][2];
#pragma unroll
            for (int p = 0; p < 4; ++p) {
                int nn = p * 16 + b_noff;
                int cc = j * 16 + b_coff;
                ldsm_x4(kf[2 * p][0], kf[2 * p][1], kf[2 * p + 1][0], kf[2 * p + 1][1],
                        kbase + nn * ATT_ROWB + cc * 2);
            }
#pragma unroll
            for (int mt = 0; mt < 2; ++mt)
#pragma unroll
                for (int nt = 0; nt < 8; ++nt)
                    mma_f16(sc[mt][nt], qh[mt][j], kf[nt]);
        }

#pragma unroll
        for (int mt = 0; mt < 2; ++mt)
#pragma unroll
            for (int nt = 0; nt < 8; ++nt)
#pragma unroll
                for (int e = 0; e < 4; ++e) sc[mt][nt][e] *= 0.125f;

        if (kb >= 2 * qb) {
#pragma unroll
            for (int mt = 0; mt < 2; ++mt) {
                const int gr0 = qb * 128 + wid * 32 + mt * 16 + (lane >> 2);
#pragma unroll
                for (int nt = 0; nt < 8; ++nt) {
                    int gc = kb * 64 + nt * 8 + (lane & 3) * 2;
                    if (gc     > gr0)     sc[mt][nt][0] = -1e30f;
                    if (gc + 1 > gr0)     sc[mt][nt][1] = -1e30f;
                    if (gc     > gr0 + 8) sc[mt][nt][2] = -1e30f;
                    if (gc + 1 > gr0 + 8) sc[mt][nt][3] = -1e30f;
                }
            }
        }

#pragma unroll
        for (int mt = 0; mt < 2; ++mt) {
            float mx0 = -1e30f, mx1 = -1e30f;
#pragma unroll
            for (int nt = 0; nt < 8; ++nt) {
                mx0 = fmaxf(mx0, fmaxf(sc[mt][nt][0], sc[mt][nt][1]));
                mx1 = fmaxf(mx1, fmaxf(sc[mt][nt][2], sc[mt][nt][3]));
            }
#pragma unroll
            for (int w = 1; w < 4; w <<= 1) {
                mx0 = fmaxf(mx0, __shfl_xor_sync(0xffffffffu, mx0, w));
                mx1 = fmaxf(mx1, __shfl_xor_sync(0xffffffffu, mx1, w));
            }
            float mn0 = fmaxf(mx[mt][0], mx0), mn1 = fmaxf(mx[mt][1], mx1);
            float c0 = __expf(mx[mt][0] - mn0), c1 = __expf(mx[mt][1] - mn1);
            mx[mt][0] = mn0; mx[mt][1] = mn1;
            float rs0 = 0.f, rs1 = 0.f;
#pragma unroll
            for (int nt = 0; nt < 8; ++nt) {
                sc[mt][nt][0] = __expf(sc[mt][nt][0] - mn0);
                sc[mt][nt][1] = __expf(sc[mt][nt][1] - mn0);
                sc[mt][nt][2] = __expf(sc[mt][nt][2] - mn1);
                sc[mt][nt][3] = __expf(sc[mt][nt][3] - mn1);
                rs0 += sc[mt][nt][0] + sc[mt][nt][1];
                rs1 += sc[mt][nt][2] + sc[mt][nt][3];
            }
#pragma unroll
            for (int w = 1; w < 4; w <<= 1) {
                rs0 += __shfl_xor_sync(0xffffffffu, rs0, w);
                rs1 += __shfl_xor_sync(0xffffffffu, rs1, w);
            }
            lsum[mt][0] = lsum[mt][0] * c0 + rs0;
            lsum[mt][1] = lsum[mt][1] * c1 + rs1;
#pragma unroll
            for (int nt = 0; nt < 8; ++nt) {
                o[mt][nt][0] *= c0; o[mt][nt][1] *= c0;
                o[mt][nt][2] *= c1; o[mt][nt][3] *= c1;
            }
        }

#pragma unroll
        for (int j = 0; j < 4; ++j) {
            uint32_t ph[2][4];
#pragma unroll
            for (int mt = 0; mt < 2; ++mt) {
                ph[mt][0] = pack_pair_h(sc[mt][2 * j][0],     sc[mt][2 * j][1]);
                ph[mt][1] = pack_pair_h(sc[mt][2 * j][2],     sc[mt][2 * j][3]);
                ph[mt][2] = pack_pair_h(sc[mt][2 * j + 1][0], sc[mt][2 * j + 1][1]);
                ph[mt][3] = pack_pair_h(sc[mt][2 * j + 1][2], sc[mt][2 * j + 1][3]);
            }
            uint32_t vf[8][2];
#pragma unroll
            for (int p = 0; p < 4; ++p) {
                uint32_t ar = (j * 16 + v_roff) * ATT_ROWB + (p * 16 + v_coff) * 2;
                ldsm_x4_t(vf[2 * p][0], vf[2 * p][1], vf[2 * p + 1][0], vf[2 * p + 1][1],
                          kbase + KV_TILE_B + ar);
            }
#pragma unroll
            for (int mt = 0; mt < 2; ++mt)
#pragma unroll
                for (int nt = 0; nt < 8; ++nt)
                    mma_f16(o[mt][nt], ph[mt], vf[nt]);
        }
        __syncthreads();
    }

#pragma unroll
    for (int mt = 0; mt < 2; ++mt) {
        const float inv0 = 1.f / lsum[mt][0], inv1 = 1.f / lsum[mt][1];
        const int gr0 = qb * 128 + wid * 32 + mt * 16 + (lane >> 2);
        const size_t row0 = (tok0 + gr0) * D_MODEL;
        const size_t row1 = (tok0 + gr0 + 8) * D_MODEL;
        const int colb = h * DH + (lane & 3) * 2;
#pragma unroll
        for (int nt = 0; nt < 8; ++nt) {
            int c = colb + nt * 8;
            *reinterpret_cast<uint32_t*>(&ao_h[row0 + c]) =
                pack_pair_h(o[mt][nt][0] * inv0, o[mt][nt][1] * inv0);
            *reinterpret_cast<uint32_t*>(&ao_h[row1 + c]) =
                pack_pair_h(o[mt][nt][2] * inv1, o[mt][nt][3] * inv1);
        }
    }
}

// ---------------------------------------------------------------------------
extern "C" void kernel_launch(void* const* d_in, const int* in_sizes, int n_in,
                              void* d_out, int out_size)
{
    (void)in_sizes; (void)n_in; (void)out_size;
    const float* x     = (const float*)d_in[0];
    const float* w_qkv = (const float*)d_in[1];
    const float* w_out = (const float*)d_in[2];
    const float* b_out = (const float*)d_in[3];
    float* out = (float*)d_out;

    uint16_t *xh, *wq, *qkvh, *aoh, *woh;
    cudaGetSymbolAddress((void**)&xh,  g_x_h);
    cudaGetSymbolAddress((void**)&wq,  g_wqkv_h);
    cudaGetSymbolAddress((void**)&qkvh, g_qkv_h);
    cudaGetSymbolAddress((void**)&aoh, g_ao_h);
    cudaGetSymbolAddress((void**)&woh, g_wout_h);

    cudaFuncSetAttribute((gemm_mma<false, true>),
                         cudaFuncAttributeMaxDynamicSharedMemorySize, G_SMEM);
    cudaFuncSetAttribute((gemm_mma<true, false>),
                         cudaFuncAttributeMaxDynamicSharedMemorySize, G_SMEM);
    cudaFuncSetAttribute(flash_attn_mma,
                         cudaFuncAttributeMaxDynamicSharedMemorySize, ATT_SMEM);

    // 1) pack inputs -> fp16 single
    {
        int n4 = M_TOK * D_MODEL / 4;
        pack_h16<<<(n4 + 255) / 256, 256>>>(x, xh, n4);
        n4 = QKV_LD * D_MODEL / 4;
        pack_h16<<<(n4 + 255) / 256, 256>>>(w_qkv, wq, n4);
        n4 = D_MODEL * D_MODEL / 4;
        pack_h16<<<(n4 + 255) / 256, 256>>>(w_out, woh, n4);
    }

    // 2) QKV projection -> qkv fp16
    //    gemm_mma<HAS_BIAS,SPLIT_OUT>(A, B, bias, C, Ch, M, N, K)
    gemm_mma<false, true><<<dim3(QKV_LD / 128, M_TOK / 128), 128, G_SMEM>>>(
        xh, wq, nullptr, nullptr, qkvh, M_TOK, QKV_LD, D_MODEL);

    // 3) causal flash attention -> ao fp16
    flash_attn_mma<<<dim3(S_LEN / 128, 2 * H_NUM), 128, ATT_SMEM>>>(qkvh, aoh);

    // 4) output projection + bias -> fp32 out
    gemm_mma<true, false><<<dim3(D_MODEL / 128, M_TOK / 128), 128, G_SMEM>>>(
        aoh, woh, b_out, out, nullptr, M_TOK, D_MODEL, D_MODEL);
}